// round 1
// baseline (speedup 1.0000x reference)
#include <cuda_runtime.h>
#include <math.h>

#define B_   2
#define C_   128
#define H_   128
#define W_   128
#define HR   64
#define L_   4096
#define F_   1152    // C*9
#define E_   2048    // C*16
#define EPS_ 0.0001f
#define SCALE_ 10.0f

// ---------------- scratch (static device globals; no runtime allocation) ----
__device__ float g_pr[(size_t)B_ * L_ * F_];      // 37.7 MB
__device__ float g_xu[(size_t)B_ * L_ * E_];      // 67 MB
__device__ float g_att[(size_t)B_ * L_ * L_];     // 134 MB
__device__ float g_outp[(size_t)B_ * L_ * E_];    // 67 MB
__device__ float g_rscale[B_ * L_];
__device__ float g_mfilt[B_ * L_];

// ---------------- prep: build pr, xu, denom, mfilt ---------------------------
// block = (b, q), 128 threads (one per channel c)
__global__ __launch_bounds__(128) void k_prep(const float* __restrict__ x,
                                              const float* __restrict__ mask) {
    int q  = blockIdx.x;
    int b  = blockIdx.y;
    int qy = q >> 6, qx = q & 63;
    int c  = threadIdx.x;

    const float* xb = x + ((size_t)b * C_ + c) * (H_ * W_);

    // pr: 3x3 patch of downsampled x around (qy,qx), pad=1
    float ss = 0.f;
    float* prq = g_pr + ((size_t)(b * L_ + q)) * F_ + c * 9;
#pragma unroll
    for (int di = 0; di < 3; di++) {
        int sy = qy - 1 + di;
#pragma unroll
        for (int dj = 0; dj < 3; dj++) {
            int sx = qx - 1 + dj;
            float v = 0.f;
            if ((unsigned)sy < HR && (unsigned)sx < HR)
                v = xb[(2 * sy) * W_ + 2 * sx];
            prq[di * 3 + dj] = v;
            ss += v * v;
        }
    }

    // xu: 4x4 raw patch of x starting at (2qy-1, 2qx-1)
    float* xuq = g_xu + ((size_t)(b * L_ + q)) * E_ + c * 16;
#pragma unroll
    for (int i = 0; i < 4; i++) {
        int ry = 2 * qy - 1 + i;
#pragma unroll
        for (int j = 0; j < 4; j++) {
            int rx = 2 * qx - 1 + j;
            float v = 0.f;
            if ((unsigned)ry < H_ && (unsigned)rx < W_)
                v = xb[ry * W_ + rx];
            xuq[i * 4 + j] = v;
        }
    }

    // block reduction of sum-of-squares over channels
    __shared__ float red[128];
    red[c] = ss;
    __syncthreads();
    for (int off = 64; off > 0; off >>= 1) {
        if (c < off) red[c] += red[c + off];
        __syncthreads();
    }
    if (c == 0) {
        float denom = sqrtf(red[0] + (float)F_ * EPS_);
        // mfilt from mask (3x3 mean over downsampled mask == 0)
        const float* mb = mask + (size_t)b * (H_ * W_);
        float msum = 0.f;
#pragma unroll
        for (int di = 0; di < 3; di++) {
            int sy = qy - 1 + di;
#pragma unroll
            for (int dj = 0; dj < 3; dj++) {
                int sx = qx - 1 + dj;
                if ((unsigned)sy < HR && (unsigned)sx < HR)
                    msum += mb[(2 * sy) * W_ + 2 * sx];
            }
        }
        float mf = (msum == 0.f) ? 1.f : 0.f;
        g_mfilt[b * L_ + q]  = mf;
        g_rscale[b * L_ + q] = SCALE_ * mf / denom;
    }
}

// ---------------- GEMM1: att_raw[p,q] = pr[p,:] . pr[q,:]  (M=N=L, K=F) -----
#define BM 128
#define BN 128
#define BK 8
#define TM 8
#define TN 8

__global__ __launch_bounds__(256) void k_gemm_gram() {
    int b = blockIdx.z;
    const float* A = g_pr + (size_t)b * L_ * F_;
    float* Cm = g_att + (size_t)b * L_ * L_;
    int m0 = blockIdx.y * BM;
    int n0 = blockIdx.x * BN;

    __shared__ float As[BK][BM];
    __shared__ float Bs[BK][BN];

    int tid  = threadIdx.x;
    int aRow = tid >> 1;          // 0..127
    int aCol = (tid & 1) * 4;     // 0 or 4
    int tr = tid >> 4, tc = tid & 15;

    float acc[TM][TN];
#pragma unroll
    for (int i = 0; i < TM; i++)
#pragma unroll
        for (int j = 0; j < TN; j++) acc[i][j] = 0.f;

    for (int k0 = 0; k0 < F_; k0 += BK) {
        float4 av = *(const float4*)&A[(size_t)(m0 + aRow) * F_ + k0 + aCol];
        float4 bv = *(const float4*)&A[(size_t)(n0 + aRow) * F_ + k0 + aCol];
        As[aCol + 0][aRow] = av.x; As[aCol + 1][aRow] = av.y;
        As[aCol + 2][aRow] = av.z; As[aCol + 3][aRow] = av.w;
        Bs[aCol + 0][aRow] = bv.x; Bs[aCol + 1][aRow] = bv.y;
        Bs[aCol + 2][aRow] = bv.z; Bs[aCol + 3][aRow] = bv.w;
        __syncthreads();
#pragma unroll
        for (int k = 0; k < BK; k++) {
            float4 m4a = *(const float4*)&As[k][tr * TM];
            float4 m4b = *(const float4*)&As[k][tr * TM + 4];
            float4 n4a = *(const float4*)&Bs[k][tc * TN];
            float4 n4b = *(const float4*)&Bs[k][tc * TN + 4];
            float rm[TM] = {m4a.x, m4a.y, m4a.z, m4a.w, m4b.x, m4b.y, m4b.z, m4b.w};
            float rn[TN] = {n4a.x, n4a.y, n4a.z, n4a.w, n4b.x, n4b.y, n4b.z, n4b.w};
#pragma unroll
            for (int i = 0; i < TM; i++)
#pragma unroll
                for (int j = 0; j < TN; j++) acc[i][j] += rm[i] * rn[j];
        }
        __syncthreads();
    }

#pragma unroll
    for (int i = 0; i < TM; i++) {
        size_t row = (size_t)(m0 + tr * TM + i) * L_ + n0 + tc * TN;
        *(float4*)&Cm[row]     = make_float4(acc[i][0], acc[i][1], acc[i][2], acc[i][3]);
        *(float4*)&Cm[row + 4] = make_float4(acc[i][4], acc[i][5], acc[i][6], acc[i][7]);
    }
}

// ---------------- softmax over p (column-wise) ------------------------------
// block: 32 columns x 8 row-lanes; grid (L/32, B)
__global__ __launch_bounds__(256) void k_softmax() {
    int b  = blockIdx.y;
    int q  = blockIdx.x * 32 + (threadIdx.x & 31);
    int ty = threadIdx.x >> 5;  // 0..7

    float* A = g_att + (size_t)b * L_ * L_;
    const float* rs = g_rscale + b * L_;
    const float* mf = g_mfilt + b * L_;

    __shared__ float sred[8][33];

    float m = -1e30f;
    for (int p = ty; p < L_; p += 8)
        m = fmaxf(m, A[(size_t)p * L_ + q] * rs[p]);
    sred[ty][threadIdx.x & 31] = m;
    __syncthreads();
    float mm = -1e30f;
#pragma unroll
    for (int j = 0; j < 8; j++) mm = fmaxf(mm, sred[j][threadIdx.x & 31]);
    __syncthreads();

    float s = 0.f;
    for (int p = ty; p < L_; p += 8)
        s += __expf(A[(size_t)p * L_ + q] * rs[p] - mm);
    sred[ty][threadIdx.x & 31] = s;
    __syncthreads();
    float tot = 0.f;
#pragma unroll
    for (int j = 0; j < 8; j++) tot += sred[j][threadIdx.x & 31];
    float inv = 1.f / tot;

    for (int p = ty; p < L_; p += 8) {
        size_t idx = (size_t)p * L_ + q;
        A[idx] = __expf(A[idx] * rs[p] - mm) * inv * mf[p];
    }
}

// ---------------- GEMM2: outp[q,e] = sum_p att[p,q] * xu[p,e] ---------------
// A' = att^T (column access of att is contiguous in q), B = xu row-major
__global__ __launch_bounds__(256) void k_gemm_deconv() {
    int b = blockIdx.z;
    const float* At = g_att + (size_t)b * L_ * L_;   // [p][q]
    const float* Bx = g_xu + (size_t)b * L_ * E_;    // [p][e]
    float* Cm = g_outp + (size_t)b * L_ * E_;        // [q][e]
    int m0 = blockIdx.y * BM;   // q
    int n0 = blockIdx.x * BN;   // e

    __shared__ float As[BK][BM];
    __shared__ float Bs[BK][BN];

    int tid = threadIdx.x;
    int lk  = tid >> 5;          // 0..7
    int lc  = (tid & 31) * 4;    // 0..124
    int tr = tid >> 4, tc = tid & 15;

    float acc[TM][TN];
#pragma unroll
    for (int i = 0; i < TM; i++)
#pragma unroll
        for (int j = 0; j < TN; j++) acc[i][j] = 0.f;

    for (int p0 = 0; p0 < L_; p0 += BK) {
        float4 av = *(const float4*)&At[(size_t)(p0 + lk) * L_ + m0 + lc];
        float4 bv = *(const float4*)&Bx[(size_t)(p0 + lk) * E_ + n0 + lc];
        *(float4*)&As[lk][lc] = av;
        *(float4*)&Bs[lk][lc] = bv;
        __syncthreads();
#pragma unroll
        for (int k = 0; k < BK; k++) {
            float4 m4a = *(const float4*)&As[k][tr * TM];
            float4 m4b = *(const float4*)&As[k][tr * TM + 4];
            float4 n4a = *(const float4*)&Bs[k][tc * TN];
            float4 n4b = *(const float4*)&Bs[k][tc * TN + 4];
            float rm[TM] = {m4a.x, m4a.y, m4a.z, m4a.w, m4b.x, m4b.y, m4b.z, m4b.w};
            float rn[TN] = {n4a.x, n4a.y, n4a.z, n4a.w, n4b.x, n4b.y, n4b.z, n4b.w};
#pragma unroll
            for (int i = 0; i < TM; i++)
#pragma unroll
                for (int j = 0; j < TN; j++) acc[i][j] += rm[i] * rn[j];
        }
        __syncthreads();
    }

#pragma unroll
    for (int i = 0; i < TM; i++) {
        size_t row = (size_t)(m0 + tr * TM + i) * E_ + n0 + tc * TN;
        *(float4*)&Cm[row]     = make_float4(acc[i][0], acc[i][1], acc[i][2], acc[i][3]);
        *(float4*)&Cm[row + 4] = make_float4(acc[i][4], acc[i][5], acc[i][6], acc[i][7]);
    }
}

// ---------------- overlap-add combine ---------------------------------------
// out[b,c,y,x] = 0.25 * sum over (<=4) overlapping patches of outp
__global__ __launch_bounds__(256) void k_combine(float* __restrict__ out) {
    int idx = blockIdx.x * blockDim.x + threadIdx.x;
    // idx = ((b*C + c)*H + y)*W + x ; C=H=W=128
    int xx = idx & 127;
    int y  = (idx >> 7) & 127;
    int c  = (idx >> 14) & 127;
    int b  = idx >> 21;

    const float* P = g_outp + (size_t)b * L_ * E_;
    float s = 0.f;
    int ki0 = (y + 1) & 1;
    int kj0 = (xx + 1) & 1;
#pragma unroll
    for (int ki = 0; ki < 4; ki++) {
        if ((ki & 1) != ki0) continue;
        int sy2 = y + 1 - ki;
        if (sy2 < 0) continue;
        int sy = sy2 >> 1;
        if (sy >= HR) continue;
#pragma unroll
        for (int kj = 0; kj < 4; kj++) {
            if ((kj & 1) != kj0) continue;
            int sx2 = xx + 1 - kj;
            if (sx2 < 0) continue;
            int sx = sx2 >> 1;
            if (sx >= HR) continue;
            s += P[((size_t)((sy << 6) + sx)) * E_ + c * 16 + ki * 4 + kj];
        }
    }
    out[idx] = 0.25f * s;
}

// ---------------- launch -----------------------------------------------------
extern "C" void kernel_launch(void* const* d_in, const int* in_sizes, int n_in,
                              void* d_out, int out_size) {
    const float* x    = (const float*)d_in[0];
    const float* mask = (const float*)d_in[1];
    float* out = (float*)d_out;

    k_prep<<<dim3(L_, B_), 128>>>(x, mask);
    k_gemm_gram<<<dim3(L_ / BN, L_ / BM, B_), 256>>>();
    k_softmax<<<dim3(L_ / 32, B_), 256>>>();
    k_gemm_deconv<<<dim3(E_ / BN, L_ / BM, B_), 256>>>();
    k_combine<<<(B_ * C_ * H_ * W_) / 256, 256>>>(out);
}

// round 3
// speedup vs baseline: 2.7600x; 2.7600x over previous
#include <cuda_runtime.h>
#include <cstdint>
#include <math.h>

#define B_   2
#define C_   128
#define H_   128
#define W_   128
#define HR   64
#define L_   4096
#define F_   1152    // C*9
#define E_   2048    // C*16
#define EPS_ 0.0001f
#define SCALE_ 10.0f

// ---------------- scratch ----------------------------------------------------
__device__ float g_pr  [(size_t)B_ * L_ * F_];   // [b][p][f]   (tf32-rounded)
__device__ float g_xuT [(size_t)B_ * E_ * L_];   // [b][e][p]   (tf32-rounded)
__device__ float g_att [(size_t)B_ * L_ * L_];   // [b][p][q]   raw Gram
__device__ float g_attT[(size_t)B_ * L_ * L_];   // [b][q][p]   softmaxed^T (tf32-rounded)
__device__ float g_outp[(size_t)B_ * L_ * E_];   // [b][q][e]
__device__ float g_rscale[B_ * L_];
__device__ float g_mfilt[B_ * L_];

// ---------------- helpers ----------------------------------------------------
__device__ __forceinline__ float to_tf32(float x) {
    uint32_t u;
    asm("cvt.rna.tf32.f32 %0, %1;" : "=r"(u) : "f"(x));
    return __uint_as_float(u);
}
__device__ __forceinline__ uint32_t smem_u32(const void* p) {
    uint32_t a;
    asm("{ .reg .u64 t; cvta.to.shared.u64 t, %1; cvt.u32.u64 %0, t; }" : "=r"(a) : "l"(p));
    return a;
}
__device__ __forceinline__ void cp_async16(uint32_t saddr, const void* g) {
    asm volatile("cp.async.cg.shared.global [%0], [%1], 16;" :: "r"(saddr), "l"(g));
}
#define CP_COMMIT() asm volatile("cp.async.commit_group;" ::: "memory")
#define CP_WAIT(n)  asm volatile("cp.async.wait_group %0;" :: "n"(n) : "memory")

__device__ __forceinline__ void mma_tf32(float c[4], uint32_t a0, uint32_t a1,
                                         uint32_t a2, uint32_t a3,
                                         uint32_t b0, uint32_t b1) {
    asm volatile(
        "mma.sync.aligned.m16n8k8.row.col.f32.tf32.tf32.f32 "
        "{%0,%1,%2,%3}, {%4,%5,%6,%7}, {%8,%9}, {%0,%1,%2,%3};"
        : "+f"(c[0]), "+f"(c[1]), "+f"(c[2]), "+f"(c[3])
        : "r"(a0), "r"(a1), "r"(a2), "r"(a3), "r"(b0), "r"(b1));
}

// ---------------- prep: pr (tf32), denom, mfilt ------------------------------
__global__ __launch_bounds__(128) void k_prep(const float* __restrict__ x,
                                              const float* __restrict__ mask) {
    int q  = blockIdx.x;
    int b  = blockIdx.y;
    int qy = q >> 6, qx = q & 63;
    int c  = threadIdx.x;
    const float* xb = x + ((size_t)b * C_ + c) * (H_ * W_);

    float ss = 0.f;
    float* prq = g_pr + ((size_t)(b * L_ + q)) * F_ + c * 9;
#pragma unroll
    for (int di = 0; di < 3; di++) {
        int sy = qy - 1 + di;
#pragma unroll
        for (int dj = 0; dj < 3; dj++) {
            int sx = qx - 1 + dj;
            float v = 0.f;
            if ((unsigned)sy < HR && (unsigned)sx < HR) v = xb[(2 * sy) * W_ + 2 * sx];
            prq[di * 3 + dj] = to_tf32(v);
            ss += v * v;
        }
    }
    __shared__ float red[128];
    red[c] = ss;
    __syncthreads();
    for (int off = 64; off > 0; off >>= 1) {
        if (c < off) red[c] += red[c + off];
        __syncthreads();
    }
    if (c == 0) {
        float denom = sqrtf(red[0] + (float)F_ * EPS_);
        const float* mb = mask + (size_t)b * (H_ * W_);
        float msum = 0.f;
#pragma unroll
        for (int di = 0; di < 3; di++) {
            int sy = qy - 1 + di;
#pragma unroll
            for (int dj = 0; dj < 3; dj++) {
                int sx = qx - 1 + dj;
                if ((unsigned)sy < HR && (unsigned)sx < HR) msum += mb[(2 * sy) * W_ + 2 * sx];
            }
        }
        float mf = (msum == 0.f) ? 1.f : 0.f;
        g_mfilt[b * L_ + q]  = mf;
        g_rscale[b * L_ + q] = SCALE_ * mf / denom;
    }
}

// ---------------- xuT[b][e][p] direct from x (tf32) --------------------------
__global__ __launch_bounds__(256) void k_xuT(const float* __restrict__ x) {
    int e = blockIdx.x, b = blockIdx.y;
    int c = e >> 4, i = (e >> 2) & 3, j = e & 3;
    const float* xb = x + ((size_t)b * C_ + c) * (H_ * W_);
    float* dst = g_xuT + ((size_t)b * E_ + e) * L_;
    for (int q = threadIdx.x; q < L_; q += 256) {
        int qy = q >> 6, qx = q & 63;
        int ry = 2 * qy - 1 + i, rx = 2 * qx - 1 + j;
        float v = 0.f;
        if ((unsigned)ry < H_ && (unsigned)rx < W_) v = xb[ry * W_ + rx];
        dst[q] = to_tf32(v);
    }
}

// ---------------- tf32 mma GEMM ---------------------------------------------
// D[m][n] = sum_k A[m][k]*B[n][k]; BM=BN=128, BK=16; 8 warps in 2x4 grid.
#define BM 128
#define BN 128
#define BK 16
#define LDS_ 20          // padded floats per row (80 B, 16B-aligned, conflict-free)

template <int MODE>
__global__ __launch_bounds__(256) void k_gemm_mma() {
    const float* A;
    const float* Bm;
    float* Cc;
    int lda, ldb, ldc, KTOT;
    int b = blockIdx.z;
    if (MODE == 0) {
        A = g_pr + (size_t)b * L_ * F_;  Bm = A;
        Cc = g_att + (size_t)b * L_ * L_;
        lda = F_; ldb = F_; ldc = L_; KTOT = F_;
    } else {
        A = g_attT + (size_t)b * L_ * L_;
        Bm = g_xuT + (size_t)b * E_ * L_;
        Cc = g_outp + (size_t)b * L_ * E_;
        lda = L_; ldb = L_; ldc = E_; KTOT = L_;
    }
    const int NI = KTOT / BK;
    int m0 = blockIdx.y * BM;
    int n0 = blockIdx.x * BN;

    __shared__ float As[2][BM][LDS_];
    __shared__ float Bs[2][BN][LDS_];

    int tid  = threadIdx.x;
    int wid  = tid >> 5, lane = tid & 31;
    int wm   = wid >> 2, wn = wid & 3;       // warp tile: 64m x 32n
    int g    = lane >> 2, tig = lane & 3;

    // global->shared mapping: 512 float4 per tile, 2 per thread
    int r0 = tid >> 2, c40 = (tid & 3) * 4;          // row 0..63
    uint32_t sA = smem_u32(&As[0][0][0]);
    uint32_t sB = smem_u32(&Bs[0][0][0]);

    float acc[4][4][4];
#pragma unroll
    for (int mt = 0; mt < 4; mt++)
#pragma unroll
        for (int nt = 0; nt < 4; nt++)
#pragma unroll
            for (int k = 0; k < 4; k++) acc[mt][nt][k] = 0.f;

    const uint32_t stage = BM * LDS_ * 4;    // bytes per stage

    // prologue: stage 0
    {
        int k0 = 0;
#pragma unroll
        for (int h = 0; h < 2; h++) {
            int row = r0 + h * 64, c4 = c40;
            cp_async16(sA + row * (LDS_ * 4) + c4 * 4,
                       &A[(size_t)(m0 + row) * lda + k0 + c4]);
            cp_async16(sB + row * (LDS_ * 4) + c4 * 4,
                       &Bm[(size_t)(n0 + row) * ldb + k0 + c4]);
        }
        CP_COMMIT();
    }

    for (int it = 0; it < NI; it++) {
        int buf = it & 1;
        if (it + 1 < NI) {
            int nb = (it + 1) & 1;
            int k0 = (it + 1) * BK;
#pragma unroll
            for (int h = 0; h < 2; h++) {
                int row = r0 + h * 64, c4 = c40;
                cp_async16(sA + nb * stage + row * (LDS_ * 4) + c4 * 4,
                           &A[(size_t)(m0 + row) * lda + k0 + c4]);
                cp_async16(sB + nb * stage + row * (LDS_ * 4) + c4 * 4,
                           &Bm[(size_t)(n0 + row) * ldb + k0 + c4]);
            }
            CP_COMMIT();
            CP_WAIT(1);
        } else {
            CP_WAIT(0);
        }
        __syncthreads();

#pragma unroll
        for (int ks = 0; ks < 2; ks++) {
            uint32_t af[4][4];
#pragma unroll
            for (int mt = 0; mt < 4; mt++) {
                const float* ap = &As[buf][wm * 64 + mt * 16 + g][ks * 8 + tig];
                af[mt][0] = __float_as_uint(ap[0]);
                af[mt][1] = __float_as_uint(ap[8 * LDS_]);
                af[mt][2] = __float_as_uint(ap[4]);
                af[mt][3] = __float_as_uint(ap[8 * LDS_ + 4]);
            }
            uint32_t bf[4][2];
#pragma unroll
            for (int nt = 0; nt < 4; nt++) {
                const float* bp = &Bs[buf][wn * 32 + nt * 8 + g][ks * 8 + tig];
                bf[nt][0] = __float_as_uint(bp[0]);
                bf[nt][1] = __float_as_uint(bp[4]);
            }
#pragma unroll
            for (int mt = 0; mt < 4; mt++)
#pragma unroll
                for (int nt = 0; nt < 4; nt++)
                    mma_tf32(acc[mt][nt], af[mt][0], af[mt][1], af[mt][2], af[mt][3],
                             bf[nt][0], bf[nt][1]);
        }
        __syncthreads();
    }

    // epilogue
#pragma unroll
    for (int mt = 0; mt < 4; mt++) {
        int row = m0 + wm * 64 + mt * 16 + g;
#pragma unroll
        for (int nt = 0; nt < 4; nt++) {
            int col = n0 + wn * 32 + nt * 8 + tig * 2;
            *(float2*)&Cc[(size_t)row * ldc + col] =
                make_float2(acc[mt][nt][0], acc[mt][nt][1]);
            *(float2*)&Cc[(size_t)(row + 8) * ldc + col] =
                make_float2(acc[mt][nt][2], acc[mt][nt][3]);
        }
    }
}

// ---------------- softmax over p, transposed tf32 output ---------------------
__global__ __launch_bounds__(256) void k_softmax_t() {
    int b  = blockIdx.y;
    int q0 = blockIdx.x * 32;
    int lane = threadIdx.x & 31;
    int ty = threadIdx.x >> 5;  // 0..7
    int q = q0 + lane;

    const float* A = g_att + (size_t)b * L_ * L_;
    float* AT = g_attT + (size_t)b * L_ * L_;
    const float* rs = g_rscale + b * L_;
    const float* mf = g_mfilt + b * L_;

    __shared__ float sred[8][33];
    __shared__ float st[32][33];

    float m = -1e30f;
    for (int p = ty; p < L_; p += 8)
        m = fmaxf(m, A[(size_t)p * L_ + q] * rs[p]);
    sred[ty][lane] = m;
    __syncthreads();
    float mm = -1e30f;
#pragma unroll
    for (int j = 0; j < 8; j++) mm = fmaxf(mm, sred[j][lane]);
    __syncthreads();

    float s = 0.f;
    for (int p = ty; p < L_; p += 8)
        s += __expf(A[(size_t)p * L_ + q] * rs[p] - mm);
    sred[ty][lane] = s;
    __syncthreads();
    float tot = 0.f;
#pragma unroll
    for (int j = 0; j < 8; j++) tot += sred[j][lane];
    float inv = 1.f / tot;
    __syncthreads();

    int wr = threadIdx.x >> 3;        // q-local row for write
    int wc = (threadIdx.x & 7) * 4;   // p-local col4
    for (int p0 = 0; p0 < L_; p0 += 32) {
#pragma unroll
        for (int pp = ty; pp < 32; pp += 8) {
            int p = p0 + pp;
            st[pp][lane] = __expf(A[(size_t)p * L_ + q] * rs[p] - mm) * inv * mf[p];
        }
        __syncthreads();
        float4 v = make_float4(to_tf32(st[wc + 0][wr]), to_tf32(st[wc + 1][wr]),
                               to_tf32(st[wc + 2][wr]), to_tf32(st[wc + 3][wr]));
        *(float4*)&AT[(size_t)(q0 + wr) * L_ + p0 + wc] = v;
        __syncthreads();
    }
}

// ---------------- overlap-add combine ----------------------------------------
__global__ __launch_bounds__(256) void k_combine(float* __restrict__ out) {
    int idx = blockIdx.x * blockDim.x + threadIdx.x;
    int xx = idx & 127;
    int y  = (idx >> 7) & 127;
    int c  = (idx >> 14) & 127;
    int b  = idx >> 21;

    const float* P = g_outp + (size_t)b * L_ * E_;
    float s = 0.f;
    int ki0 = (y + 1) & 1;
    int kj0 = (xx + 1) & 1;
#pragma unroll
    for (int ki = 0; ki < 4; ki++) {
        if ((ki & 1) != ki0) continue;
        int sy2 = y + 1 - ki;
        if (sy2 < 0) continue;
        int sy = sy2 >> 1;
        if (sy >= HR) continue;
#pragma unroll
        for (int kj = 0; kj < 4; kj++) {
            if ((kj & 1) != kj0) continue;
            int sx2 = xx + 1 - kj;
            if (sx2 < 0) continue;
            int sx = sx2 >> 1;
            if (sx >= HR) continue;
            s += P[((size_t)((sy << 6) + sx)) * E_ + c * 16 + ki * 4 + kj];
        }
    }
    out[idx] = 0.25f * s;
}

// ---------------- launch ------------------------------------------------------
extern "C" void kernel_launch(void* const* d_in, const int* in_sizes, int n_in,
                              void* d_out, int out_size) {
    const float* x    = (const float*)d_in[0];
    const float* mask = (const float*)d_in[1];
    float* out = (float*)d_out;

    k_prep<<<dim3(L_, B_), 128>>>(x, mask);
    k_xuT<<<dim3(E_, B_), 256>>>(x);
    k_gemm_mma<0><<<dim3(L_ / BN, L_ / BM, B_), 256>>>();
    k_softmax_t<<<dim3(L_ / 32, B_), 256>>>();
    k_gemm_mma<1><<<dim3(E_ / BN, L_ / BM, B_), 256>>>();
    k_combine<<<(B_ * C_ * H_ * W_) / 256, 256>>>(out);
}

// round 4
// speedup vs baseline: 5.2833x; 1.9142x over previous
#include <cuda_runtime.h>
#include <cuda_fp16.h>
#include <cstdint>
#include <math.h>

#define B_   2
#define C_   128
#define H_   128
#define W_   128
#define HR   64
#define L_   4096
#define F_   1152    // C*9
#define E_   2048    // C*16
#define EPS_ 0.0001f
#define SCALE_ 10.0f
#define NPC  32      // softmax p-chunks
#define PCH  128     // p rows per chunk

// ---------------- scratch ----------------------------------------------------
__device__ __half g_pr  [(size_t)B_ * L_ * F_];   // [b][p][f]
__device__ __half g_xuT [(size_t)B_ * E_ * L_];   // [b][e][p]
__device__ __half g_att [(size_t)B_ * L_ * L_];   // [b][p][q]  raw Gram (half)
__device__ __half g_attT[(size_t)B_ * L_ * L_];   // [b][q][p]  softmaxed^T
__device__ float  g_outp[(size_t)B_ * L_ * E_];   // [b][q][e]
__device__ float  g_rscale[B_ * L_];
__device__ float  g_mfilt[B_ * L_];
__device__ float  g_statm[(size_t)B_ * NPC * L_];
__device__ float  g_stats[(size_t)B_ * NPC * L_];
__device__ float  g_cm[B_ * L_];
__device__ float  g_ci[B_ * L_];

// ---------------- helpers ----------------------------------------------------
__device__ __forceinline__ uint32_t smem_u32(const void* p) {
    uint32_t a;
    asm("{ .reg .u64 t; cvta.to.shared.u64 t, %1; cvt.u32.u64 %0, t; }" : "=r"(a) : "l"(p));
    return a;
}
__device__ __forceinline__ void cp_async16(uint32_t saddr, const void* g) {
    asm volatile("cp.async.cg.shared.global [%0], [%1], 16;" :: "r"(saddr), "l"(g));
}
#define CP_COMMIT() asm volatile("cp.async.commit_group;" ::: "memory")
#define CP_WAIT(n)  asm volatile("cp.async.wait_group %0;" :: "n"(n) : "memory")

__device__ __forceinline__ void mma_f16(float c[4], uint32_t a0, uint32_t a1,
                                        uint32_t a2, uint32_t a3,
                                        uint32_t b0, uint32_t b1) {
    asm volatile(
        "mma.sync.aligned.m16n8k16.row.col.f32.f16.f16.f32 "
        "{%0,%1,%2,%3}, {%4,%5,%6,%7}, {%8,%9}, {%0,%1,%2,%3};"
        : "+f"(c[0]), "+f"(c[1]), "+f"(c[2]), "+f"(c[3])
        : "r"(a0), "r"(a1), "r"(a2), "r"(a3), "r"(b0), "r"(b1));
}

// ---------------- prep: pr (half), denom, mfilt ------------------------------
__global__ __launch_bounds__(128) void k_prep(const float* __restrict__ x,
                                              const float* __restrict__ mask) {
    int q  = blockIdx.x;
    int b  = blockIdx.y;
    int qy = q >> 6, qx = q & 63;
    int c  = threadIdx.x;
    const float* xb = x + ((size_t)b * C_ + c) * (H_ * W_);

    float ss = 0.f;
    __half* prq = g_pr + ((size_t)(b * L_ + q)) * F_ + c * 9;
#pragma unroll
    for (int di = 0; di < 3; di++) {
        int sy = qy - 1 + di;
#pragma unroll
        for (int dj = 0; dj < 3; dj++) {
            int sx = qx - 1 + dj;
            float v = 0.f;
            if ((unsigned)sy < HR && (unsigned)sx < HR) v = xb[(2 * sy) * W_ + 2 * sx];
            prq[di * 3 + dj] = __float2half_rn(v);
            ss += v * v;
        }
    }
    __shared__ float red[128];
    red[c] = ss;
    __syncthreads();
    for (int off = 64; off > 0; off >>= 1) {
        if (c < off) red[c] += red[c + off];
        __syncthreads();
    }
    if (c == 0) {
        float denom = sqrtf(red[0] + (float)F_ * EPS_);
        const float* mb = mask + (size_t)b * (H_ * W_);
        float msum = 0.f;
#pragma unroll
        for (int di = 0; di < 3; di++) {
            int sy = qy - 1 + di;
#pragma unroll
            for (int dj = 0; dj < 3; dj++) {
                int sx = qx - 1 + dj;
                if ((unsigned)sy < HR && (unsigned)sx < HR) msum += mb[(2 * sy) * W_ + 2 * sx];
            }
        }
        float mf = (msum == 0.f) ? 1.f : 0.f;
        g_mfilt[b * L_ + q]  = mf;
        g_rscale[b * L_ + q] = SCALE_ * mf / denom;
    }
}

// ---------------- xuT[b][e][p] (half) ----------------------------------------
__global__ __launch_bounds__(256) void k_xuT(const float* __restrict__ x) {
    int e = blockIdx.x, b = blockIdx.y;
    int c = e >> 4, i = (e >> 2) & 3, j = e & 3;
    const float* xb = x + ((size_t)b * C_ + c) * (H_ * W_);
    __half* dst = g_xuT + ((size_t)b * E_ + e) * L_;
    for (int q = threadIdx.x; q < L_; q += 256) {
        int qy = q >> 6, qx = q & 63;
        int ry = 2 * qy - 1 + i, rx = 2 * qx - 1 + j;
        float v = 0.f;
        if ((unsigned)ry < H_ && (unsigned)rx < W_) v = xb[ry * W_ + rx];
        dst[q] = __float2half_rn(v);
    }
}

// ---------------- fp16 mma GEMM ----------------------------------------------
// D[m][n] = sum_k A[m][k]*B[n][k]; BM=BN=128, BK=32 halves; 8 warps (2x4).
#define BM 128
#define BN 128
#define BKH 32
#define LDH 40                      // padded halves per smem row (80B)
#define STG (BM * LDH * 2)          // bytes per stage = 10240

template <int MODE>
__global__ __launch_bounds__(256) void k_gemm_h() {
    int b = blockIdx.z;
    const __half* A;
    const __half* Bm;
    int lda, ldb, KTOT;
    if (MODE == 0) {
        A = g_pr + (size_t)b * L_ * F_;  Bm = A;
        lda = F_; ldb = F_; KTOT = F_;
    } else {
        A = g_attT + (size_t)b * L_ * L_;
        Bm = g_xuT + (size_t)b * E_ * L_;
        lda = L_; ldb = L_; KTOT = L_;
    }
    const int NI = KTOT / BKH;
    int m0 = blockIdx.y * BM;
    int n0 = blockIdx.x * BN;

    __shared__ __half As[2][BM][LDH];
    __shared__ __half Bs[2][BN][LDH];

    int tid  = threadIdx.x;
    int wid  = tid >> 5, lane = tid & 31;
    int wm   = wid >> 2, wn = wid & 3;       // warp tile: 64m x 32n
    int g    = lane >> 2, tig = lane & 3;

    int rowL = tid >> 2, seg = tid & 3;      // g->s: rows 0..63 (+64), 16B segs
    uint32_t sA = smem_u32(&As[0][0][0]);
    uint32_t sB = smem_u32(&Bs[0][0][0]);

    float acc[4][4][4];
#pragma unroll
    for (int mt = 0; mt < 4; mt++)
#pragma unroll
        for (int nt = 0; nt < 4; nt++)
#pragma unroll
            for (int k = 0; k < 4; k++) acc[mt][nt][k] = 0.f;

    // prologue
    {
#pragma unroll
        for (int h = 0; h < 2; h++) {
            int row = rowL + h * 64;
            cp_async16(sA + row * (LDH * 2) + seg * 16,
                       &A[(size_t)(m0 + row) * lda + seg * 8]);
            cp_async16(sB + row * (LDH * 2) + seg * 16,
                       &Bm[(size_t)(n0 + row) * ldb + seg * 8]);
        }
        CP_COMMIT();
    }

    for (int it = 0; it < NI; it++) {
        int buf = it & 1;
        if (it + 1 < NI) {
            int nb = (it + 1) & 1;
            int k0 = (it + 1) * BKH;
#pragma unroll
            for (int h = 0; h < 2; h++) {
                int row = rowL + h * 64;
                cp_async16(sA + nb * STG + row * (LDH * 2) + seg * 16,
                           &A[(size_t)(m0 + row) * lda + k0 + seg * 8]);
                cp_async16(sB + nb * STG + row * (LDH * 2) + seg * 16,
                           &Bm[(size_t)(n0 + row) * ldb + k0 + seg * 8]);
            }
            CP_COMMIT();
            CP_WAIT(1);
        } else {
            CP_WAIT(0);
        }
        __syncthreads();

#pragma unroll
        for (int ks = 0; ks < 2; ks++) {
            int ko = ks * 16 + tig * 2;
            uint32_t af[4][4];
#pragma unroll
            for (int mt = 0; mt < 4; mt++) {
                const __half* ap = &As[buf][wm * 64 + mt * 16 + g][ko];
                af[mt][0] = *(const uint32_t*)(ap);
                af[mt][1] = *(const uint32_t*)(ap + 8 * LDH);
                af[mt][2] = *(const uint32_t*)(ap + 8);
                af[mt][3] = *(const uint32_t*)(ap + 8 * LDH + 8);
            }
            uint32_t bf[4][2];
#pragma unroll
            for (int nt = 0; nt < 4; nt++) {
                const __half* bp = &Bs[buf][wn * 32 + nt * 8 + g][ko];
                bf[nt][0] = *(const uint32_t*)(bp);
                bf[nt][1] = *(const uint32_t*)(bp + 8);
            }
#pragma unroll
            for (int mt = 0; mt < 4; mt++)
#pragma unroll
                for (int nt = 0; nt < 4; nt++)
                    mma_f16(acc[mt][nt], af[mt][0], af[mt][1], af[mt][2], af[mt][3],
                            bf[nt][0], bf[nt][1]);
        }
        __syncthreads();
    }

    // epilogue
    if (MODE == 0) {
        __half* Cc = g_att + (size_t)b * L_ * L_;
#pragma unroll
        for (int mt = 0; mt < 4; mt++) {
            int row = m0 + wm * 64 + mt * 16 + g;
#pragma unroll
            for (int nt = 0; nt < 4; nt++) {
                int col = n0 + wn * 32 + nt * 8 + tig * 2;
                *(__half2*)&Cc[(size_t)row * L_ + col] =
                    __floats2half2_rn(acc[mt][nt][0], acc[mt][nt][1]);
                *(__half2*)&Cc[(size_t)(row + 8) * L_ + col] =
                    __floats2half2_rn(acc[mt][nt][2], acc[mt][nt][3]);
            }
        }
    } else {
        float* Cc = g_outp + (size_t)b * L_ * E_;
#pragma unroll
        for (int mt = 0; mt < 4; mt++) {
            int row = m0 + wm * 64 + mt * 16 + g;
#pragma unroll
            for (int nt = 0; nt < 4; nt++) {
                int col = n0 + wn * 32 + nt * 8 + tig * 2;
                *(float2*)&Cc[(size_t)row * E_ + col] =
                    make_float2(acc[mt][nt][0], acc[mt][nt][1]);
                *(float2*)&Cc[(size_t)(row + 8) * E_ + col] =
                    make_float2(acc[mt][nt][2], acc[mt][nt][3]);
            }
        }
    }
}

// ---------------- softmax stage A: per-chunk online (max,sum) ---------------
// grid (4 q-blocks, NPC p-chunks, B); thread owns 4 consecutive q.
__global__ __launch_bounds__(256) void k_smA() {
    int b = blockIdx.z, pc = blockIdx.y;
    int q = blockIdx.x * 1024 + threadIdx.x * 4;
    const __half* A = g_att + (size_t)b * L_ * L_;
    const float* rs = g_rscale + b * L_;
    int p0 = pc * PCH;

    float m[4] = {-1e30f, -1e30f, -1e30f, -1e30f};
    float s[4] = {0.f, 0.f, 0.f, 0.f};

    for (int i = 0; i < PCH; i += 2) {
        uint2 v0 = *(const uint2*)&A[(size_t)(p0 + i) * L_ + q];
        uint2 v1 = *(const uint2*)&A[(size_t)(p0 + i + 1) * L_ + q];
        float r0 = rs[p0 + i], r1 = rs[p0 + i + 1];
        float l[2][4];
        {
            __half2 ha = *(__half2*)&v0.x, hb = *(__half2*)&v0.y;
            l[0][0] = __low2float(ha) * r0; l[0][1] = __high2float(ha) * r0;
            l[0][2] = __low2float(hb) * r0; l[0][3] = __high2float(hb) * r0;
        }
        {
            __half2 ha = *(__half2*)&v1.x, hb = *(__half2*)&v1.y;
            l[1][0] = __low2float(ha) * r1; l[1][1] = __high2float(ha) * r1;
            l[1][2] = __low2float(hb) * r1; l[1][3] = __high2float(hb) * r1;
        }
#pragma unroll
        for (int u = 0; u < 2; u++)
#pragma unroll
            for (int j = 0; j < 4; j++) {
                float lv = l[u][j];
                if (lv <= m[j]) {
                    s[j] += __expf(lv - m[j]);
                } else {
                    s[j] = s[j] * __expf(m[j] - lv) + 1.f;
                    m[j] = lv;
                }
            }
    }
    size_t o = ((size_t)b * NPC + pc) * L_ + q;
    *(float4*)&g_statm[o] = make_float4(m[0], m[1], m[2], m[3]);
    *(float4*)&g_stats[o] = make_float4(s[0], s[1], s[2], s[3]);
}

// ---------------- softmax stage B: combine chunks ----------------------------
__global__ __launch_bounds__(256) void k_smB() {
    int i = blockIdx.x * 256 + threadIdx.x;   // 0..8191
    int b = i >> 12, q = i & (L_ - 1);
    float M = -1e30f;
#pragma unroll 4
    for (int pc = 0; pc < NPC; pc++)
        M = fmaxf(M, g_statm[((size_t)b * NPC + pc) * L_ + q]);
    float S = 0.f;
#pragma unroll 4
    for (int pc = 0; pc < NPC; pc++) {
        size_t o = ((size_t)b * NPC + pc) * L_ + q;
        S += g_stats[o] * __expf(g_statm[o] - M);
    }
    g_cm[b * L_ + q] = M;
    g_ci[b * L_ + q] = 1.f / S;
}

// ---------------- softmax stage C: normalize + transpose ---------------------
// 64x64 tiles; read att[p][q], write attT[q][p] (half).
__global__ __launch_bounds__(256) void k_smC() {
    int b = blockIdx.z;
    int q0 = blockIdx.x * 64, p0 = blockIdx.y * 64;
    const __half* A = g_att + (size_t)b * L_ * L_;
    __half* AT = g_attT + (size_t)b * L_ * L_;

    __shared__ __half st[64][72];
    __shared__ float sM[64], sI[64], sRS[64], sMF[64];

    int t = threadIdx.x;
    if (t < 64)       { sM[t] = g_cm[b * L_ + q0 + t];  sI[t] = g_ci[b * L_ + q0 + t]; }
    else if (t < 128) { int i2 = t - 64; sRS[i2] = g_rscale[b * L_ + p0 + i2]; sMF[i2] = g_mfilt[b * L_ + p0 + i2]; }
    __syncthreads();

    {
        int row = t >> 2, qs = t & 3;
        float r = sRS[row], mfv = sMF[row];
        int bs = ((row >> 4) ^ 0);  // p block of this row
        (void)bs;
        uint4 v0 = *(const uint4*)&A[(size_t)(p0 + row) * L_ + q0 + qs * 16];
        uint4 v1 = *(const uint4*)&A[(size_t)(p0 + row) * L_ + q0 + qs * 16 + 8];
        const uint32_t* vv[2] = {(const uint32_t*)&v0, (const uint32_t*)&v1};
        int pblk = row >> 4, plo = row & 15;
#pragma unroll
        for (int half4 = 0; half4 < 2; half4++) {
#pragma unroll
            for (int w2 = 0; w2 < 4; w2++) {
                __half2 h2 = *(__half2*)&vv[half4][w2];
                int q = qs * 16 + half4 * 8 + w2 * 2;
                float w0 = __expf(__low2float(h2) * r - sM[q]) * sI[q] * mfv;
                float w1 = __expf(__high2float(h2) * r - sM[q + 1]) * sI[q + 1] * mfv;
                int sw0 = (((pblk ^ ((q >> 4) & 3)) << 4) | plo);
                int sw1 = (((pblk ^ (((q + 1) >> 4) & 3)) << 4) | plo);
                st[q][sw0]     = __float2half_rn(w0);
                st[q + 1][sw1] = __float2half_rn(w1);
            }
        }
    }
    __syncthreads();
    {
        int qr = t >> 2, ps = t & 3;
        int qrb = (qr >> 4) & 3;
        const __half* src = &st[qr][(ps ^ qrb) << 4];
        uint4 w0 = *(const uint4*)src;
        uint4 w1 = *(const uint4*)(src + 8);
        *(uint4*)&AT[(size_t)(q0 + qr) * L_ + p0 + ps * 16]     = w0;
        *(uint4*)&AT[(size_t)(q0 + qr) * L_ + p0 + ps * 16 + 8] = w1;
    }
}

// ---------------- overlap-add combine ----------------------------------------
__global__ __launch_bounds__(256) void k_combine(float* __restrict__ out) {
    int idx = blockIdx.x * blockDim.x + threadIdx.x;
    int xx = idx & 127;
    int y  = (idx >> 7) & 127;
    int c  = (idx >> 14) & 127;
    int b  = idx >> 21;

    const float* P = g_outp + (size_t)b * L_ * E_;
    float s = 0.f;
    int ki0 = (y + 1) & 1;
    int kj0 = (xx + 1) & 1;
#pragma unroll
    for (int ki = 0; ki < 4; ki++) {
        if ((ki & 1) != ki0) continue;
        int sy2 = y + 1 - ki;
        if (sy2 < 0) continue;
        int sy = sy2 >> 1;
        if (sy >= HR) continue;
#pragma unroll
        for (int kj = 0; kj < 4; kj++) {
            if ((kj & 1) != kj0) continue;
            int sx2 = xx + 1 - kj;
            if (sx2 < 0) continue;
            int sx = sx2 >> 1;
            if (sx >= HR) continue;
            s += P[((size_t)((sy << 6) + sx)) * E_ + c * 16 + ki * 4 + kj];
        }
    }
    out[idx] = 0.25f * s;
}

// ---------------- launch ------------------------------------------------------
extern "C" void kernel_launch(void* const* d_in, const int* in_sizes, int n_in,
                              void* d_out, int out_size) {
    const float* x    = (const float*)d_in[0];
    const float* mask = (const float*)d_in[1];
    float* out = (float*)d_out;

    k_prep<<<dim3(L_, B_), 128>>>(x, mask);
    k_xuT<<<dim3(E_, B_), 256>>>(x);
    k_gemm_h<0><<<dim3(L_ / BN, L_ / BM, B_), 256>>>();
    k_smA<<<dim3(4, NPC, B_), 256>>>();
    k_smB<<<(B_ * L_) / 256, 256>>>();
    k_smC<<<dim3(L_ / 64, L_ / 64, B_), 256>>>();
    k_gemm_h<1><<<dim3(E_ / BN, L_ / BM, B_), 256>>>();
    k_combine<<<(B_ * C_ * H_ * W_) / 256, 256>>>(out);
}

// round 5
// speedup vs baseline: 6.5227x; 1.2346x over previous
#include <cuda_runtime.h>
#include <cuda_fp16.h>
#include <cstdint>
#include <math.h>

#define B_   2
#define C_   128
#define H_   128
#define W_   128
#define HR   64
#define L_   4096
#define F_   1152    // C*9
#define E_   2048    // C*16
#define EPS_ 0.0001f
#define SCALE_ 10.0f
#define NPC  32      // softmax p-chunks = L_/BN

// ---------------- scratch ----------------------------------------------------
__device__ __half g_pr  [(size_t)B_ * L_ * F_];   // [b][p][f]
__device__ __half g_xuT [(size_t)B_ * E_ * L_];   // [b][e][p]
__device__ __half g_att [(size_t)B_ * L_ * L_];   // [b][r][c] logit, then softmaxed in-place
__device__ float  g_outp[(size_t)B_ * E_ * L_];   // [b][e][q]  (outp transposed)
__device__ float  g_rscale[B_ * L_];
__device__ float  g_mfilt[B_ * L_];
__device__ float  g_statm[(size_t)B_ * NPC * L_];
__device__ float  g_stats[(size_t)B_ * NPC * L_];
__device__ float  g_cm[B_ * L_];
__device__ float  g_ci[B_ * L_];

// ---------------- helpers ----------------------------------------------------
__device__ __forceinline__ uint32_t smem_u32(const void* p) {
    uint32_t a;
    asm("{ .reg .u64 t; cvta.to.shared.u64 t, %1; cvt.u32.u64 %0, t; }" : "=r"(a) : "l"(p));
    return a;
}
__device__ __forceinline__ void cp_async16(uint32_t saddr, const void* g) {
    asm volatile("cp.async.cg.shared.global [%0], [%1], 16;" :: "r"(saddr), "l"(g));
}
#define CP_COMMIT() asm volatile("cp.async.commit_group;" ::: "memory")
#define CP_WAIT(n)  asm volatile("cp.async.wait_group %0;" :: "n"(n) : "memory")

__device__ __forceinline__ void ldsm_x4(uint32_t& r0, uint32_t& r1, uint32_t& r2,
                                        uint32_t& r3, uint32_t addr) {
    asm volatile("ldmatrix.sync.aligned.m8n8.x4.shared.b16 {%0,%1,%2,%3}, [%4];"
                 : "=r"(r0), "=r"(r1), "=r"(r2), "=r"(r3) : "r"(addr));
}
__device__ __forceinline__ void mma_f16(float c[4], uint32_t a0, uint32_t a1,
                                        uint32_t a2, uint32_t a3,
                                        uint32_t b0, uint32_t b1) {
    asm volatile(
        "mma.sync.aligned.m16n8k16.row.col.f32.f16.f16.f32 "
        "{%0,%1,%2,%3}, {%4,%5,%6,%7}, {%8,%9}, {%0,%1,%2,%3};"
        : "+f"(c[0]), "+f"(c[1]), "+f"(c[2]), "+f"(c[3])
        : "r"(a0), "r"(a1), "r"(a2), "r"(a3), "r"(b0), "r"(b1));
}
__device__ __forceinline__ void sm_upd(float& m, float& s, float l) {
    if (l <= m) s += __expf(l - m);
    else { s = s * __expf(m - l) + 1.f; m = l; }
}
__device__ __forceinline__ void sm_comb(float& m, float& s, float om, float os) {
    float M = fmaxf(m, om);
    s = s * __expf(m - M) + os * __expf(om - M);
    m = M;
}

// ---------------- prep: pr (half), rscale, mfilt -----------------------------
__global__ __launch_bounds__(128) void k_prep(const float* __restrict__ x,
                                              const float* __restrict__ mask) {
    int q  = blockIdx.x;
    int b  = blockIdx.y;
    int qy = q >> 6, qx = q & 63;
    int c  = threadIdx.x;
    const float* xb = x + ((size_t)b * C_ + c) * (H_ * W_);

    float ss = 0.f;
    __half* prq = g_pr + ((size_t)(b * L_ + q)) * F_ + c * 9;
#pragma unroll
    for (int di = 0; di < 3; di++) {
        int sy = qy - 1 + di;
#pragma unroll
        for (int dj = 0; dj < 3; dj++) {
            int sx = qx - 1 + dj;
            float v = 0.f;
            if ((unsigned)sy < HR && (unsigned)sx < HR) v = xb[(2 * sy) * W_ + 2 * sx];
            prq[di * 3 + dj] = __float2half_rn(v);
            ss += v * v;
        }
    }
    __shared__ float red[128];
    red[c] = ss;
    __syncthreads();
    for (int off = 64; off > 0; off >>= 1) {
        if (c < off) red[c] += red[c + off];
        __syncthreads();
    }
    if (c == 0) {
        float denom = sqrtf(red[0] + (float)F_ * EPS_);
        const float* mb = mask + (size_t)b * (H_ * W_);
        float msum = 0.f;
#pragma unroll
        for (int di = 0; di < 3; di++) {
            int sy = qy - 1 + di;
#pragma unroll
            for (int dj = 0; dj < 3; dj++) {
                int sx = qx - 1 + dj;
                if ((unsigned)sy < HR && (unsigned)sx < HR) msum += mb[(2 * sy) * W_ + 2 * sx];
            }
        }
        float mf = (msum == 0.f) ? 1.f : 0.f;
        g_mfilt[b * L_ + q]  = mf;
        g_rscale[b * L_ + q] = SCALE_ * mf / denom;
    }
}

// ---------------- xuT[b][e][p] (half) ----------------------------------------
__global__ __launch_bounds__(256) void k_xuT(const float* __restrict__ x) {
    int e = blockIdx.x, b = blockIdx.y;
    int c = e >> 4, i = (e >> 2) & 3, j = e & 3;
    const float* xb = x + ((size_t)b * C_ + c) * (H_ * W_);
    __half* dst = g_xuT + ((size_t)b * E_ + e) * L_;
    for (int q = threadIdx.x; q < L_; q += 256) {
        int qy = q >> 6, qx = q & 63;
        int ry = 2 * qy - 1 + i, rx = 2 * qx - 1 + j;
        float v = 0.f;
        if ((unsigned)ry < H_ && (unsigned)rx < W_) v = xb[ry * W_ + rx];
        dst[q] = __float2half_rn(v);
    }
}

// ---------------- fp16 mma GEMM, 3-stage pipeline, ldmatrix ------------------
#define BM 128
#define BN 128
#define BKH 32
#define LDH 40                       // padded halves per smem row (80B)
#define STAGES 3
#define STG_A (BM * LDH * 2)         // 10240 bytes per stage per operand
#define A_OFF 0
#define B_OFF (STAGES * STG_A)       // 30720
#define RED_OFF (2 * STAGES * STG_A) // 61440
#define SMEM_TOT (RED_OFF + (BN + 2 * BM * 4) * 4)   // + rs + m/s red

// MODE 0: att logits = pr . pr^T * rs[col]  + fused softmax partial stats
// MODE 1: outpT[e][q] = xuT[e][:] . attW[q][:]
template <int MODE>
__global__ __launch_bounds__(256) void k_gemm_h() {
    int b = blockIdx.z;
    const __half* A;
    const __half* Bm;
    int lda, ldb, KTOT;
    if (MODE == 0) {
        A = g_pr + (size_t)b * L_ * F_;  Bm = A;
        lda = F_; ldb = F_; KTOT = F_;
    } else {
        A = g_xuT + (size_t)b * E_ * L_;
        Bm = g_att + (size_t)b * L_ * L_;
        lda = L_; ldb = L_; KTOT = L_;
    }
    const int NI = KTOT / BKH;
    int m0 = blockIdx.y * BM;
    int n0 = blockIdx.x * BN;

    extern __shared__ char smem[];
    uint32_t sA = smem_u32(smem) + A_OFF;
    uint32_t sB = smem_u32(smem) + B_OFF;

    int tid  = threadIdx.x;
    int wid  = tid >> 5, lane = tid & 31;
    int wm   = wid >> 2, wn = wid & 3;       // warp tile: 64m x 32n
    int g    = lane >> 2, tig = lane & 3;

    // ldmatrix lane addressing
    int arow  = lane & 15;
    int acol8 = (lane >> 4) * 8;
    int bmi   = lane >> 3;
    int brow  = (bmi >> 1) * 8 + (lane & 7);
    int bk8   = (bmi & 1) * 8;

    // cp.async mapping
    int rowL = tid >> 2, seg = tid & 3;

    float acc[4][4][4];
#pragma unroll
    for (int mt = 0; mt < 4; mt++)
#pragma unroll
        for (int nt = 0; nt < 4; nt++)
#pragma unroll
            for (int k = 0; k < 4; k++) acc[mt][nt][k] = 0.f;

#define ISSUE(it2) do {                                                          \
    int st_ = (it2) % STAGES;                                                    \
    int k0_ = (it2) * BKH;                                                       \
    _Pragma("unroll")                                                            \
    for (int h_ = 0; h_ < 2; h_++) {                                             \
        int row_ = rowL + h_ * 64;                                               \
        cp_async16(sA + st_ * STG_A + (row_ * LDH + seg * 8) * 2,                \
                   &A[(size_t)(m0 + row_) * lda + k0_ + seg * 8]);               \
        cp_async16(sB + st_ * STG_A + (row_ * LDH + seg * 8) * 2,                \
                   &Bm[(size_t)(n0 + row_) * ldb + k0_ + seg * 8]);              \
    }                                                                            \
} while (0)

    ISSUE(0); CP_COMMIT();
    ISSUE(1); CP_COMMIT();

    for (int it = 0; it < NI; it++) {
        CP_WAIT(1);
        __syncthreads();
        if (it + 2 < NI) ISSUE(it + 2);
        CP_COMMIT();

        uint32_t sAb = sA + (it % STAGES) * STG_A;
        uint32_t sBb = sB + (it % STAGES) * STG_A;
#pragma unroll
        for (int ks = 0; ks < 2; ks++) {
            int ko = ks * 16;
            uint32_t af[4][4];
#pragma unroll
            for (int mt = 0; mt < 4; mt++)
                ldsm_x4(af[mt][0], af[mt][1], af[mt][2], af[mt][3],
                        sAb + ((wm * 64 + mt * 16 + arow) * LDH + ko + acol8) * 2);
            uint32_t bf[2][4];
#pragma unroll
            for (int nt2 = 0; nt2 < 2; nt2++)
                ldsm_x4(bf[nt2][0], bf[nt2][1], bf[nt2][2], bf[nt2][3],
                        sBb + ((wn * 32 + nt2 * 16 + brow) * LDH + ko + bk8) * 2);
#pragma unroll
            for (int mt = 0; mt < 4; mt++)
#pragma unroll
                for (int nt = 0; nt < 4; nt++) {
                    int nt2 = nt >> 1, sel = (nt & 1) * 2;
                    mma_f16(acc[mt][nt], af[mt][0], af[mt][1], af[mt][2], af[mt][3],
                            bf[nt2][sel], bf[nt2][sel + 1]);
                }
        }
    }
#undef ISSUE

    if (MODE == 0) {
        // ---- fused epilogue: scale by rs[col], store half logits, row stats ----
        float* s_rs = (float*)(smem + RED_OFF);
        float* s_m  = s_rs + BN;
        float* s_s  = s_m + BM * 4;
        __syncthreads();
        if (tid < BN) s_rs[tid] = g_rscale[b * L_ + n0 + tid];
        __syncthreads();

        __half* Cc = g_att + (size_t)b * L_ * L_;
        float rm[4][2], rs_[4][2];
#pragma unroll
        for (int mt = 0; mt < 4; mt++) {
            rm[mt][0] = rm[mt][1] = -1e30f;
            rs_[mt][0] = rs_[mt][1] = 0.f;
        }
#pragma unroll
        for (int mt = 0; mt < 4; mt++) {
            int row = m0 + wm * 64 + mt * 16 + g;
#pragma unroll
            for (int nt = 0; nt < 4; nt++) {
                int col = wn * 32 + nt * 8 + tig * 2;
                float r0 = s_rs[col], r1 = s_rs[col + 1];
                __half2 h0 = __floats2half2_rn(acc[mt][nt][0] * r0, acc[mt][nt][1] * r1);
                __half2 h1 = __floats2half2_rn(acc[mt][nt][2] * r0, acc[mt][nt][3] * r1);
                *(__half2*)&Cc[(size_t)row * L_ + n0 + col] = h0;
                *(__half2*)&Cc[(size_t)(row + 8) * L_ + n0 + col] = h1;
                sm_upd(rm[mt][0], rs_[mt][0], __low2float(h0));
                sm_upd(rm[mt][0], rs_[mt][0], __high2float(h0));
                sm_upd(rm[mt][1], rs_[mt][1], __low2float(h1));
                sm_upd(rm[mt][1], rs_[mt][1], __high2float(h1));
            }
        }
#pragma unroll
        for (int mt = 0; mt < 4; mt++)
#pragma unroll
            for (int hh = 0; hh < 2; hh++) {
                float m = rm[mt][hh], s = rs_[mt][hh];
#pragma unroll
                for (int off = 1; off <= 2; off <<= 1) {
                    float om = __shfl_xor_sync(0xffffffffu, m, off);
                    float os = __shfl_xor_sync(0xffffffffu, s, off);
                    sm_comb(m, s, om, os);
                }
                if (tig == 0) {
                    int lrow = wm * 64 + mt * 16 + g + hh * 8;
                    s_m[lrow * 4 + wn] = m;
                    s_s[lrow * 4 + wn] = s;
                }
            }
        __syncthreads();
        if (tid < BM) {
            float M = -1e30f, S = 0.f;
#pragma unroll
            for (int w = 0; w < 4; w++) sm_comb(M, S, s_m[tid * 4 + w], s_s[tid * 4 + w]);
            size_t o = ((size_t)b * NPC + (n0 >> 7)) * L_ + m0 + tid;
            g_statm[o] = M;
            g_stats[o] = S;
        }
    } else {
        float* Cc = g_outp + (size_t)b * E_ * L_;
#pragma unroll
        for (int mt = 0; mt < 4; mt++) {
            int row = m0 + wm * 64 + mt * 16 + g;
#pragma unroll
            for (int nt = 0; nt < 4; nt++) {
                int col = n0 + wn * 32 + nt * 8 + tig * 2;
                *(float2*)&Cc[(size_t)row * L_ + col] =
                    make_float2(acc[mt][nt][0], acc[mt][nt][1]);
                *(float2*)&Cc[(size_t)(row + 8) * L_ + col] =
                    make_float2(acc[mt][nt][2], acc[mt][nt][3]);
            }
        }
    }
}

// ---------------- softmax stage B: combine chunk partials --------------------
__global__ __launch_bounds__(256) void k_smB() {
    int i = blockIdx.x * 256 + threadIdx.x;   // 0..8191
    int b = i >> 12, q = i & (L_ - 1);
    float M = -1e30f, S = 0.f;
#pragma unroll 4
    for (int pc = 0; pc < NPC; pc++) {
        size_t o = ((size_t)b * NPC + pc) * L_ + q;
        sm_comb(M, S, g_statm[o], g_stats[o]);
    }
    g_cm[b * L_ + q] = M;
    g_ci[b * L_ + q] = 1.f / S;
}

// ---------------- softmax stage C: normalize rows in place -------------------
// att[r][c] -> exp(att[r][c] - M[r]) * I[r] * mf[c]   (symmetry: no transpose)
__global__ __launch_bounds__(256) void k_smC() {
    int b = blockIdx.y;
    int r = blockIdx.x * 4 + (threadIdx.x >> 6);
    int cs = threadIdx.x & 63;
    __half* Ar = g_att + (size_t)b * L_ * L_ + (size_t)r * L_;
    float M = g_cm[b * L_ + r], I = g_ci[b * L_ + r];
    const float* mfp = g_mfilt + b * L_;
#pragma unroll
    for (int s8 = 0; s8 < 8; s8++) {
        int c = (cs + s8 * 64) * 8;
        uint4 v = *(uint4*)&Ar[c];
        __half2* hp = (__half2*)&v;
        float4 m0 = *(const float4*)&mfp[c];
        float4 m1 = *(const float4*)&mfp[c + 4];
        float mf[8] = {m0.x, m0.y, m0.z, m0.w, m1.x, m1.y, m1.z, m1.w};
#pragma unroll
        for (int j = 0; j < 4; j++) {
            float l0 = __low2float(hp[j]), l1 = __high2float(hp[j]);
            hp[j] = __floats2half2_rn(__expf(l0 - M) * I * mf[j * 2],
                                      __expf(l1 - M) * I * mf[j * 2 + 1]);
        }
        *(uint4*)&Ar[c] = v;
    }
}

// ---------------- overlap-add combine (outpT layout) -------------------------
__global__ __launch_bounds__(256) void k_combine(float* __restrict__ out) {
    int idx = blockIdx.x * blockDim.x + threadIdx.x;
    int xx = idx & 127;
    int y  = (idx >> 7) & 127;
    int c  = (idx >> 14) & 127;
    int b  = idx >> 21;

    const float* P = g_outp + (size_t)b * E_ * L_;
    float s = 0.f;
    int ki0 = (y + 1) & 1;
    int kj0 = (xx + 1) & 1;
#pragma unroll
    for (int ki = 0; ki < 4; ki++) {
        if ((ki & 1) != ki0) continue;
        int sy2 = y + 1 - ki;
        if (sy2 < 0) continue;
        int sy = sy2 >> 1;
        if (sy >= HR) continue;
#pragma unroll
        for (int kj = 0; kj < 4; kj++) {
            if ((kj & 1) != kj0) continue;
            int sx2 = xx + 1 - kj;
            if (sx2 < 0) continue;
            int sx = sx2 >> 1;
            if (sx >= HR) continue;
            s += P[(size_t)(c * 16 + ki * 4 + kj) * L_ + (sy << 6) + sx];
        }
    }
    out[idx] = 0.25f * s;
}

// ---------------- launch ------------------------------------------------------
extern "C" void kernel_launch(void* const* d_in, const int* in_sizes, int n_in,
                              void* d_out, int out_size) {
    const float* x    = (const float*)d_in[0];
    const float* mask = (const float*)d_in[1];
    float* out = (float*)d_out;

    cudaFuncSetAttribute(k_gemm_h<0>, cudaFuncAttributeMaxDynamicSharedMemorySize, SMEM_TOT);
    cudaFuncSetAttribute(k_gemm_h<1>, cudaFuncAttributeMaxDynamicSharedMemorySize, SMEM_TOT);

    k_prep<<<dim3(L_, B_), 128>>>(x, mask);
    k_xuT<<<dim3(E_, B_), 256>>>(x);
    k_gemm_h<0><<<dim3(L_ / BN, L_ / BM, B_), 256, SMEM_TOT>>>();
    k_smB<<<(B_ * L_) / 256, 256>>>();
    k_smC<<<dim3(L_ / 4, B_), 256>>>();
    k_gemm_h<1><<<dim3(L_ / BN, E_ / BM, B_), 256, SMEM_TOT>>>();
    k_combine<<<(B_ * C_ * H_ * W_) / 256, 256>>>(out);
}

// round 6
// speedup vs baseline: 7.2130x; 1.1058x over previous
#include <cuda_runtime.h>
#include <cuda_fp16.h>
#include <cstdint>
#include <math.h>

#define B_   2
#define C_   128
#define H_   128
#define W_   128
#define HR   64
#define L_   4096
#define F_   1152    // C*9
#define E_   2048    // C*16
#define EPS_ 0.0001f
#define SCALE_ 10.0f
#define NPC  32      // softmax chunks = L_/128
#define NTRI 528     // 32*33/2 triangle tiles

// ---------------- scratch ----------------------------------------------------
__device__ __half g_pr  [(size_t)B_ * L_ * F_];   // [b][p][f]
__device__ __half g_xuT [(size_t)B_ * E_ * L_];   // [b][e][p]
__device__ __half g_att [(size_t)B_ * L_ * L_];   // [b][r][c] logits -> softmaxed in place
__device__ float  g_outp[(size_t)B_ * E_ * L_];   // [b][e][q]
__device__ float  g_rscale[B_ * L_];
__device__ float  g_mfilt[B_ * L_];
__device__ float  g_statm[(size_t)B_ * NPC * L_];
__device__ float  g_stats[(size_t)B_ * NPC * L_];
__device__ float  g_cm[B_ * L_];
__device__ float  g_ci[B_ * L_];

// ---------------- helpers ----------------------------------------------------
__device__ __forceinline__ uint32_t smem_u32(const void* p) {
    uint32_t a;
    asm("{ .reg .u64 t; cvta.to.shared.u64 t, %1; cvt.u32.u64 %0, t; }" : "=r"(a) : "l"(p));
    return a;
}
__device__ __forceinline__ void cp_async16(uint32_t saddr, const void* g) {
    asm volatile("cp.async.cg.shared.global [%0], [%1], 16;" :: "r"(saddr), "l"(g));
}
#define CP_COMMIT() asm volatile("cp.async.commit_group;" ::: "memory")
#define CP_WAIT(n)  asm volatile("cp.async.wait_group %0;" :: "n"(n) : "memory")

__device__ __forceinline__ void ldsm_x4(uint32_t& r0, uint32_t& r1, uint32_t& r2,
                                        uint32_t& r3, uint32_t addr) {
    asm volatile("ldmatrix.sync.aligned.m8n8.x4.shared.b16 {%0,%1,%2,%3}, [%4];"
                 : "=r"(r0), "=r"(r1), "=r"(r2), "=r"(r3) : "r"(addr));
}
__device__ __forceinline__ void mma_f16(float c[4], uint32_t a0, uint32_t a1,
                                        uint32_t a2, uint32_t a3,
                                        uint32_t b0, uint32_t b1) {
    asm volatile(
        "mma.sync.aligned.m16n8k16.row.col.f32.f16.f16.f32 "
        "{%0,%1,%2,%3}, {%4,%5,%6,%7}, {%8,%9}, {%0,%1,%2,%3};"
        : "+f"(c[0]), "+f"(c[1]), "+f"(c[2]), "+f"(c[3])
        : "r"(a0), "r"(a1), "r"(a2), "r"(a3), "r"(b0), "r"(b1));
}
__device__ __forceinline__ void sm_upd(float& m, float& s, float l) {
    if (l <= m) s += __expf(l - m);
    else { s = s * __expf(m - l) + 1.f; m = l; }
}
__device__ __forceinline__ void sm_comb(float& m, float& s, float om, float os) {
    float M = fmaxf(m, om);
    s = s * __expf(m - M) + os * __expf(om - M);
    m = M;
}

// ---------------- prep: pr (half), rscale, mfilt -----------------------------
__global__ __launch_bounds__(128) void k_prep(const float* __restrict__ x,
                                              const float* __restrict__ mask) {
    int q  = blockIdx.x;
    int b  = blockIdx.y;
    int qy = q >> 6, qx = q & 63;
    int c  = threadIdx.x;
    const float* xb = x + ((size_t)b * C_ + c) * (H_ * W_);

    float ss = 0.f;
    __half* prq = g_pr + ((size_t)(b * L_ + q)) * F_ + c * 9;
#pragma unroll
    for (int di = 0; di < 3; di++) {
        int sy = qy - 1 + di;
#pragma unroll
        for (int dj = 0; dj < 3; dj++) {
            int sx = qx - 1 + dj;
            float v = 0.f;
            if ((unsigned)sy < HR && (unsigned)sx < HR) v = xb[(2 * sy) * W_ + 2 * sx];
            prq[di * 3 + dj] = __float2half_rn(v);
            ss += v * v;
        }
    }
    __shared__ float red[128];
    red[c] = ss;
    __syncthreads();
    for (int off = 64; off > 0; off >>= 1) {
        if (c < off) red[c] += red[c + off];
        __syncthreads();
    }
    if (c == 0) {
        float denom = sqrtf(red[0] + (float)F_ * EPS_);
        const float* mb = mask + (size_t)b * (H_ * W_);
        float msum = 0.f;
#pragma unroll
        for (int di = 0; di < 3; di++) {
            int sy = qy - 1 + di;
#pragma unroll
            for (int dj = 0; dj < 3; dj++) {
                int sx = qx - 1 + dj;
                if ((unsigned)sy < HR && (unsigned)sx < HR) msum += mb[(2 * sy) * W_ + 2 * sx];
            }
        }
        float mf = (msum == 0.f) ? 1.f : 0.f;
        g_mfilt[b * L_ + q]  = mf;
        g_rscale[b * L_ + q] = SCALE_ * mf / denom;
    }
}

// ---------------- xuT[b][e][p] (half) ----------------------------------------
__global__ __launch_bounds__(256) void k_xuT(const float* __restrict__ x) {
    int e = blockIdx.x, b = blockIdx.y;
    int c = e >> 4, i = (e >> 2) & 3, j = e & 3;
    const float* xb = x + ((size_t)b * C_ + c) * (H_ * W_);
    __half* dst = g_xuT + ((size_t)b * E_ + e) * L_;
    for (int q = threadIdx.x; q < L_; q += 256) {
        int qy = q >> 6, qx = q & 63;
        int ry = 2 * qy - 1 + i, rx = 2 * qx - 1 + j;
        float v = 0.f;
        if ((unsigned)ry < H_ && (unsigned)rx < W_) v = xb[ry * W_ + rx];
        dst[q] = __float2half_rn(v);
    }
}

// ---------------- fp16 mma GEMM core -----------------------------------------
#define BM 128
#define BN 128
#define BKH 32
#define LDH 40
#define STAGES 3
#define STG_A (BM * LDH * 2)           // 10240
#define A_OFF 0
#define B_OFF (STAGES * STG_A)
#define EPI_OFF 0                      // epilogue reuses stage area
#define LDT 136                        // transposed tile row stride (halves)
#define SMEM_TOT (2 * STAGES * STG_A + 8 * 1024)   // 61440 + 8K epilogue tail

// MODE 0: triangular Gram + fused stats + symmetric stores
// MODE 1: outpT[e][q] = xuT[e][:] . attW[q][:]
template <int MODE>
__global__ __launch_bounds__(256) void k_gemm_h() {
    int b = blockIdx.z;
    const __half* A;
    const __half* Bm;
    int lda, ldb, KTOT;
    int m0, n0, ti = 0, tj = 0;
    if (MODE == 0) {
        int t = blockIdx.x;
        int j = (int)((sqrtf(8.f * t + 1.f) - 1.f) * 0.5f);
        while ((j + 1) * (j + 2) / 2 <= t) j++;
        while (j * (j + 1) / 2 > t) j--;
        ti = t - j * (j + 1) / 2;   // i <= j
        tj = j;
        m0 = ti * BM;               // p block
        n0 = tj * BN;               // q block
        A = g_pr + (size_t)b * L_ * F_;  Bm = A;
        lda = F_; ldb = F_; KTOT = F_;
    } else {
        m0 = blockIdx.y * BM;
        n0 = blockIdx.x * BN;
        A = g_xuT + (size_t)b * E_ * L_;
        Bm = g_att + (size_t)b * L_ * L_;
        lda = L_; ldb = L_; KTOT = L_;
    }
    const int NI = KTOT / BKH;

    extern __shared__ char smem[];
    uint32_t sA = smem_u32(smem) + A_OFF;
    uint32_t sB = smem_u32(smem) + B_OFF;

    int tid  = threadIdx.x;
    int wid  = tid >> 5, lane = tid & 31;
    int wm   = wid >> 2, wn = wid & 3;
    int g    = lane >> 2, tig = lane & 3;

    int arow  = lane & 15;
    int acol8 = (lane >> 4) * 8;
    int bmi   = lane >> 3;
    int brow  = (bmi >> 1) * 8 + (lane & 7);
    int bk8   = (bmi & 1) * 8;

    int rowL = tid >> 2, seg = tid & 3;

    float acc[4][4][4];
#pragma unroll
    for (int mt = 0; mt < 4; mt++)
#pragma unroll
        for (int nt = 0; nt < 4; nt++)
#pragma unroll
            for (int k = 0; k < 4; k++) acc[mt][nt][k] = 0.f;

#define ISSUE(it2) do {                                                          \
    int st_ = (it2) % STAGES;                                                    \
    int k0_ = (it2) * BKH;                                                       \
    _Pragma("unroll")                                                            \
    for (int h_ = 0; h_ < 2; h_++) {                                             \
        int row_ = rowL + h_ * 64;                                               \
        cp_async16(sA + st_ * STG_A + (row_ * LDH + seg * 8) * 2,                \
                   &A[(size_t)(m0 + row_) * lda + k0_ + seg * 8]);               \
        cp_async16(sB + st_ * STG_A + (row_ * LDH + seg * 8) * 2,                \
                   &Bm[(size_t)(n0 + row_) * ldb + k0_ + seg * 8]);              \
    }                                                                            \
} while (0)

    ISSUE(0); CP_COMMIT();
    ISSUE(1); CP_COMMIT();

    for (int it = 0; it < NI; it++) {
        CP_WAIT(1);
        __syncthreads();
        if (it + 2 < NI) ISSUE(it + 2);
        CP_COMMIT();

        uint32_t sAb = sA + (it % STAGES) * STG_A;
        uint32_t sBb = sB + (it % STAGES) * STG_A;
#pragma unroll
        for (int ks = 0; ks < 2; ks++) {
            int ko = ks * 16;
            uint32_t af[4][4];
#pragma unroll
            for (int mt = 0; mt < 4; mt++)
                ldsm_x4(af[mt][0], af[mt][1], af[mt][2], af[mt][3],
                        sAb + ((wm * 64 + mt * 16 + arow) * LDH + ko + acol8) * 2);
            uint32_t bf[2][4];
#pragma unroll
            for (int nt2 = 0; nt2 < 2; nt2++)
                ldsm_x4(bf[nt2][0], bf[nt2][1], bf[nt2][2], bf[nt2][3],
                        sBb + ((wn * 32 + nt2 * 16 + brow) * LDH + ko + bk8) * 2);
#pragma unroll
            for (int mt = 0; mt < 4; mt++)
#pragma unroll
                for (int nt = 0; nt < 4; nt++) {
                    int nt2 = nt >> 1, sel = (nt & 1) * 2;
                    mma_f16(acc[mt][nt], af[mt][0], af[mt][1], af[mt][2], af[mt][3],
                            bf[nt2][sel], bf[nt2][sel + 1]);
                }
        }
    }
#undef ISSUE

    if (MODE == 0) {
        bool offdiag = (ti != tj);
        // smem reuse: s_t [128][LDT] halves, then rsN/rsM/stat arrays
        __half* s_t  = (__half*)(smem + EPI_OFF);                 // 34816 B
        float* s_rsN = (float*)(smem + 128 * LDT * 2);
        float* s_rsM = s_rsN + 128;
        float* s_m   = s_rsM + 128;                                // [128*4]
        float* s_s   = s_m + 512;
        __syncthreads();   // mainloop smem reads done before reuse
        if (tid < 128) {
            s_rsN[tid] = g_rscale[b * L_ + n0 + tid];
            s_rsM[tid] = g_rscale[b * L_ + m0 + tid];
        }
        __syncthreads();

        __half* Cc = g_att + (size_t)b * L_ * L_;
        float rm[4][2], rs_[4][2];
#pragma unroll
        for (int mt = 0; mt < 4; mt++) {
            rm[mt][0] = rm[mt][1] = -1e30f;
            rs_[mt][0] = rs_[mt][1] = 0.f;
        }
#pragma unroll
        for (int mt = 0; mt < 4; mt++) {
            int row = wm * 64 + mt * 16 + g;
#pragma unroll
            for (int nt = 0; nt < 4; nt++) {
                int col = wn * 32 + nt * 8 + tig * 2;
                float r0 = s_rsN[col], r1 = s_rsN[col + 1];
                __half2 h0 = __floats2half2_rn(acc[mt][nt][0] * r0, acc[mt][nt][1] * r1);
                __half2 h1 = __floats2half2_rn(acc[mt][nt][2] * r0, acc[mt][nt][3] * r1);
                *(__half2*)&Cc[(size_t)(m0 + row) * L_ + n0 + col] = h0;
                *(__half2*)&Cc[(size_t)(m0 + row + 8) * L_ + n0 + col] = h1;
                sm_upd(rm[mt][0], rs_[mt][0], __low2float(h0));
                sm_upd(rm[mt][0], rs_[mt][0], __high2float(h0));
                sm_upd(rm[mt][1], rs_[mt][1], __low2float(h1));
                sm_upd(rm[mt][1], rs_[mt][1], __high2float(h1));
                if (offdiag) {
                    float rM0 = s_rsM[row], rM1 = s_rsM[row + 8];
                    s_t[col * LDT + row]           = __float2half_rn(acc[mt][nt][0] * rM0);
                    s_t[(col + 1) * LDT + row]     = __float2half_rn(acc[mt][nt][1] * rM0);
                    s_t[col * LDT + row + 8]       = __float2half_rn(acc[mt][nt][2] * rM1);
                    s_t[(col + 1) * LDT + row + 8] = __float2half_rn(acc[mt][nt][3] * rM1);
                }
            }
        }
        // row stats -> chunk tj, rows m0-block
#pragma unroll
        for (int mt = 0; mt < 4; mt++)
#pragma unroll
            for (int hh = 0; hh < 2; hh++) {
                float m = rm[mt][hh], s = rs_[mt][hh];
#pragma unroll
                for (int off = 1; off <= 2; off <<= 1) {
                    float om = __shfl_xor_sync(0xffffffffu, m, off);
                    float os = __shfl_xor_sync(0xffffffffu, s, off);
                    sm_comb(m, s, om, os);
                }
                if (tig == 0) {
                    int lrow = wm * 64 + mt * 16 + g + hh * 8;
                    s_m[lrow * 4 + wn] = m;
                    s_s[lrow * 4 + wn] = s;
                }
            }
        __syncthreads();   // s_m/s_s AND s_t complete
        if (tid < BM) {
            float M = -1e30f, S = 0.f;
#pragma unroll
            for (int w = 0; w < 4; w++) sm_comb(M, S, s_m[tid * 4 + w], s_s[tid * 4 + w]);
            size_t o = ((size_t)b * NPC + tj) * L_ + m0 + tid;
            g_statm[o] = M;
            g_stats[o] = S;
        }
        if (offdiag) {
            // transposed tile: coalesced store att[n0+qr][m0+...] + stats chunk ti
            int qr = tid >> 1, sg = (tid & 1) * 64;
            const __half* srow = &s_t[qr * LDT + sg];
            __half* drow = &Cc[(size_t)(n0 + qr) * L_ + m0 + sg];
            float m = -1e30f, s = 0.f;
#pragma unroll
            for (int u = 0; u < 8; u++) {
                uint4 v = *(const uint4*)(srow + u * 8);
                const __half2* hp = (const __half2*)&v;
#pragma unroll
                for (int jj = 0; jj < 4; jj++) {
                    sm_upd(m, s, __low2float(hp[jj]));
                    sm_upd(m, s, __high2float(hp[jj]));
                }
                *(uint4*)(drow + u * 8) = v;
            }
            float om = __shfl_xor_sync(0xffffffffu, m, 1);
            float os = __shfl_xor_sync(0xffffffffu, s, 1);
            sm_comb(m, s, om, os);
            if ((tid & 1) == 0) {
                size_t o = ((size_t)b * NPC + ti) * L_ + n0 + qr;
                g_statm[o] = m;
                g_stats[o] = s;
            }
        }
    } else {
        float* Cc = g_outp + (size_t)b * E_ * L_;
#pragma unroll
        for (int mt = 0; mt < 4; mt++) {
            int row = m0 + wm * 64 + mt * 16 + g;
#pragma unroll
            for (int nt = 0; nt < 4; nt++) {
                int col = n0 + wn * 32 + nt * 8 + tig * 2;
                *(float2*)&Cc[(size_t)row * L_ + col] =
                    make_float2(acc[mt][nt][0], acc[mt][nt][1]);
                *(float2*)&Cc[(size_t)(row + 8) * L_ + col] =
                    make_float2(acc[mt][nt][2], acc[mt][nt][3]);
            }
        }
    }
}

// ---------------- softmax stage B: combine chunk partials --------------------
__global__ __launch_bounds__(256) void k_smB() {
    int i = blockIdx.x * 256 + threadIdx.x;
    int b = i >> 12, q = i & (L_ - 1);
    float M = -1e30f, S = 0.f;
#pragma unroll 4
    for (int pc = 0; pc < NPC; pc++) {
        size_t o = ((size_t)b * NPC + pc) * L_ + q;
        sm_comb(M, S, g_statm[o], g_stats[o]);
    }
    g_cm[b * L_ + q] = M;
    g_ci[b * L_ + q] = 1.f / S;
}

// ---------------- softmax stage C: normalize rows in place -------------------
__global__ __launch_bounds__(256) void k_smC() {
    int b = blockIdx.y;
    int r = blockIdx.x * 4 + (threadIdx.x >> 6);
    int cs = threadIdx.x & 63;
    __half* Ar = g_att + (size_t)b * L_ * L_ + (size_t)r * L_;
    float M = g_cm[b * L_ + r], I = g_ci[b * L_ + r];
    const float* mfp = g_mfilt + b * L_;
#pragma unroll
    for (int s8 = 0; s8 < 8; s8++) {
        int c = (cs + s8 * 64) * 8;
        uint4 v = *(uint4*)&Ar[c];
        __half2* hp = (__half2*)&v;
        float4 m0 = *(const float4*)&mfp[c];
        float4 m1 = *(const float4*)&mfp[c + 4];
        float mf[8] = {m0.x, m0.y, m0.z, m0.w, m1.x, m1.y, m1.z, m1.w};
#pragma unroll
        for (int j = 0; j < 4; j++) {
            float l0 = __low2float(hp[j]), l1 = __high2float(hp[j]);
            hp[j] = __floats2half2_rn(__expf(l0 - M) * I * mf[j * 2],
                                      __expf(l1 - M) * I * mf[j * 2 + 1]);
        }
        *(uint4*)&Ar[c] = v;
    }
}

// ---------------- overlap-add combine (outpT layout) -------------------------
__global__ __launch_bounds__(256) void k_combine(float* __restrict__ out) {
    int idx = blockIdx.x * blockDim.x + threadIdx.x;
    int xx = idx & 127;
    int y  = (idx >> 7) & 127;
    int c  = (idx >> 14) & 127;
    int b  = idx >> 21;

    const float* P = g_outp + (size_t)b * E_ * L_;
    float s = 0.f;
    int ki0 = (y + 1) & 1;
    int kj0 = (xx + 1) & 1;
#pragma unroll
    for (int ki = 0; ki < 4; ki++) {
        if ((ki & 1) != ki0) continue;
        int sy2 = y + 1 - ki;
        if (sy2 < 0) continue;
        int sy = sy2 >> 1;
        if (sy >= HR) continue;
#pragma unroll
        for (int kj = 0; kj < 4; kj++) {
            if ((kj & 1) != kj0) continue;
            int sx2 = xx + 1 - kj;
            if (sx2 < 0) continue;
            int sx = sx2 >> 1;
            if (sx >= HR) continue;
            s += P[(size_t)(c * 16 + ki * 4 + kj) * L_ + (sy << 6) + sx];
        }
    }
    out[idx] = 0.25f * s;
}

// ---------------- launch ------------------------------------------------------
extern "C" void kernel_launch(void* const* d_in, const int* in_sizes, int n_in,
                              void* d_out, int out_size) {
    const float* x    = (const float*)d_in[0];
    const float* mask = (const float*)d_in[1];
    float* out = (float*)d_out;

    cudaFuncSetAttribute(k_gemm_h<0>, cudaFuncAttributeMaxDynamicSharedMemorySize, SMEM_TOT);
    cudaFuncSetAttribute(k_gemm_h<1>, cudaFuncAttributeMaxDynamicSharedMemorySize, SMEM_TOT);

    k_prep<<<dim3(L_, B_), 128>>>(x, mask);
    k_xuT<<<dim3(E_, B_), 256>>>(x);
    k_gemm_h<0><<<dim3(NTRI, 1, B_), 256, SMEM_TOT>>>();
    k_smB<<<(B_ * L_) / 256, 256>>>();
    k_smC<<<dim3(L_ / 4, B_), 256>>>();
    k_gemm_h<1><<<dim3(L_ / BN, E_ / BM, B_), 256, SMEM_TOT>>>();
    k_combine<<<(B_ * C_ * H_ * W_) / 256, 256>>>(out);
}

// round 7
// speedup vs baseline: 8.6680x; 1.2017x over previous
#include <cuda_runtime.h>
#include <cuda_fp16.h>
#include <cstdint>
#include <math.h>

#define B_   2
#define C_   128
#define H_   128
#define W_   128
#define HR   64
#define L_   4096
#define F_   1152    // C*9
#define E_   2048    // C*16
#define EPS_ 0.0001f
#define SCALE_ 10.0f
#define NPC  32      // softmax chunks = L_/128
#define NTRI 528     // 32*33/2 triangle tiles
#define CAP  32      // sparse list capacity per column
#define THRESH 5.9604645e-8f   // half min subnormal: smaller underflows to 0 in half

// ---------------- scratch ----------------------------------------------------
__device__ __half g_pr  [(size_t)B_ * L_ * F_];   // [b][p][f]
__device__ __half g_att [(size_t)B_ * L_ * L_];   // [b][r][c] logits (att^T layout)
__device__ float  g_outp[(size_t)B_ * L_ * E_];   // [b][q][e]
__device__ float  g_rscale[B_ * L_];
__device__ float  g_mfilt[B_ * L_];
__device__ float  g_statm[(size_t)B_ * NPC * L_];
__device__ float  g_stats[(size_t)B_ * NPC * L_];
__device__ float  g_cm[B_ * L_];
__device__ float  g_ci[B_ * L_];
__device__ int    g_cnt[B_ * L_];
__device__ int    g_listp[(size_t)B_ * L_ * CAP];
__device__ float  g_listw[(size_t)B_ * L_ * CAP];

// ---------------- helpers ----------------------------------------------------
__device__ __forceinline__ uint32_t smem_u32(const void* p) {
    uint32_t a;
    asm("{ .reg .u64 t; cvta.to.shared.u64 t, %1; cvt.u32.u64 %0, t; }" : "=r"(a) : "l"(p));
    return a;
}
__device__ __forceinline__ void cp_async16(uint32_t saddr, const void* g) {
    asm volatile("cp.async.cg.shared.global [%0], [%1], 16;" :: "r"(saddr), "l"(g));
}
#define CP_COMMIT() asm volatile("cp.async.commit_group;" ::: "memory")
#define CP_WAIT(n)  asm volatile("cp.async.wait_group %0;" :: "n"(n) : "memory")

__device__ __forceinline__ void ldsm_x4(uint32_t& r0, uint32_t& r1, uint32_t& r2,
                                        uint32_t& r3, uint32_t addr) {
    asm volatile("ldmatrix.sync.aligned.m8n8.x4.shared.b16 {%0,%1,%2,%3}, [%4];"
                 : "=r"(r0), "=r"(r1), "=r"(r2), "=r"(r3) : "r"(addr));
}
__device__ __forceinline__ void mma_f16(float c[4], uint32_t a0, uint32_t a1,
                                        uint32_t a2, uint32_t a3,
                                        uint32_t b0, uint32_t b1) {
    asm volatile(
        "mma.sync.aligned.m16n8k16.row.col.f32.f16.f16.f32 "
        "{%0,%1,%2,%3}, {%4,%5,%6,%7}, {%8,%9}, {%0,%1,%2,%3};"
        : "+f"(c[0]), "+f"(c[1]), "+f"(c[2]), "+f"(c[3])
        : "r"(a0), "r"(a1), "r"(a2), "r"(a3), "r"(b0), "r"(b1));
}
__device__ __forceinline__ void sm_upd(float& m, float& s, float l) {
    if (l <= m) s += __expf(l - m);
    else { s = s * __expf(m - l) + 1.f; m = l; }
}
__device__ __forceinline__ void sm_comb(float& m, float& s, float om, float os) {
    float M = fmaxf(m, om);
    s = s * __expf(m - M) + os * __expf(om - M);
    m = M;
}

// ---------------- prep: pr (half), rscale, mfilt -----------------------------
__global__ __launch_bounds__(128) void k_prep(const float* __restrict__ x,
                                              const float* __restrict__ mask) {
    int q  = blockIdx.x;
    int b  = blockIdx.y;
    int qy = q >> 6, qx = q & 63;
    int c  = threadIdx.x;
    const float* xb = x + ((size_t)b * C_ + c) * (H_ * W_);

    float ss = 0.f;
    __half* prq = g_pr + ((size_t)(b * L_ + q)) * F_ + c * 9;
#pragma unroll
    for (int di = 0; di < 3; di++) {
        int sy = qy - 1 + di;
#pragma unroll
        for (int dj = 0; dj < 3; dj++) {
            int sx = qx - 1 + dj;
            float v = 0.f;
            if ((unsigned)sy < HR && (unsigned)sx < HR) v = xb[(2 * sy) * W_ + 2 * sx];
            prq[di * 3 + dj] = __float2half_rn(v);
            ss += v * v;
        }
    }
    __shared__ float red[128];
    red[c] = ss;
    __syncthreads();
    for (int off = 64; off > 0; off >>= 1) {
        if (c < off) red[c] += red[c + off];
        __syncthreads();
    }
    if (c == 0) {
        float denom = sqrtf(red[0] + (float)F_ * EPS_);
        const float* mb = mask + (size_t)b * (H_ * W_);
        float msum = 0.f;
#pragma unroll
        for (int di = 0; di < 3; di++) {
            int sy = qy - 1 + di;
#pragma unroll
            for (int dj = 0; dj < 3; dj++) {
                int sx = qx - 1 + dj;
                if ((unsigned)sy < HR && (unsigned)sx < HR) msum += mb[(2 * sy) * W_ + 2 * sx];
            }
        }
        float mf = (msum == 0.f) ? 1.f : 0.f;
        g_mfilt[b * L_ + q]  = mf;
        g_rscale[b * L_ + q] = SCALE_ * mf / denom;
    }
}

// ---------------- triangular Gram GEMM (fp16 mma) + fused stats --------------
#define BM 128
#define BN 128
#define BKH 32
#define LDH 40
#define STAGES 3
#define STG_A (BM * LDH * 2)
#define A_OFF 0
#define B_OFF (STAGES * STG_A)
#define LDT 136
#define SMEM_TOT (2 * STAGES * STG_A + 8 * 1024)

__global__ __launch_bounds__(256) void k_gram() {
    int b = blockIdx.z;
    int t = blockIdx.x;
    int j = (int)((sqrtf(8.f * t + 1.f) - 1.f) * 0.5f);
    while ((j + 1) * (j + 2) / 2 <= t) j++;
    while (j * (j + 1) / 2 > t) j--;
    int ti = t - j * (j + 1) / 2;   // i <= j
    int tj = j;
    int m0 = ti * BM;
    int n0 = tj * BN;
    const __half* A = g_pr + (size_t)b * L_ * F_;
    const int lda = F_;
    const int NI = F_ / BKH;

    extern __shared__ char smem[];
    uint32_t sA = smem_u32(smem) + A_OFF;
    uint32_t sB = smem_u32(smem) + B_OFF;

    int tid  = threadIdx.x;
    int wid  = tid >> 5, lane = tid & 31;
    int wm   = wid >> 2, wn = wid & 3;
    int g    = lane >> 2, tig = lane & 3;

    int arow  = lane & 15;
    int acol8 = (lane >> 4) * 8;
    int bmi   = lane >> 3;
    int brow  = (bmi >> 1) * 8 + (lane & 7);
    int bk8   = (bmi & 1) * 8;

    int rowL = tid >> 2, seg = tid & 3;

    float acc[4][4][4];
#pragma unroll
    for (int mt = 0; mt < 4; mt++)
#pragma unroll
        for (int nt = 0; nt < 4; nt++)
#pragma unroll
            for (int k = 0; k < 4; k++) acc[mt][nt][k] = 0.f;

#define ISSUE(it2) do {                                                          \
    int st_ = (it2) % STAGES;                                                    \
    int k0_ = (it2) * BKH;                                                       \
    _Pragma("unroll")                                                            \
    for (int h_ = 0; h_ < 2; h_++) {                                             \
        int row_ = rowL + h_ * 64;                                               \
        cp_async16(sA + st_ * STG_A + (row_ * LDH + seg * 8) * 2,                \
                   &A[(size_t)(m0 + row_) * lda + k0_ + seg * 8]);               \
        cp_async16(sB + st_ * STG_A + (row_ * LDH + seg * 8) * 2,                \
                   &A[(size_t)(n0 + row_) * lda + k0_ + seg * 8]);               \
    }                                                                            \
} while (0)

    ISSUE(0); CP_COMMIT();
    ISSUE(1); CP_COMMIT();

    for (int it = 0; it < NI; it++) {
        CP_WAIT(1);
        __syncthreads();
        if (it + 2 < NI) ISSUE(it + 2);
        CP_COMMIT();

        uint32_t sAb = sA + (it % STAGES) * STG_A;
        uint32_t sBb = sB + (it % STAGES) * STG_A;
#pragma unroll
        for (int ks = 0; ks < 2; ks++) {
            int ko = ks * 16;
            uint32_t af[4][4];
#pragma unroll
            for (int mt = 0; mt < 4; mt++)
                ldsm_x4(af[mt][0], af[mt][1], af[mt][2], af[mt][3],
                        sAb + ((wm * 64 + mt * 16 + arow) * LDH + ko + acol8) * 2);
            uint32_t bf[2][4];
#pragma unroll
            for (int nt2 = 0; nt2 < 2; nt2++)
                ldsm_x4(bf[nt2][0], bf[nt2][1], bf[nt2][2], bf[nt2][3],
                        sBb + ((wn * 32 + nt2 * 16 + brow) * LDH + ko + bk8) * 2);
#pragma unroll
            for (int mt = 0; mt < 4; mt++)
#pragma unroll
                for (int nt = 0; nt < 4; nt++) {
                    int nt2 = nt >> 1, sel = (nt & 1) * 2;
                    mma_f16(acc[mt][nt], af[mt][0], af[mt][1], af[mt][2], af[mt][3],
                            bf[nt2][sel], bf[nt2][sel + 1]);
                }
        }
    }
#undef ISSUE

    bool offdiag = (ti != tj);
    __half* s_t  = (__half*)(smem);
    float* s_rsN = (float*)(smem + 128 * LDT * 2);
    float* s_rsM = s_rsN + 128;
    float* s_m   = s_rsM + 128;
    float* s_s   = s_m + 512;
    __syncthreads();
    if (tid < 128) {
        s_rsN[tid] = g_rscale[b * L_ + n0 + tid];
        s_rsM[tid] = g_rscale[b * L_ + m0 + tid];
    }
    __syncthreads();

    __half* Cc = g_att + (size_t)b * L_ * L_;
    float rm[4][2], rs_[4][2];
#pragma unroll
    for (int mt = 0; mt < 4; mt++) {
        rm[mt][0] = rm[mt][1] = -1e30f;
        rs_[mt][0] = rs_[mt][1] = 0.f;
    }
#pragma unroll
    for (int mt = 0; mt < 4; mt++) {
        int row = wm * 64 + mt * 16 + g;
#pragma unroll
        for (int nt = 0; nt < 4; nt++) {
            int col = wn * 32 + nt * 8 + tig * 2;
            float r0 = s_rsN[col], r1 = s_rsN[col + 1];
            __half2 h0 = __floats2half2_rn(acc[mt][nt][0] * r0, acc[mt][nt][1] * r1);
            __half2 h1 = __floats2half2_rn(acc[mt][nt][2] * r0, acc[mt][nt][3] * r1);
            *(__half2*)&Cc[(size_t)(m0 + row) * L_ + n0 + col] = h0;
            *(__half2*)&Cc[(size_t)(m0 + row + 8) * L_ + n0 + col] = h1;
            sm_upd(rm[mt][0], rs_[mt][0], __low2float(h0));
            sm_upd(rm[mt][0], rs_[mt][0], __high2float(h0));
            sm_upd(rm[mt][1], rs_[mt][1], __low2float(h1));
            sm_upd(rm[mt][1], rs_[mt][1], __high2float(h1));
            if (offdiag) {
                float rM0 = s_rsM[row], rM1 = s_rsM[row + 8];
                s_t[col * LDT + row]           = __float2half_rn(acc[mt][nt][0] * rM0);
                s_t[(col + 1) * LDT + row]     = __float2half_rn(acc[mt][nt][1] * rM0);
                s_t[col * LDT + row + 8]       = __float2half_rn(acc[mt][nt][2] * rM1);
                s_t[(col + 1) * LDT + row + 8] = __float2half_rn(acc[mt][nt][3] * rM1);
            }
        }
    }
#pragma unroll
    for (int mt = 0; mt < 4; mt++)
#pragma unroll
        for (int hh = 0; hh < 2; hh++) {
            float m = rm[mt][hh], s = rs_[mt][hh];
#pragma unroll
            for (int off = 1; off <= 2; off <<= 1) {
                float om = __shfl_xor_sync(0xffffffffu, m, off);
                float os = __shfl_xor_sync(0xffffffffu, s, off);
                sm_comb(m, s, om, os);
            }
            if (tig == 0) {
                int lrow = wm * 64 + mt * 16 + g + hh * 8;
                s_m[lrow * 4 + wn] = m;
                s_s[lrow * 4 + wn] = s;
            }
        }
    __syncthreads();
    if (tid < BM) {
        float M = -1e30f, S = 0.f;
#pragma unroll
        for (int w = 0; w < 4; w++) sm_comb(M, S, s_m[tid * 4 + w], s_s[tid * 4 + w]);
        size_t o = ((size_t)b * NPC + tj) * L_ + m0 + tid;
        g_statm[o] = M;
        g_stats[o] = S;
    }
    if (offdiag) {
        int qr = tid >> 1, sg = (tid & 1) * 64;
        const __half* srow = &s_t[qr * LDT + sg];
        __half* drow = &Cc[(size_t)(n0 + qr) * L_ + m0 + sg];
        float m = -1e30f, s = 0.f;
#pragma unroll
        for (int u = 0; u < 8; u++) {
            uint4 v = *(const uint4*)(srow + u * 8);
            const __half2* hp = (const __half2*)&v;
#pragma unroll
            for (int jj = 0; jj < 4; jj++) {
                sm_upd(m, s, __low2float(hp[jj]));
                sm_upd(m, s, __high2float(hp[jj]));
            }
            *(uint4*)(drow + u * 8) = v;
        }
        float om = __shfl_xor_sync(0xffffffffu, m, 1);
        float os = __shfl_xor_sync(0xffffffffu, s, 1);
        sm_comb(m, s, om, os);
        if ((tid & 1) == 0) {
            size_t o = ((size_t)b * NPC + ti) * L_ + n0 + qr;
            g_statm[o] = m;
            g_stats[o] = s;
        }
    }
}

// ---------------- softmax stage B: combine chunk partials --------------------
__global__ __launch_bounds__(256) void k_smB() {
    int i = blockIdx.x * 256 + threadIdx.x;
    int b = i >> 12, q = i & (L_ - 1);
    float M = -1e30f, S = 0.f;
#pragma unroll 4
    for (int pc = 0; pc < NPC; pc++) {
        size_t o = ((size_t)b * NPC + pc) * L_ + q;
        sm_comb(M, S, g_statm[o], g_stats[o]);
    }
    g_cm[b * L_ + q] = M;
    g_ci[b * L_ + q] = 1.f / S;
}

// ---------------- stage C: build deterministic sparse lists ------------------
// block = 4 rows x 64 threads; thread owns 64 contiguous columns of its row.
__global__ __launch_bounds__(256) void k_smC() {
    int b = blockIdx.y;
    int rl = threadIdx.x >> 6;               // 0..3
    int t64 = threadIdx.x & 63;              // owner lane
    int r = blockIdx.x * 4 + rl;
    const __half* Ar = g_att + (size_t)b * L_ * L_ + (size_t)r * L_;
    float M = g_cm[b * L_ + r], I = g_ci[b * L_ + r];
    const float* mfp = g_mfilt + b * L_;

    __shared__ int s_cnt[4][64];
    __shared__ int s_off[4][65];

    int c0 = t64 * 64;
    // pass 1: count
    int cnt = 0;
#pragma unroll
    for (int u = 0; u < 8; u++) {
        uint4 v = *(const uint4*)&Ar[c0 + u * 8];
        const __half2* hp = (const __half2*)&v;
#pragma unroll
        for (int jj = 0; jj < 4; jj++) {
            int c = c0 + u * 8 + jj * 2;
            float w0 = __expf(__low2float(hp[jj]) - M) * I * mfp[c];
            float w1 = __expf(__high2float(hp[jj]) - M) * I * mfp[c + 1];
            if (w0 >= THRESH) cnt++;
            if (w1 >= THRESH) cnt++;
        }
    }
    s_cnt[rl][t64] = cnt;
    __syncthreads();
    if (t64 == 0) {
        int run = 0;
#pragma unroll 8
        for (int k = 0; k < 64; k++) {
            s_off[rl][k] = run;
            run += s_cnt[rl][k];
        }
        s_off[rl][64] = run;
        g_cnt[b * L_ + r] = run;
    }
    __syncthreads();
    // pass 2: write
    int idx = s_off[rl][t64];
    size_t base = (size_t)(b * L_ + r) * CAP;
#pragma unroll
    for (int u = 0; u < 8; u++) {
        uint4 v = *(const uint4*)&Ar[c0 + u * 8];
        const __half2* hp = (const __half2*)&v;
#pragma unroll
        for (int jj = 0; jj < 4; jj++) {
            int c = c0 + u * 8 + jj * 2;
            float w0 = __expf(__low2float(hp[jj]) - M) * I * mfp[c];
            float w1 = __expf(__high2float(hp[jj]) - M) * I * mfp[c + 1];
            if (w0 >= THRESH) {
                if (idx < CAP) { g_listp[base + idx] = c; g_listw[base + idx] = w0; }
                idx++;
            }
            if (w1 >= THRESH) {
                if (idx < CAP) { g_listp[base + idx] = c + 1; g_listw[base + idx] = w1; }
                idx++;
            }
        }
    }
}

// ---------------- sparse "GEMM2": outp[q][e] = sum_p w * xu[p][e] ------------
__global__ __launch_bounds__(128) void k_sparse(const float* __restrict__ x) {
    int q = blockIdx.x, b = blockIdx.y;
    int c = threadIdx.x;
    const float* xb = x + ((size_t)b * C_ + c) * (H_ * W_);
    float acc[16];
#pragma unroll
    for (int k = 0; k < 16; k++) acc[k] = 0.f;

    int cnt = g_cnt[b * L_ + q];
    if (cnt <= CAP) {
        size_t base = (size_t)(b * L_ + q) * CAP;
        for (int t = 0; t < cnt; t++) {
            int p = g_listp[base + t];
            float w = g_listw[base + t];
            int py = p >> 6, px = p & 63;
#pragma unroll
            for (int i = 0; i < 4; i++) {
                int ry = 2 * py - 1 + i;
                if ((unsigned)ry >= H_) continue;
#pragma unroll
                for (int jj = 0; jj < 4; jj++) {
                    int rx = 2 * px - 1 + jj;
                    if ((unsigned)rx >= W_) continue;
                    acc[i * 4 + jj] += w * xb[ry * W_ + rx];
                }
            }
        }
    } else {
        // dense fallback: recompute weights from logits + stats
        const __half* Ar = g_att + (size_t)b * L_ * L_ + (size_t)q * L_;
        float M = g_cm[b * L_ + q], I = g_ci[b * L_ + q];
        const float* mfp = g_mfilt + b * L_;
        for (int p = 0; p < L_; p++) {
            float w = __expf(__half2float(Ar[p]) - M) * I * mfp[p];
            if (w < THRESH) continue;
            int py = p >> 6, px = p & 63;
#pragma unroll
            for (int i = 0; i < 4; i++) {
                int ry = 2 * py - 1 + i;
                if ((unsigned)ry >= H_) continue;
#pragma unroll
                for (int jj = 0; jj < 4; jj++) {
                    int rx = 2 * px - 1 + jj;
                    if ((unsigned)rx >= W_) continue;
                    acc[i * 4 + jj] += w * xb[ry * W_ + rx];
                }
            }
        }
    }
    float* dst = g_outp + ((size_t)(b * L_ + q)) * E_ + c * 16;
#pragma unroll
    for (int k = 0; k < 4; k++)
        *(float4*)&dst[k * 4] = make_float4(acc[k * 4], acc[k * 4 + 1],
                                            acc[k * 4 + 2], acc[k * 4 + 3]);
}

// ---------------- overlap-add combine ----------------------------------------
__global__ __launch_bounds__(256) void k_combine(float* __restrict__ out) {
    int idx = blockIdx.x * blockDim.x + threadIdx.x;
    int xx = idx & 127;
    int y  = (idx >> 7) & 127;
    int c  = (idx >> 14) & 127;
    int b  = idx >> 21;

    const float* P = g_outp + (size_t)b * L_ * E_;
    float s = 0.f;
    int ki0 = (y + 1) & 1;
    int kj0 = (xx + 1) & 1;
#pragma unroll
    for (int ki = 0; ki < 4; ki++) {
        if ((ki & 1) != ki0) continue;
        int sy2 = y + 1 - ki;
        if (sy2 < 0) continue;
        int sy = sy2 >> 1;
        if (sy >= HR) continue;
#pragma unroll
        for (int kj = 0; kj < 4; kj++) {
            if ((kj & 1) != kj0) continue;
            int sx2 = xx + 1 - kj;
            if (sx2 < 0) continue;
            int sx = sx2 >> 1;
            if (sx >= HR) continue;
            s += P[((size_t)((sy << 6) + sx)) * E_ + c * 16 + ki * 4 + kj];
        }
    }
    out[idx] = 0.25f * s;
}

// ---------------- launch ------------------------------------------------------
extern "C" void kernel_launch(void* const* d_in, const int* in_sizes, int n_in,
                              void* d_out, int out_size) {
    const float* x    = (const float*)d_in[0];
    const float* mask = (const float*)d_in[1];
    float* out = (float*)d_out;

    cudaFuncSetAttribute(k_gram, cudaFuncAttributeMaxDynamicSharedMemorySize, SMEM_TOT);

    k_prep<<<dim3(L_, B_), 128>>>(x, mask);
    k_gram<<<dim3(NTRI, 1, B_), 256, SMEM_TOT>>>();
    k_smB<<<(B_ * L_) / 256, 256>>>();
    k_smC<<<dim3(L_ / 4, B_), 256>>>();
    k_sparse<<<dim3(L_, B_), 128>>>(x);
    k_combine<<<(B_ * C_ * H_ * W_) / 256, 256>>>(out);
}

// round 8
// speedup vs baseline: 14.3932x; 1.6605x over previous
#include <cuda_runtime.h>
#include <cuda_fp16.h>
#include <cstdint>
#include <math.h>

#define B_   2
#define C_   128
#define H_   128
#define W_   128
#define HR   64
#define L_   4096
#define F_   1152    // C*9
#define E_   2048    // C*16
#define EPS_ 0.0001f
#define SCALE_ 10.0f
#define NPC  32      // softmax chunks = L_/128
#define NTRI 528     // 32*33/2 triangle tiles
#define CAP  32      // sparse list capacity per row
#define THRESH 5.9604645e-8f   // half min subnormal

// ---------------- scratch ----------------------------------------------------
__device__ __half g_pr  [(size_t)B_ * L_ * F_];   // [b][p][f]
__device__ __half g_att [(size_t)B_ * L_ * L_];   // [b][r][c] logits
__device__ float  g_outp[(size_t)B_ * L_ * E_];   // [b][q][e]
__device__ float  g_rscale[B_ * L_];
__device__ float  g_mfilt[B_ * L_];
__device__ float  g_statm[(size_t)B_ * NPC * L_];
__device__ float  g_stats[(size_t)B_ * NPC * L_];
__device__ float  g_cm[B_ * L_];
__device__ float  g_ci[B_ * L_];
__device__ int    g_cnt[B_ * L_];
__device__ int    g_listp[(size_t)B_ * L_ * CAP];
__device__ float  g_listw[(size_t)B_ * L_ * CAP];

// ---------------- helpers ----------------------------------------------------
__device__ __forceinline__ uint32_t smem_u32(const void* p) {
    uint32_t a;
    asm("{ .reg .u64 t; cvta.to.shared.u64 t, %1; cvt.u32.u64 %0, t; }" : "=r"(a) : "l"(p));
    return a;
}
__device__ __forceinline__ void cp_async16(uint32_t saddr, const void* g) {
    asm volatile("cp.async.cg.shared.global [%0], [%1], 16;" :: "r"(saddr), "l"(g));
}
#define CP_COMMIT() asm volatile("cp.async.commit_group;" ::: "memory")
#define CP_WAIT(n)  asm volatile("cp.async.wait_group %0;" :: "n"(n) : "memory")

__device__ __forceinline__ void ldsm_x4(uint32_t& r0, uint32_t& r1, uint32_t& r2,
                                        uint32_t& r3, uint32_t addr) {
    asm volatile("ldmatrix.sync.aligned.m8n8.x4.shared.b16 {%0,%1,%2,%3}, [%4];"
                 : "=r"(r0), "=r"(r1), "=r"(r2), "=r"(r3) : "r"(addr));
}
__device__ __forceinline__ void mma_f16(float c[4], uint32_t a0, uint32_t a1,
                                        uint32_t a2, uint32_t a3,
                                        uint32_t b0, uint32_t b1) {
    asm volatile(
        "mma.sync.aligned.m16n8k16.row.col.f32.f16.f16.f32 "
        "{%0,%1,%2,%3}, {%4,%5,%6,%7}, {%8,%9}, {%0,%1,%2,%3};"
        : "+f"(c[0]), "+f"(c[1]), "+f"(c[2]), "+f"(c[3])
        : "r"(a0), "r"(a1), "r"(a2), "r"(a3), "r"(b0), "r"(b1));
}
__device__ __forceinline__ void sm_upd(float& m, float& s, float l) {
    if (l <= m) s += __expf(l - m);
    else { s = s * __expf(m - l) + 1.f; m = l; }
}
__device__ __forceinline__ void sm_comb(float& m, float& s, float om, float os) {
    float M = fmaxf(m, om);
    s = s * __expf(m - M) + os * __expf(om - M);
    m = M;
}

// ---------------- prep: pr (half), rscale, mfilt -----------------------------
__global__ __launch_bounds__(128) void k_prep(const float* __restrict__ x,
                                              const float* __restrict__ mask) {
    int q  = blockIdx.x;
    int b  = blockIdx.y;
    int qy = q >> 6, qx = q & 63;
    int c  = threadIdx.x;
    const float* xb = x + ((size_t)b * C_ + c) * (H_ * W_);

    float ss = 0.f;
    __half* prq = g_pr + ((size_t)(b * L_ + q)) * F_ + c * 9;
#pragma unroll
    for (int di = 0; di < 3; di++) {
        int sy = qy - 1 + di;
#pragma unroll
        for (int dj = 0; dj < 3; dj++) {
            int sx = qx - 1 + dj;
            float v = 0.f;
            if ((unsigned)sy < HR && (unsigned)sx < HR) v = xb[(2 * sy) * W_ + 2 * sx];
            prq[di * 3 + dj] = __float2half_rn(v);
            ss += v * v;
        }
    }
    __shared__ float red[128];
    red[c] = ss;
    __syncthreads();
    for (int off = 64; off > 0; off >>= 1) {
        if (c < off) red[c] += red[c + off];
        __syncthreads();
    }
    if (c == 0) {
        float denom = sqrtf(red[0] + (float)F_ * EPS_);
        const float* mb = mask + (size_t)b * (H_ * W_);
        float msum = 0.f;
#pragma unroll
        for (int di = 0; di < 3; di++) {
            int sy = qy - 1 + di;
#pragma unroll
            for (int dj = 0; dj < 3; dj++) {
                int sx = qx - 1 + dj;
                if ((unsigned)sy < HR && (unsigned)sx < HR) msum += mb[(2 * sy) * W_ + 2 * sx];
            }
        }
        float mf = (msum == 0.f) ? 1.f : 0.f;
        g_mfilt[b * L_ + q]  = mf;
        g_rscale[b * L_ + q] = SCALE_ * mf / denom;
    }
}

// ---------------- triangular Gram GEMM (fp16 mma) + fused stats --------------
#define BM 128
#define BN 128
#define BKH 32
#define LDH 40
#define STAGES 3
#define STG_A (BM * LDH * 2)
#define A_OFF 0
#define B_OFF (STAGES * STG_A)
#define LDT 136
#define SMEM_TOT (2 * STAGES * STG_A + 8 * 1024)

__global__ __launch_bounds__(256) void k_gram() {
    int b = blockIdx.z;
    int t = blockIdx.x;
    int j = (int)((sqrtf(8.f * t + 1.f) - 1.f) * 0.5f);
    while ((j + 1) * (j + 2) / 2 <= t) j++;
    while (j * (j + 1) / 2 > t) j--;
    int ti = t - j * (j + 1) / 2;   // i <= j
    int tj = j;
    int m0 = ti * BM;
    int n0 = tj * BN;
    const __half* A = g_pr + (size_t)b * L_ * F_;
    const int lda = F_;
    const int NI = F_ / BKH;

    extern __shared__ char smem[];
    uint32_t sA = smem_u32(smem) + A_OFF;
    uint32_t sB = smem_u32(smem) + B_OFF;

    int tid  = threadIdx.x;
    int wid  = tid >> 5, lane = tid & 31;
    int wm   = wid >> 2, wn = wid & 3;
    int g    = lane >> 2, tig = lane & 3;

    int arow  = lane & 15;
    int acol8 = (lane >> 4) * 8;
    int bmi   = lane >> 3;
    int brow  = (bmi >> 1) * 8 + (lane & 7);
    int bk8   = (bmi & 1) * 8;

    int rowL = tid >> 2, seg = tid & 3;

    float acc[4][4][4];
#pragma unroll
    for (int mt = 0; mt < 4; mt++)
#pragma unroll
        for (int nt = 0; nt < 4; nt++)
#pragma unroll
            for (int k = 0; k < 4; k++) acc[mt][nt][k] = 0.f;

#define ISSUE(it2) do {                                                          \
    int st_ = (it2) % STAGES;                                                    \
    int k0_ = (it2) * BKH;                                                       \
    _Pragma("unroll")                                                            \
    for (int h_ = 0; h_ < 2; h_++) {                                             \
        int row_ = rowL + h_ * 64;                                               \
        cp_async16(sA + st_ * STG_A + (row_ * LDH + seg * 8) * 2,                \
                   &A[(size_t)(m0 + row_) * lda + k0_ + seg * 8]);               \
        cp_async16(sB + st_ * STG_A + (row_ * LDH + seg * 8) * 2,                \
                   &A[(size_t)(n0 + row_) * lda + k0_ + seg * 8]);               \
    }                                                                            \
} while (0)

    ISSUE(0); CP_COMMIT();
    ISSUE(1); CP_COMMIT();

    for (int it = 0; it < NI; it++) {
        CP_WAIT(1);
        __syncthreads();
        if (it + 2 < NI) ISSUE(it + 2);
        CP_COMMIT();

        uint32_t sAb = sA + (it % STAGES) * STG_A;
        uint32_t sBb = sB + (it % STAGES) * STG_A;
#pragma unroll
        for (int ks = 0; ks < 2; ks++) {
            int ko = ks * 16;
            uint32_t af[4][4];
#pragma unroll
            for (int mt = 0; mt < 4; mt++)
                ldsm_x4(af[mt][0], af[mt][1], af[mt][2], af[mt][3],
                        sAb + ((wm * 64 + mt * 16 + arow) * LDH + ko + acol8) * 2);
            uint32_t bf[2][4];
#pragma unroll
            for (int nt2 = 0; nt2 < 2; nt2++)
                ldsm_x4(bf[nt2][0], bf[nt2][1], bf[nt2][2], bf[nt2][3],
                        sBb + ((wn * 32 + nt2 * 16 + brow) * LDH + ko + bk8) * 2);
#pragma unroll
            for (int mt = 0; mt < 4; mt++)
#pragma unroll
                for (int nt = 0; nt < 4; nt++) {
                    int nt2 = nt >> 1, sel = (nt & 1) * 2;
                    mma_f16(acc[mt][nt], af[mt][0], af[mt][1], af[mt][2], af[mt][3],
                            bf[nt2][sel], bf[nt2][sel + 1]);
                }
        }
    }
#undef ISSUE

    bool offdiag = (ti != tj);
    __half* s_t  = (__half*)(smem);
    float* s_rsN = (float*)(smem + 128 * LDT * 2);
    float* s_rsM = s_rsN + 128;
    float* s_m   = s_rsM + 128;
    float* s_s   = s_m + 512;
    __syncthreads();
    if (tid < 128) {
        s_rsN[tid] = g_rscale[b * L_ + n0 + tid];
        s_rsM[tid] = g_rscale[b * L_ + m0 + tid];
    }
    __syncthreads();

    __half* Cc = g_att + (size_t)b * L_ * L_;
    float rm[4][2], rs_[4][2];
#pragma unroll
    for (int mt = 0; mt < 4; mt++) {
        rm[mt][0] = rm[mt][1] = -1e30f;
        rs_[mt][0] = rs_[mt][1] = 0.f;
    }
#pragma unroll
    for (int mt = 0; mt < 4; mt++) {
        int row = wm * 64 + mt * 16 + g;
#pragma unroll
        for (int nt = 0; nt < 4; nt++) {
            int col = wn * 32 + nt * 8 + tig * 2;
            float r0 = s_rsN[col], r1 = s_rsN[col + 1];
            __half2 h0 = __floats2half2_rn(acc[mt][nt][0] * r0, acc[mt][nt][1] * r1);
            __half2 h1 = __floats2half2_rn(acc[mt][nt][2] * r0, acc[mt][nt][3] * r1);
            *(__half2*)&Cc[(size_t)(m0 + row) * L_ + n0 + col] = h0;
            *(__half2*)&Cc[(size_t)(m0 + row + 8) * L_ + n0 + col] = h1;
            sm_upd(rm[mt][0], rs_[mt][0], __low2float(h0));
            sm_upd(rm[mt][0], rs_[mt][0], __high2float(h0));
            sm_upd(rm[mt][1], rs_[mt][1], __low2float(h1));
            sm_upd(rm[mt][1], rs_[mt][1], __high2float(h1));
            if (offdiag) {
                float rM0 = s_rsM[row], rM1 = s_rsM[row + 8];
                s_t[col * LDT + row]           = __float2half_rn(acc[mt][nt][0] * rM0);
                s_t[(col + 1) * LDT + row]     = __float2half_rn(acc[mt][nt][1] * rM0);
                s_t[col * LDT + row + 8]       = __float2half_rn(acc[mt][nt][2] * rM1);
                s_t[(col + 1) * LDT + row + 8] = __float2half_rn(acc[mt][nt][3] * rM1);
            }
        }
    }
#pragma unroll
    for (int mt = 0; mt < 4; mt++)
#pragma unroll
        for (int hh = 0; hh < 2; hh++) {
            float m = rm[mt][hh], s = rs_[mt][hh];
#pragma unroll
            for (int off = 1; off <= 2; off <<= 1) {
                float om = __shfl_xor_sync(0xffffffffu, m, off);
                float os = __shfl_xor_sync(0xffffffffu, s, off);
                sm_comb(m, s, om, os);
            }
            if (tig == 0) {
                int lrow = wm * 64 + mt * 16 + g + hh * 8;
                s_m[lrow * 4 + wn] = m;
                s_s[lrow * 4 + wn] = s;
            }
        }
    __syncthreads();
    if (tid < BM) {
        float M = -1e30f, S = 0.f;
#pragma unroll
        for (int w = 0; w < 4; w++) sm_comb(M, S, s_m[tid * 4 + w], s_s[tid * 4 + w]);
        size_t o = ((size_t)b * NPC + tj) * L_ + m0 + tid;
        g_statm[o] = M;
        g_stats[o] = S;
    }
    if (offdiag) {
        int qr = tid >> 1, sg = (tid & 1) * 64;
        const __half* srow = &s_t[qr * LDT + sg];
        __half* drow = &Cc[(size_t)(n0 + qr) * L_ + m0 + sg];
        float m = -1e30f, s = 0.f;
#pragma unroll
        for (int u = 0; u < 8; u++) {
            uint4 v = *(const uint4*)(srow + u * 8);
            const __half2* hp = (const __half2*)&v;
#pragma unroll
            for (int jj = 0; jj < 4; jj++) {
                sm_upd(m, s, __low2float(hp[jj]));
                sm_upd(m, s, __high2float(hp[jj]));
            }
            *(uint4*)(drow + u * 8) = v;
        }
        float om = __shfl_xor_sync(0xffffffffu, m, 1);
        float os = __shfl_xor_sync(0xffffffffu, s, 1);
        sm_comb(m, s, om, os);
        if ((tid & 1) == 0) {
            size_t o = ((size_t)b * NPC + ti) * L_ + n0 + qr;
            g_statm[o] = m;
            g_stats[o] = s;
        }
    }
}

// ---------------- softmax stage B: combine chunk partials --------------------
__global__ __launch_bounds__(256) void k_smB() {
    int i = blockIdx.x * 256 + threadIdx.x;
    int b = i >> 12, q = i & (L_ - 1);
    float M = -1e30f, S = 0.f;
#pragma unroll 4
    for (int pc = 0; pc < NPC; pc++) {
        size_t o = ((size_t)b * NPC + pc) * L_ + q;
        sm_comb(M, S, g_statm[o], g_stats[o]);
    }
    g_cm[b * L_ + q] = M;
    g_ci[b * L_ + q] = 1.f / S;
}

// ---------------- stage C: chunk-gated sparse list build ---------------------
// one warp per row; lanes hold the 32 chunk maxima; only qualifying chunks scanned.
__global__ __launch_bounds__(256) void k_smC() {
    int b = blockIdx.y;
    int wid = threadIdx.x >> 5, lane = threadIdx.x & 31;
    int r = blockIdx.x * 8 + wid;
    const __half* Ar = g_att + (size_t)b * L_ * L_ + (size_t)r * L_;
    float M = g_cm[b * L_ + r], Iv = g_ci[b * L_ + r];
    const float* mfp = g_mfilt + b * L_;

    // gate: chunk max (mf upper bound 1) — conservative by exp monotonicity
    float sm = g_statm[((size_t)b * NPC + lane) * L_ + r];
    bool qual = (__expf(sm - M) * Iv >= THRESH);
    unsigned qmask = __ballot_sync(0xffffffffu, qual);

    int cnt = 0;
    size_t base = (size_t)(b * L_ + r) * CAP;
    while (qmask) {
        int pc = __ffs(qmask) - 1;
        qmask &= qmask - 1;
        int c = pc * 128 + lane * 4;
        uint2 v = *(const uint2*)&Ar[c];
        __half2 h0 = *(__half2*)&v.x, h1 = *(__half2*)&v.y;
        float4 mfv = *(const float4*)&mfp[c];
        float w[4];
        w[0] = __expf(__low2float(h0) - M) * Iv * mfv.x;
        w[1] = __expf(__high2float(h0) - M) * Iv * mfv.y;
        w[2] = __expf(__low2float(h1) - M) * Iv * mfv.z;
        w[3] = __expf(__high2float(h1) - M) * Iv * mfv.w;
        int lc = (w[0] >= THRESH) + (w[1] >= THRESH) + (w[2] >= THRESH) + (w[3] >= THRESH);
        int incl = lc;
#pragma unroll
        for (int d = 1; d < 32; d <<= 1) {
            int o2 = __shfl_up_sync(0xffffffffu, incl, d);
            if (lane >= d) incl += o2;
        }
        int idx = cnt + incl - lc;
#pragma unroll
        for (int k = 0; k < 4; k++)
            if (w[k] >= THRESH) {
                if (idx < CAP) { g_listp[base + idx] = c + k; g_listw[base + idx] = w[k]; }
                idx++;
            }
        cnt += __shfl_sync(0xffffffffu, incl, 31);
    }
    if (lane == 0) g_cnt[b * L_ + r] = cnt;
}

// ---------------- sparse "GEMM2": outp[q][e] = sum_p w * xu[p][e] ------------
__global__ __launch_bounds__(128) void k_sparse(const float* __restrict__ x) {
    int q = blockIdx.x, b = blockIdx.y;
    int c = threadIdx.x;
    const float* xb = x + ((size_t)b * C_ + c) * (H_ * W_);
    float acc[16];
#pragma unroll
    for (int k = 0; k < 16; k++) acc[k] = 0.f;

    int cnt = g_cnt[b * L_ + q];
    if (cnt <= CAP) {
        size_t base = (size_t)(b * L_ + q) * CAP;
        for (int t = 0; t < cnt; t++) {
            int p = g_listp[base + t];
            float w = g_listw[base + t];
            int py = p >> 6, px = p & 63;
#pragma unroll
            for (int i = 0; i < 4; i++) {
                int ry = 2 * py - 1 + i;
                if ((unsigned)ry >= H_) continue;
#pragma unroll
                for (int jj = 0; jj < 4; jj++) {
                    int rx = 2 * px - 1 + jj;
                    if ((unsigned)rx >= W_) continue;
                    acc[i * 4 + jj] += w * xb[ry * W_ + rx];
                }
            }
        }
    } else {
        const __half* Ar = g_att + (size_t)b * L_ * L_ + (size_t)q * L_;
        float M = g_cm[b * L_ + q], I = g_ci[b * L_ + q];
        const float* mfp = g_mfilt + b * L_;
        for (int p = 0; p < L_; p++) {
            float w = __expf(__half2float(Ar[p]) - M) * I * mfp[p];
            if (w < THRESH) continue;
            int py = p >> 6, px = p & 63;
#pragma unroll
            for (int i = 0; i < 4; i++) {
                int ry = 2 * py - 1 + i;
                if ((unsigned)ry >= H_) continue;
#pragma unroll
                for (int jj = 0; jj < 4; jj++) {
                    int rx = 2 * px - 1 + jj;
                    if ((unsigned)rx >= W_) continue;
                    acc[i * 4 + jj] += w * xb[ry * W_ + rx];
                }
            }
        }
    }
    float* dst = g_outp + ((size_t)(b * L_ + q)) * E_ + c * 16;
#pragma unroll
    for (int k = 0; k < 4; k++)
        *(float4*)&dst[k * 4] = make_float4(acc[k * 4], acc[k * 4 + 1],
                                            acc[k * 4 + 2], acc[k * 4 + 3]);
}

// ---------------- overlap-add combine ----------------------------------------
__global__ __launch_bounds__(256) void k_combine(float* __restrict__ out) {
    int idx = blockIdx.x * blockDim.x + threadIdx.x;
    int xx = idx & 127;
    int y  = (idx >> 7) & 127;
    int c  = (idx >> 14) & 127;
    int b  = idx >> 21;

    const float* P = g_outp + (size_t)b * L_ * E_;
    float s = 0.f;
    int ki0 = (y + 1) & 1;
    int kj0 = (xx + 1) & 1;
#pragma unroll
    for (int ki = 0; ki < 4; ki++) {
        if ((ki & 1) != ki0) continue;
        int sy2 = y + 1 - ki;
        if (sy2 < 0) continue;
        int sy = sy2 >> 1;
        if (sy >= HR) continue;
#pragma unroll
        for (int kj = 0; kj < 4; kj++) {
            if ((kj & 1) != kj0) continue;
            int sx2 = xx + 1 - kj;
            if (sx2 < 0) continue;
            int sx = sx2 >> 1;
            if (sx >= HR) continue;
            s += P[((size_t)((sy << 6) + sx)) * E_ + c * 16 + ki * 4 + kj];
        }
    }
    out[idx] = 0.25f * s;
}

// ---------------- launch ------------------------------------------------------
extern "C" void kernel_launch(void* const* d_in, const int* in_sizes, int n_in,
                              void* d_out, int out_size) {
    const float* x    = (const float*)d_in[0];
    const float* mask = (const float*)d_in[1];
    float* out = (float*)d_out;

    cudaFuncSetAttribute(k_gram, cudaFuncAttributeMaxDynamicSharedMemorySize, SMEM_TOT);

    k_prep<<<dim3(L_, B_), 128>>>(x, mask);
    k_gram<<<dim3(NTRI, 1, B_), 256, SMEM_TOT>>>();
    k_smB<<<(B_ * L_) / 256, 256>>>();
    k_smC<<<dim3(L_ / 8, B_), 256>>>();
    k_sparse<<<dim3(L_, B_), 128>>>(x);
    k_combine<<<(B_ * C_ * H_ * W_) / 256, 256>>>(out);
}

// round 9
// speedup vs baseline: 17.3549x; 1.2058x over previous
#include <cuda_runtime.h>
#include <cuda_fp16.h>
#include <cstdint>
#include <math.h>

#define B_   2
#define C_   128
#define H_   128
#define W_   128
#define HR   64
#define L_   4096
#define F_   1152    // C*9
#define EPS_ 0.0001f
#define SCALE_ 10.0f
#define NPC  32      // softmax chunks = L_/128
#define NTRI 528     // 32*33/2 triangle tiles
#define CAP  32      // sparse list capacity per row
#define THRESH 5.9604645e-8f   // half min subnormal

// ---------------- scratch ----------------------------------------------------
__device__ __half g_pr  [(size_t)B_ * L_ * F_];   // [b][p][f]
__device__ __half g_att [(size_t)B_ * L_ * L_];   // [b][r][c] logits
__device__ float  g_rscale[B_ * L_];
__device__ float  g_mfilt[B_ * L_];
__device__ float  g_statm[(size_t)B_ * NPC * L_];
__device__ float  g_stats[(size_t)B_ * NPC * L_];
__device__ float  g_cm[B_ * L_];
__device__ float  g_ci[B_ * L_];
__device__ int    g_cnt[B_ * L_];
__device__ int    g_listp[(size_t)B_ * L_ * CAP];
__device__ float  g_listw[(size_t)B_ * L_ * CAP];

// ---------------- helpers ----------------------------------------------------
__device__ __forceinline__ uint32_t smem_u32(const void* p) {
    uint32_t a;
    asm("{ .reg .u64 t; cvta.to.shared.u64 t, %1; cvt.u32.u64 %0, t; }" : "=r"(a) : "l"(p));
    return a;
}
__device__ __forceinline__ void cp_async16(uint32_t saddr, const void* g) {
    asm volatile("cp.async.cg.shared.global [%0], [%1], 16;" :: "r"(saddr), "l"(g));
}
#define CP_COMMIT() asm volatile("cp.async.commit_group;" ::: "memory")
#define CP_WAIT(n)  asm volatile("cp.async.wait_group %0;" :: "n"(n) : "memory")

__device__ __forceinline__ void ldsm_x4(uint32_t& r0, uint32_t& r1, uint32_t& r2,
                                        uint32_t& r3, uint32_t addr) {
    asm volatile("ldmatrix.sync.aligned.m8n8.x4.shared.b16 {%0,%1,%2,%3}, [%4];"
                 : "=r"(r0), "=r"(r1), "=r"(r2), "=r"(r3) : "r"(addr));
}
__device__ __forceinline__ void mma_f16(float c[4], uint32_t a0, uint32_t a1,
                                        uint32_t a2, uint32_t a3,
                                        uint32_t b0, uint32_t b1) {
    asm volatile(
        "mma.sync.aligned.m16n8k16.row.col.f32.f16.f16.f32 "
        "{%0,%1,%2,%3}, {%4,%5,%6,%7}, {%8,%9}, {%0,%1,%2,%3};"
        : "+f"(c[0]), "+f"(c[1]), "+f"(c[2]), "+f"(c[3])
        : "r"(a0), "r"(a1), "r"(a2), "r"(a3), "r"(b0), "r"(b1));
}
__device__ __forceinline__ void sm_upd(float& m, float& s, float l) {
    if (l <= m) s += __expf(l - m);
    else { s = s * __expf(m - l) + 1.f; m = l; }
}
__device__ __forceinline__ void sm_comb(float& m, float& s, float om, float os) {
    float M = fmaxf(m, om);
    s = s * __expf(m - M) + os * __expf(om - M);
    m = M;
}

// ---------------- prep: pr (half), rscale, mfilt -----------------------------
__global__ __launch_bounds__(128) void k_prep(const float* __restrict__ x,
                                              const float* __restrict__ mask) {
    int q  = blockIdx.x;
    int b  = blockIdx.y;
    int qy = q >> 6, qx = q & 63;
    int c  = threadIdx.x;
    const float* xb = x + ((size_t)b * C_ + c) * (H_ * W_);

    float ss = 0.f;
    __half* prq = g_pr + ((size_t)(b * L_ + q)) * F_ + c * 9;
#pragma unroll
    for (int di = 0; di < 3; di++) {
        int sy = qy - 1 + di;
#pragma unroll
        for (int dj = 0; dj < 3; dj++) {
            int sx = qx - 1 + dj;
            float v = 0.f;
            if ((unsigned)sy < HR && (unsigned)sx < HR) v = xb[(2 * sy) * W_ + 2 * sx];
            prq[di * 3 + dj] = __float2half_rn(v);
            ss += v * v;
        }
    }
    __shared__ float red[128];
    red[c] = ss;
    __syncthreads();
    for (int off = 64; off > 0; off >>= 1) {
        if (c < off) red[c] += red[c + off];
        __syncthreads();
    }
    if (c == 0) {
        float denom = sqrtf(red[0] + (float)F_ * EPS_);
        const float* mb = mask + (size_t)b * (H_ * W_);
        float msum = 0.f;
#pragma unroll
        for (int di = 0; di < 3; di++) {
            int sy = qy - 1 + di;
#pragma unroll
            for (int dj = 0; dj < 3; dj++) {
                int sx = qx - 1 + dj;
                if ((unsigned)sy < HR && (unsigned)sx < HR) msum += mb[(2 * sy) * W_ + 2 * sx];
            }
        }
        float mf = (msum == 0.f) ? 1.f : 0.f;
        g_mfilt[b * L_ + q]  = mf;
        g_rscale[b * L_ + q] = SCALE_ * mf / denom;
    }
}

// ---------------- triangular Gram GEMM (fp16 mma) + fused stats --------------
#define BM 128
#define BN 128
#define BKH 32
#define LDH 40
#define STAGES 3
#define STG_A (BM * LDH * 2)
#define A_OFF 0
#define B_OFF (STAGES * STG_A)
#define LDT 136
#define SMEM_TOT (2 * STAGES * STG_A + 8 * 1024)

__global__ __launch_bounds__(256) void k_gram() {
    int b = blockIdx.z;
    int t = blockIdx.x;
    int j = (int)((sqrtf(8.f * t + 1.f) - 1.f) * 0.5f);
    while ((j + 1) * (j + 2) / 2 <= t) j++;
    while (j * (j + 1) / 2 > t) j--;
    int ti = t - j * (j + 1) / 2;   // i <= j
    int tj = j;
    int m0 = ti * BM;
    int n0 = tj * BN;
    const __half* A = g_pr + (size_t)b * L_ * F_;
    const int lda = F_;
    const int NI = F_ / BKH;

    extern __shared__ char smem[];
    uint32_t sA = smem_u32(smem) + A_OFF;
    uint32_t sB = smem_u32(smem) + B_OFF;

    int tid  = threadIdx.x;
    int wid  = tid >> 5, lane = tid & 31;
    int wm   = wid >> 2, wn = wid & 3;
    int g    = lane >> 2, tig = lane & 3;

    int arow  = lane & 15;
    int acol8 = (lane >> 4) * 8;
    int bmi   = lane >> 3;
    int brow  = (bmi >> 1) * 8 + (lane & 7);
    int bk8   = (bmi & 1) * 8;

    int rowL = tid >> 2, seg = tid & 3;

    float acc[4][4][4];
#pragma unroll
    for (int mt = 0; mt < 4; mt++)
#pragma unroll
        for (int nt = 0; nt < 4; nt++)
#pragma unroll
            for (int k = 0; k < 4; k++) acc[mt][nt][k] = 0.f;

#define ISSUE(it2) do {                                                          \
    int st_ = (it2) % STAGES;                                                    \
    int k0_ = (it2) * BKH;                                                       \
    _Pragma("unroll")                                                            \
    for (int h_ = 0; h_ < 2; h_++) {                                             \
        int row_ = rowL + h_ * 64;                                               \
        cp_async16(sA + st_ * STG_A + (row_ * LDH + seg * 8) * 2,                \
                   &A[(size_t)(m0 + row_) * lda + k0_ + seg * 8]);               \
        cp_async16(sB + st_ * STG_A + (row_ * LDH + seg * 8) * 2,                \
                   &A[(size_t)(n0 + row_) * lda + k0_ + seg * 8]);               \
    }                                                                            \
} while (0)

    ISSUE(0); CP_COMMIT();
    ISSUE(1); CP_COMMIT();

    for (int it = 0; it < NI; it++) {
        CP_WAIT(1);
        __syncthreads();
        if (it + 2 < NI) ISSUE(it + 2);
        CP_COMMIT();

        uint32_t sAb = sA + (it % STAGES) * STG_A;
        uint32_t sBb = sB + (it % STAGES) * STG_A;
#pragma unroll
        for (int ks = 0; ks < 2; ks++) {
            int ko = ks * 16;
            uint32_t af[4][4];
#pragma unroll
            for (int mt = 0; mt < 4; mt++)
                ldsm_x4(af[mt][0], af[mt][1], af[mt][2], af[mt][3],
                        sAb + ((wm * 64 + mt * 16 + arow) * LDH + ko + acol8) * 2);
            uint32_t bf[2][4];
#pragma unroll
            for (int nt2 = 0; nt2 < 2; nt2++)
                ldsm_x4(bf[nt2][0], bf[nt2][1], bf[nt2][2], bf[nt2][3],
                        sBb + ((wn * 32 + nt2 * 16 + brow) * LDH + ko + bk8) * 2);
#pragma unroll
            for (int mt = 0; mt < 4; mt++)
#pragma unroll
                for (int nt = 0; nt < 4; nt++) {
                    int nt2 = nt >> 1, sel = (nt & 1) * 2;
                    mma_f16(acc[mt][nt], af[mt][0], af[mt][1], af[mt][2], af[mt][3],
                            bf[nt2][sel], bf[nt2][sel + 1]);
                }
        }
    }
#undef ISSUE

    bool offdiag = (ti != tj);
    __half* s_t  = (__half*)(smem);
    float* s_rsN = (float*)(smem + 128 * LDT * 2);
    float* s_rsM = s_rsN + 128;
    float* s_m   = s_rsM + 128;
    float* s_s   = s_m + 512;
    __syncthreads();
    if (tid < 128) {
        s_rsN[tid] = g_rscale[b * L_ + n0 + tid];
        s_rsM[tid] = g_rscale[b * L_ + m0 + tid];
    }
    __syncthreads();

    __half* Cc = g_att + (size_t)b * L_ * L_;
    float rm[4][2], rs_[4][2];
#pragma unroll
    for (int mt = 0; mt < 4; mt++) {
        rm[mt][0] = rm[mt][1] = -1e30f;
        rs_[mt][0] = rs_[mt][1] = 0.f;
    }
#pragma unroll
    for (int mt = 0; mt < 4; mt++) {
        int row = wm * 64 + mt * 16 + g;
#pragma unroll
        for (int nt = 0; nt < 4; nt++) {
            int col = wn * 32 + nt * 8 + tig * 2;
            float r0 = s_rsN[col], r1 = s_rsN[col + 1];
            __half2 h0 = __floats2half2_rn(acc[mt][nt][0] * r0, acc[mt][nt][1] * r1);
            __half2 h1 = __floats2half2_rn(acc[mt][nt][2] * r0, acc[mt][nt][3] * r1);
            *(__half2*)&Cc[(size_t)(m0 + row) * L_ + n0 + col] = h0;
            *(__half2*)&Cc[(size_t)(m0 + row + 8) * L_ + n0 + col] = h1;
            sm_upd(rm[mt][0], rs_[mt][0], __low2float(h0));
            sm_upd(rm[mt][0], rs_[mt][0], __high2float(h0));
            sm_upd(rm[mt][1], rs_[mt][1], __low2float(h1));
            sm_upd(rm[mt][1], rs_[mt][1], __high2float(h1));
            if (offdiag) {
                float rM0 = s_rsM[row], rM1 = s_rsM[row + 8];
                s_t[col * LDT + row]           = __float2half_rn(acc[mt][nt][0] * rM0);
                s_t[(col + 1) * LDT + row]     = __float2half_rn(acc[mt][nt][1] * rM0);
                s_t[col * LDT + row + 8]       = __float2half_rn(acc[mt][nt][2] * rM1);
                s_t[(col + 1) * LDT + row + 8] = __float2half_rn(acc[mt][nt][3] * rM1);
            }
        }
    }
#pragma unroll
    for (int mt = 0; mt < 4; mt++)
#pragma unroll
        for (int hh = 0; hh < 2; hh++) {
            float m = rm[mt][hh], s = rs_[mt][hh];
#pragma unroll
            for (int off = 1; off <= 2; off <<= 1) {
                float om = __shfl_xor_sync(0xffffffffu, m, off);
                float os = __shfl_xor_sync(0xffffffffu, s, off);
                sm_comb(m, s, om, os);
            }
            if (tig == 0) {
                int lrow = wm * 64 + mt * 16 + g + hh * 8;
                s_m[lrow * 4 + wn] = m;
                s_s[lrow * 4 + wn] = s;
            }
        }
    __syncthreads();
    if (tid < BM) {
        float M = -1e30f, S = 0.f;
#pragma unroll
        for (int w = 0; w < 4; w++) sm_comb(M, S, s_m[tid * 4 + w], s_s[tid * 4 + w]);
        size_t o = ((size_t)b * NPC + tj) * L_ + m0 + tid;
        g_statm[o] = M;
        g_stats[o] = S;
    }
    if (offdiag) {
        int qr = tid >> 1, sg = (tid & 1) * 64;
        const __half* srow = &s_t[qr * LDT + sg];
        __half* drow = &Cc[(size_t)(n0 + qr) * L_ + m0 + sg];
        float m = -1e30f, s = 0.f;
#pragma unroll
        for (int u = 0; u < 8; u++) {
            uint4 v = *(const uint4*)(srow + u * 8);
            const __half2* hp = (const __half2*)&v;
#pragma unroll
            for (int jj = 0; jj < 4; jj++) {
                sm_upd(m, s, __low2float(hp[jj]));
                sm_upd(m, s, __high2float(hp[jj]));
            }
            *(uint4*)(drow + u * 8) = v;
        }
        float om = __shfl_xor_sync(0xffffffffu, m, 1);
        float os = __shfl_xor_sync(0xffffffffu, s, 1);
        sm_comb(m, s, om, os);
        if ((tid & 1) == 0) {
            size_t o = ((size_t)b * NPC + ti) * L_ + n0 + qr;
            g_statm[o] = m;
            g_stats[o] = s;
        }
    }
}

// ---------------- stage C: combine stats + chunk-gated list build -----------
// one warp per row; lane = chunk. Butterfly-combine (M,S), gate, scan chunks.
__global__ __launch_bounds__(256) void k_smC() {
    int b = blockIdx.y;
    int wid = threadIdx.x >> 5, lane = threadIdx.x & 31;
    int r = blockIdx.x * 8 + wid;
    const __half* Ar = g_att + (size_t)b * L_ * L_ + (size_t)r * L_;
    const float* mfp = g_mfilt + b * L_;

    // per-lane chunk partials -> global (M, S) via butterfly
    float sm = g_statm[((size_t)b * NPC + lane) * L_ + r];
    float ms = sm, ss = g_stats[((size_t)b * NPC + lane) * L_ + r];
#pragma unroll
    for (int off = 16; off > 0; off >>= 1) {
        float om = __shfl_xor_sync(0xffffffffu, ms, off);
        float os = __shfl_xor_sync(0xffffffffu, ss, off);
        sm_comb(ms, ss, om, os);
    }
    float M = ms, Iv = 1.f / ss;
    if (lane == 0) { g_cm[b * L_ + r] = M; g_ci[b * L_ + r] = Iv; }

    bool qual = (__expf(sm - M) * Iv >= THRESH);
    unsigned qmask = __ballot_sync(0xffffffffu, qual);

    int cnt = 0;
    size_t base = (size_t)(b * L_ + r) * CAP;
    while (qmask) {
        int pc = __ffs(qmask) - 1;
        qmask &= qmask - 1;
        int c = pc * 128 + lane * 4;
        uint2 v = *(const uint2*)&Ar[c];
        __half2 h0 = *(__half2*)&v.x, h1 = *(__half2*)&v.y;
        float4 mfv = *(const float4*)&mfp[c];
        float w[4];
        w[0] = __expf(__low2float(h0) - M) * Iv * mfv.x;
        w[1] = __expf(__high2float(h0) - M) * Iv * mfv.y;
        w[2] = __expf(__low2float(h1) - M) * Iv * mfv.z;
        w[3] = __expf(__high2float(h1) - M) * Iv * mfv.w;
        int lc = (w[0] >= THRESH) + (w[1] >= THRESH) + (w[2] >= THRESH) + (w[3] >= THRESH);
        int incl = lc;
#pragma unroll
        for (int d = 1; d < 32; d <<= 1) {
            int o2 = __shfl_up_sync(0xffffffffu, incl, d);
            if (lane >= d) incl += o2;
        }
        int idx = cnt + incl - lc;
#pragma unroll
        for (int k = 0; k < 4; k++)
            if (w[k] >= THRESH) {
                if (idx < CAP) { g_listp[base + idx] = c + k; g_listw[base + idx] = w[k]; }
                idx++;
            }
        cnt += __shfl_sync(0xffffffffu, incl, 31);
    }
    if (lane == 0) g_cnt[b * L_ + r] = cnt;
}

// ---------------- fused sparse apply + overlap-add ---------------------------
// out[b,c,y,x] = 0.25 * sum over overlapping q of sum_{(p,w) in list(q)}
//               w * x[c, 2py-1+ki, 2px-1+kj]
__global__ __launch_bounds__(128) void k_out(const float* __restrict__ x,
                                             float* __restrict__ out) {
    int y = blockIdx.x, c = blockIdx.y, b = blockIdx.z;
    int xx = threadIdx.x;
    const float* xb = x + ((size_t)b * C_ + c) * (H_ * W_);

    float acc = 0.f;
    int ki0 = (y + 1) & 1;
    int kj0 = (xx + 1) & 1;
#pragma unroll
    for (int a = 0; a < 2; a++) {
        int ki = ki0 + a * 2;
        int sy2 = y + 1 - ki;
        if (sy2 < 0) continue;
        int sy = sy2 >> 1;
        if (sy >= HR) continue;
#pragma unroll
        for (int bb = 0; bb < 2; bb++) {
            int kj = kj0 + bb * 2;
            int sx2 = xx + 1 - kj;
            if (sx2 < 0) continue;
            int sx = sx2 >> 1;
            if (sx >= HR) continue;
            int q = (sy << 6) + sx;
            int cnt = g_cnt[b * L_ + q];
            if (cnt <= CAP) {
                size_t base = (size_t)(b * L_ + q) * CAP;
                for (int t = 0; t < cnt; t++) {
                    int p = g_listp[base + t];
                    float w = g_listw[base + t];
                    int py = p >> 6, px = p & 63;
                    int ry = 2 * py - 1 + ki, rx = 2 * px - 1 + kj;
                    if ((unsigned)ry < H_ && (unsigned)rx < W_)
                        acc += w * __ldg(&xb[ry * W_ + rx]);
                }
            } else {
                // dense fallback (never hit on benign data; exactness guard)
                const __half* Ar = g_att + (size_t)b * L_ * L_ + (size_t)q * L_;
                float M = g_cm[b * L_ + q], Iv = g_ci[b * L_ + q];
                const float* mfp = g_mfilt + b * L_;
                for (int p = 0; p < L_; p++) {
                    float w = __expf(__half2float(Ar[p]) - M) * Iv * mfp[p];
                    if (w < THRESH) continue;
                    int py = p >> 6, px = p & 63;
                    int ry = 2 * py - 1 + ki, rx = 2 * px - 1 + kj;
                    if ((unsigned)ry < H_ && (unsigned)rx < W_)
                        acc += w * __ldg(&xb[ry * W_ + rx]);
                }
            }
        }
    }
    out[(((size_t)b * C_ + c) * H_ + y) * W_ + xx] = 0.25f * acc;
}

// ---------------- launch ------------------------------------------------------
extern "C" void kernel_launch(void* const* d_in, const int* in_sizes, int n_in,
                              void* d_out, int out_size) {
    const float* x    = (const float*)d_in[0];
    const float* mask = (const float*)d_in[1];
    float* out = (float*)d_out;

    cudaFuncSetAttribute(k_gram, cudaFuncAttributeMaxDynamicSharedMemorySize, SMEM_TOT);

    k_prep<<<dim3(L_, B_), 128>>>(x, mask);
    k_gram<<<dim3(NTRI, 1, B_), 256, SMEM_TOT>>>();
    k_smC<<<dim3(L_ / 8, B_), 256>>>();
    k_out<<<dim3(H_, C_, B_), 128>>>(x, out);
}

// round 10
// speedup vs baseline: 20.6012x; 1.1871x over previous
#include <cuda_runtime.h>
#include <cuda_fp16.h>
#include <cstdint>
#include <math.h>

#define B_   2
#define C_   128
#define H_   128
#define W_   128
#define HR   64
#define L_   4096
#define EPS_ 0.0001f
#define SCALE_ 10.0f
#define NPC  32
#define CAP  32
#define THRESH 5.9604645e-8f
#define F_FULL 1152.0f

// ---------------- scratch ----------------------------------------------------
__device__ __half g_xd [(size_t)B_ * L_ * 128];  // [b][q][c] downsampled center
__device__ __half g_R  [(size_t)B_ * L_ * L_];   // [b][p][q] correlation
__device__ __half g_att[(size_t)B_ * L_ * L_];   // [b][r][c] logits
__device__ float  g_rscale[B_ * L_];
__device__ float  g_mfilt[B_ * L_];
__device__ float  g_statm[(size_t)B_ * NPC * L_];
__device__ float  g_stats[(size_t)B_ * NPC * L_];
__device__ float  g_cm[B_ * L_];
__device__ float  g_ci[B_ * L_];
__device__ int    g_cnt[B_ * L_];
__device__ int    g_listp[(size_t)B_ * L_ * CAP];
__device__ float  g_listw[(size_t)B_ * L_ * CAP];

// ---------------- helpers ----------------------------------------------------
__device__ __forceinline__ uint32_t smem_u32(const void* p) {
    uint32_t a;
    asm("{ .reg .u64 t; cvta.to.shared.u64 t, %1; cvt.u32.u64 %0, t; }" : "=r"(a) : "l"(p));
    return a;
}
__device__ __forceinline__ void cp_async16(uint32_t saddr, const void* g) {
    asm volatile("cp.async.cg.shared.global [%0], [%1], 16;" :: "r"(saddr), "l"(g));
}
#define CP_COMMIT() asm volatile("cp.async.commit_group;" ::: "memory")
#define CP_WAIT(n)  asm volatile("cp.async.wait_group %0;" :: "n"(n) : "memory")

__device__ __forceinline__ void ldsm_x4(uint32_t& r0, uint32_t& r1, uint32_t& r2,
                                        uint32_t& r3, uint32_t addr) {
    asm volatile("ldmatrix.sync.aligned.m8n8.x4.shared.b16 {%0,%1,%2,%3}, [%4];"
                 : "=r"(r0), "=r"(r1), "=r"(r2), "=r"(r3) : "r"(addr));
}
__device__ __forceinline__ void mma_f16(float c[4], uint32_t a0, uint32_t a1,
                                        uint32_t a2, uint32_t a3,
                                        uint32_t b0, uint32_t b1) {
    asm volatile(
        "mma.sync.aligned.m16n8k16.row.col.f32.f16.f16.f32 "
        "{%0,%1,%2,%3}, {%4,%5,%6,%7}, {%8,%9}, {%0,%1,%2,%3};"
        : "+f"(c[0]), "+f"(c[1]), "+f"(c[2]), "+f"(c[3])
        : "r"(a0), "r"(a1), "r"(a2), "r"(a3), "r"(b0), "r"(b1));
}
__device__ __forceinline__ void sm_upd(float& m, float& s, float l) {
    if (l <= m) s += __expf(l - m);
    else { s = s * __expf(m - l) + 1.f; m = l; }
}
__device__ __forceinline__ void sm_comb(float& m, float& s, float om, float os) {
    float M = fmaxf(m, om);
    s = s * __expf(m - M) + os * __expf(om - M);
    m = M;
}

// ---------------- prep: xd (half center), rscale, mfilt ----------------------
__global__ __launch_bounds__(128) void k_prep(const float* __restrict__ x,
                                              const float* __restrict__ mask) {
    int q  = blockIdx.x;
    int b  = blockIdx.y;
    int qy = q >> 6, qx = q & 63;
    int c  = threadIdx.x;
    const float* xb = x + ((size_t)b * C_ + c) * (H_ * W_);

    float ss = 0.f;
#pragma unroll
    for (int di = 0; di < 3; di++) {
        int sy = qy - 1 + di;
#pragma unroll
        for (int dj = 0; dj < 3; dj++) {
            int sx = qx - 1 + dj;
            float v = 0.f;
            if ((unsigned)sy < HR && (unsigned)sx < HR) v = xb[(2 * sy) * W_ + 2 * sx];
            ss += v * v;
            if (di == 1 && dj == 1)
                g_xd[((size_t)(b * L_ + q)) * 128 + c] = __float2half_rn(v);
        }
    }
    __shared__ float red[128];
    red[c] = ss;
    __syncthreads();
    for (int off = 64; off > 0; off >>= 1) {
        if (c < off) red[c] += red[c + off];
        __syncthreads();
    }
    if (c == 0) {
        float denom = sqrtf(red[0] + F_FULL * EPS_);
        const float* mb = mask + (size_t)b * (H_ * W_);
        float msum = 0.f;
#pragma unroll
        for (int di = 0; di < 3; di++) {
            int sy = qy - 1 + di;
#pragma unroll
            for (int dj = 0; dj < 3; dj++) {
                int sx = qx - 1 + dj;
                if ((unsigned)sy < HR && (unsigned)sx < HR) msum += mb[(2 * sy) * W_ + 2 * sx];
            }
        }
        float mf = (msum == 0.f) ? 1.f : 0.f;
        g_mfilt[b * L_ + q]  = mf;
        g_rscale[b * L_ + q] = SCALE_ * mf / denom;
    }
}

// ---------------- k_R: R[p][q] = xd[p] . xd[q]  (K=128, half out) ------------
#define BM 128
#define BN 128
#define BKH 32
#define LDH 40
#define STAGES 3
#define STG_A (BM * LDH * 2)
#define SMEM_R (2 * STAGES * STG_A)   // 61440

__global__ __launch_bounds__(256) void k_R() {
    int b = blockIdx.z;
    int m0 = blockIdx.y * BM;
    int n0 = blockIdx.x * BN;
    const __half* A = g_xd + (size_t)b * L_ * 128;
    const int lda = 128;
    const int NI = 4;   // K=128 / 32

    extern __shared__ char smem[];
    uint32_t sA = smem_u32(smem);
    uint32_t sB = sA + STAGES * STG_A;

    int tid  = threadIdx.x;
    int wid  = tid >> 5, lane = tid & 31;
    int wm   = wid >> 2, wn = wid & 3;
    int g    = lane >> 2, tig = lane & 3;

    int arow  = lane & 15;
    int acol8 = (lane >> 4) * 8;
    int bmi   = lane >> 3;
    int brow  = (bmi >> 1) * 8 + (lane & 7);
    int bk8   = (bmi & 1) * 8;

    int rowL = tid >> 2, seg = tid & 3;

    float acc[4][4][4];
#pragma unroll
    for (int mt = 0; mt < 4; mt++)
#pragma unroll
        for (int nt = 0; nt < 4; nt++)
#pragma unroll
            for (int k = 0; k < 4; k++) acc[mt][nt][k] = 0.f;

#define ISSUE(it2) do {                                                          \
    int st_ = (it2) % STAGES;                                                    \
    int k0_ = (it2) * BKH;                                                       \
    _Pragma("unroll")                                                            \
    for (int h_ = 0; h_ < 2; h_++) {                                             \
        int row_ = rowL + h_ * 64;                                               \
        cp_async16(sA + st_ * STG_A + (row_ * LDH + seg * 8) * 2,                \
                   &A[(size_t)(m0 + row_) * lda + k0_ + seg * 8]);               \
        cp_async16(sB + st_ * STG_A + (row_ * LDH + seg * 8) * 2,                \
                   &A[(size_t)(n0 + row_) * lda + k0_ + seg * 8]);               \
    }                                                                            \
} while (0)

    ISSUE(0); CP_COMMIT();
    ISSUE(1); CP_COMMIT();

    for (int it = 0; it < NI; it++) {
        CP_WAIT(1);
        __syncthreads();
        if (it + 2 < NI) ISSUE(it + 2);
        CP_COMMIT();

        uint32_t sAb = sA + (it % STAGES) * STG_A;
        uint32_t sBb = sB + (it % STAGES) * STG_A;
#pragma unroll
        for (int ks = 0; ks < 2; ks++) {
            int ko = ks * 16;
            uint32_t af[4][4];
#pragma unroll
            for (int mt = 0; mt < 4; mt++)
                ldsm_x4(af[mt][0], af[mt][1], af[mt][2], af[mt][3],
                        sAb + ((wm * 64 + mt * 16 + arow) * LDH + ko + acol8) * 2);
            uint32_t bf[2][4];
#pragma unroll
            for (int nt2 = 0; nt2 < 2; nt2++)
                ldsm_x4(bf[nt2][0], bf[nt2][1], bf[nt2][2], bf[nt2][3],
                        sBb + ((wn * 32 + nt2 * 16 + brow) * LDH + ko + bk8) * 2);
#pragma unroll
            for (int mt = 0; mt < 4; mt++)
#pragma unroll
                for (int nt = 0; nt < 4; nt++) {
                    int nt2 = nt >> 1, sel = (nt & 1) * 2;
                    mma_f16(acc[mt][nt], af[mt][0], af[mt][1], af[mt][2], af[mt][3],
                            bf[nt2][sel], bf[nt2][sel + 1]);
                }
        }
    }
#undef ISSUE

    __half* Rr = g_R + (size_t)b * L_ * L_;
#pragma unroll
    for (int mt = 0; mt < 4; mt++) {
        int row = m0 + wm * 64 + mt * 16 + g;
#pragma unroll
        for (int nt = 0; nt < 4; nt++) {
            int col = n0 + wn * 32 + nt * 8 + tig * 2;
            *(__half2*)&Rr[(size_t)row * L_ + col] =
                __floats2half2_rn(acc[mt][nt][0], acc[mt][nt][1]);
            *(__half2*)&Rr[(size_t)(row + 8) * L_ + col] =
                __floats2half2_rn(acc[mt][nt][2], acc[mt][nt][3]);
        }
    }
}

// ---------------- k_att: 9-point diagonal stencil of R + rs + stats ----------
#define AT_R 16
#define AT_C 512
#define AT_SROWS 54
#define AT_SCOLS 656
#define AT_SC32 (AT_SCOLS / 2)
#define AT_SMEM (AT_SROWS * AT_SCOLS * 2 + AT_C * 4)   // 72896

__global__ __launch_bounds__(256) void k_att() {
    int b  = blockIdx.z;
    int c0 = blockIdx.x * AT_C;
    int rb0 = blockIdx.y * AT_R;
    extern __shared__ char smc[];
    __half* sR = (__half*)smc;
    const uint32_t* sR32 = (const uint32_t*)smc;
    float* s_rs = (float*)(smc + AT_SROWS * AT_SCOLS * 2);
    const __half* Rg = g_R + (size_t)b * L_ * L_;
    int tid = threadIdx.x;

    for (int i = tid; i < AT_C; i += 256) s_rs[i] = g_rscale[b * L_ + c0 + i];

    for (int i = tid; i < AT_SROWS * (AT_SCOLS / 8); i += 256) {
        int srow = i / (AT_SCOLS / 8);
        int v8   = i % (AT_SCOLS / 8);
        int band = srow / 18, within = srow % 18;
        int rr = rb0 + 64 * (band - 1) - 1 + within;
        int gc0 = c0 - 72 + v8 * 8;
        if ((unsigned)rr < (unsigned)L_ && gc0 >= 0 && gc0 + 8 <= L_) {
            *(uint4*)&sR[srow * AT_SCOLS + v8 * 8] = *(const uint4*)&Rg[(size_t)rr * L_ + gc0];
        } else {
            for (int k2 = 0; k2 < 8; k2++) {
                int gc = gc0 + k2;
                __half hv = ((unsigned)rr < (unsigned)L_ && (unsigned)gc < (unsigned)L_)
                                ? Rg[(size_t)rr * L_ + gc] : __float2half(0.f);
                sR[srow * AT_SCOLS + v8 * 8 + k2] = hv;
            }
        }
    }
    __syncthreads();

    int w = tid >> 5, lane = tid & 31;
    float fl0  = (lane > 0)  ? 1.f : 0.f;
    float fl31 = (lane < 31) ? 1.f : 0.f;
    __half* att = g_att + (size_t)b * L_ * L_;

    for (int rr2 = 0; rr2 < 2; rr2++) {
        int k = w * 2 + rr2;
        int r = rb0 + k;
        int ry = r >> 6, rx = r & 63;
        float frxm1 = (rx > 0)  ? 1.f : 0.f;
        float frx1  = (rx < 63) ? 1.f : 0.f;
        bool vrym1 = (ry > 0), vry1 = (ry < 63);
        float m = -1e30f, s = 0.f;
        for (int cc = 0; cc < 8; cc++) {
            int cy = (c0 >> 6) + cc;
            int lc = cc * 64 + lane * 2;
            int c  = c0 + lc;
            float g0 = 0.f, g1 = 0.f;
#pragma unroll
            for (int dy = -1; dy <= 1; dy++) {
                bool vy = (dy < 0) ? (vrym1 && cy > 0)
                                   : ((dy > 0) ? (vry1 && cy < 63) : true);
                if (!vy) continue;
                int sb = (dy + 1) * 18 + k + 1;
                int cb = lc + 64 * dy + 72;     // even
                const uint32_t* rm1 = sR32 + (sb - 1) * AT_SC32;
                const uint32_t* rw0 = sR32 + sb * AT_SC32;
                const uint32_t* rp1 = sR32 + (sb + 1) * AT_SC32;
                uint32_t uA1 = rm1[(cb - 2) >> 1];
                uint32_t uA2 = rm1[cb >> 1];
                uint32_t uB  = rw0[cb >> 1];
                uint32_t uC1 = rp1[cb >> 1];
                uint32_t uC2 = rp1[(cb + 2) >> 1];
                __half2 hA1 = *(__half2*)&uA1, hA2 = *(__half2*)&uA2;
                __half2 hB  = *(__half2*)&uB;
                __half2 hC1 = *(__half2*)&uC1, hC2 = *(__half2*)&uC2;
                g0 += frxm1 * fl0 * __high2float(hA1) + __low2float(hB)
                      + frx1 * __high2float(hC1);
                g1 += frxm1 * __low2float(hA2) + __high2float(hB)
                      + frx1 * fl31 * __low2float(hC2);
            }
            __half2 h = __floats2half2_rn(g0 * s_rs[lc], g1 * s_rs[lc + 1]);
            *(__half2*)&att[(size_t)r * L_ + c] = h;
            sm_upd(m, s, __low2float(h));
            sm_upd(m, s, __high2float(h));
            if (cc & 1) {
                float mm = m, ss = s;
#pragma unroll
                for (int off = 16; off > 0; off >>= 1) {
                    float om = __shfl_xor_sync(0xffffffffu, mm, off);
                    float os = __shfl_xor_sync(0xffffffffu, ss, off);
                    sm_comb(mm, ss, om, os);
                }
                if (lane == 0) {
                    int pc = (c0 >> 7) + (cc >> 1);
                    size_t o = ((size_t)b * NPC + pc) * L_ + r;
                    g_statm[o] = mm;
                    g_stats[o] = ss;
                }
                m = -1e30f; s = 0.f;
            }
        }
    }
}

// ---------------- stage C: combine stats + chunk-gated list build ------------
__global__ __launch_bounds__(256) void k_smC() {
    int b = blockIdx.y;
    int wid = threadIdx.x >> 5, lane = threadIdx.x & 31;
    int r = blockIdx.x * 8 + wid;
    const __half* Ar = g_att + (size_t)b * L_ * L_ + (size_t)r * L_;
    const float* mfp = g_mfilt + b * L_;

    float sm = g_statm[((size_t)b * NPC + lane) * L_ + r];
    float ms = sm, ss = g_stats[((size_t)b * NPC + lane) * L_ + r];
#pragma unroll
    for (int off = 16; off > 0; off >>= 1) {
        float om = __shfl_xor_sync(0xffffffffu, ms, off);
        float os = __shfl_xor_sync(0xffffffffu, ss, off);
        sm_comb(ms, ss, om, os);
    }
    float M = ms, Iv = 1.f / ss;
    if (lane == 0) { g_cm[b * L_ + r] = M; g_ci[b * L_ + r] = Iv; }

    bool qual = (__expf(sm - M) * Iv >= THRESH);
    unsigned qmask = __ballot_sync(0xffffffffu, qual);

    int cnt = 0;
    size_t base = (size_t)(b * L_ + r) * CAP;
    while (qmask) {
        int pc = __ffs(qmask) - 1;
        qmask &= qmask - 1;
        int c = pc * 128 + lane * 4;
        uint2 v = *(const uint2*)&Ar[c];
        __half2 h0 = *(__half2*)&v.x, h1 = *(__half2*)&v.y;
        float4 mfv = *(const float4*)&mfp[c];
        float wv[4];
        wv[0] = __expf(__low2float(h0) - M) * Iv * mfv.x;
        wv[1] = __expf(__high2float(h0) - M) * Iv * mfv.y;
        wv[2] = __expf(__low2float(h1) - M) * Iv * mfv.z;
        wv[3] = __expf(__high2float(h1) - M) * Iv * mfv.w;
        int lc = (wv[0] >= THRESH) + (wv[1] >= THRESH) + (wv[2] >= THRESH) + (wv[3] >= THRESH);
        int incl = lc;
#pragma unroll
        for (int d = 1; d < 32; d <<= 1) {
            int o2 = __shfl_up_sync(0xffffffffu, incl, d);
            if (lane >= d) incl += o2;
        }
        int idx = cnt + incl - lc;
#pragma unroll
        for (int k = 0; k < 4; k++)
            if (wv[k] >= THRESH) {
                if (idx < CAP) { g_listp[base + idx] = c + k; g_listw[base + idx] = wv[k]; }
                idx++;
            }
        cnt += __shfl_sync(0xffffffffu, incl, 31);
    }
    if (lane == 0) g_cnt[b * L_ + r] = cnt;
}

// ---------------- fused sparse apply + overlap-add (channel-amortized) -------
__global__ __launch_bounds__(128) void k_out(const float* __restrict__ x,
                                             float* __restrict__ out) {
    int y = blockIdx.x, cg = blockIdx.y, b = blockIdx.z;
    int xx = threadIdx.x;
    int c0 = cg * 16;
    const float* xb = x + (size_t)(b * C_ + c0) * (H_ * W_);
    float acc[16];
#pragma unroll
    for (int k = 0; k < 16; k++) acc[k] = 0.f;

    int ki0 = (y + 1) & 1, kj0 = (xx + 1) & 1;
#pragma unroll
    for (int a = 0; a < 2; a++) {
        int ki = ki0 + a * 2;
        int sy2 = y + 1 - ki;
        if (sy2 < 0) continue;
        int sy = sy2 >> 1;
        if (sy >= HR) continue;
#pragma unroll
        for (int bb = 0; bb < 2; bb++) {
            int kj = kj0 + bb * 2;
            int sx2 = xx + 1 - kj;
            if (sx2 < 0) continue;
            int sx = sx2 >> 1;
            if (sx >= HR) continue;
            int q = (sy << 6) + sx;
            int cnt = g_cnt[b * L_ + q];
            if (cnt <= CAP) {
                size_t base = (size_t)(b * L_ + q) * CAP;
                for (int t = 0; t < cnt; t++) {
                    int p = g_listp[base + t];
                    float wv = g_listw[base + t];
                    int py = p >> 6, px = p & 63;
                    int ry = 2 * py - 1 + ki, rx = 2 * px - 1 + kj;
                    if ((unsigned)ry < H_ && (unsigned)rx < W_) {
                        int off = ry * W_ + rx;
#pragma unroll
                        for (int cn = 0; cn < 16; cn++)
                            acc[cn] += wv * __ldg(&xb[(size_t)cn * (H_ * W_) + off]);
                    }
                }
            } else {
                // dense fallback (exactness guard; not hit on benign data)
                const __half* Ar = g_att + (size_t)b * L_ * L_ + (size_t)q * L_;
                float M = g_cm[b * L_ + q], Iv = g_ci[b * L_ + q];
                const float* mfp = g_mfilt + b * L_;
                for (int p = 0; p < L_; p++) {
                    float wv = __expf(__half2float(Ar[p]) - M) * Iv * mfp[p];
                    if (wv < THRESH) continue;
                    int py = p >> 6, px = p & 63;
                    int ry = 2 * py - 1 + ki, rx = 2 * px - 1 + kj;
                    if ((unsigned)ry < H_ && (unsigned)rx < W_) {
                        int off = ry * W_ + rx;
                        for (int cn = 0; cn < 16; cn++)
                            acc[cn] += wv * __ldg(&xb[(size_t)cn * (H_ * W_) + off]);
                    }
                }
            }
        }
    }
#pragma unroll
    for (int cn = 0; cn < 16; cn++)
        out[(((size_t)(b * C_ + c0 + cn)) * H_ + y) * W_ + xx] = 0.25f * acc[cn];
}

// ---------------- launch ------------------------------------------------------
extern "C" void kernel_launch(void* const* d_in, const int* in_sizes, int n_in,
                              void* d_out, int out_size) {
    const float* x    = (const float*)d_in[0];
    const float* mask = (const float*)d_in[1];
    float* out = (float*)d_out;

    cudaFuncSetAttribute(k_R, cudaFuncAttributeMaxDynamicSharedMemorySize, SMEM_R);
    cudaFuncSetAttribute(k_att, cudaFuncAttributeMaxDynamicSharedMemorySize, AT_SMEM);

    k_prep<<<dim3(L_, B_), 128>>>(x, mask);
    k_R<<<dim3(L_ / BN, L_ / BM, B_), 256, SMEM_R>>>();
    k_att<<<dim3(L_ / AT_C, L_ / AT_R, B_), 256, AT_SMEM>>>();
    k_smC<<<dim3(L_ / 8, B_), 256>>>();
    k_out<<<dim3(H_, 8, B_), 128>>>(x, out);
}

// round 11
// speedup vs baseline: 23.2810x; 1.1301x over previous
#include <cuda_runtime.h>
#include <cuda_fp16.h>
#include <cstdint>
#include <math.h>

#define B_   2
#define C_   128
#define H_   128
#define W_   128
#define HR   64
#define L_   4096
#define EPS_ 0.0001f
#define SCALE_ 10.0f
#define NPC  32
#define CAP  32
#define THRESH 5.9604645e-8f
#define F_FULL 1152.0f

// ---------------- scratch ----------------------------------------------------
__device__ __half g_xd [(size_t)B_ * L_ * 128];  // [b][q][c]
__device__ float  g_S2 [B_ * L_];                // per-pixel channel sum of squares
__device__ __half g_R  [(size_t)B_ * L_ * L_];   // [b][p][q] correlation
__device__ __half g_att[(size_t)B_ * L_ * L_];   // [b][r][c] logits
__device__ float  g_rscale[B_ * L_];
__device__ float  g_mfilt[B_ * L_];
__device__ float  g_statm[(size_t)B_ * NPC * L_];
__device__ float  g_stats[(size_t)B_ * NPC * L_];
__device__ float  g_cm[B_ * L_];
__device__ float  g_ci[B_ * L_];
__device__ int    g_cnt[B_ * L_];
__device__ int    g_listp[(size_t)B_ * L_ * CAP];
__device__ float  g_listw[(size_t)B_ * L_ * CAP];

// ---------------- helpers ----------------------------------------------------
__device__ __forceinline__ uint32_t smem_u32(const void* p) {
    uint32_t a;
    asm("{ .reg .u64 t; cvta.to.shared.u64 t, %1; cvt.u32.u64 %0, t; }" : "=r"(a) : "l"(p));
    return a;
}
__device__ __forceinline__ void cp_async16(uint32_t saddr, const void* g) {
    asm volatile("cp.async.cg.shared.global [%0], [%1], 16;" :: "r"(saddr), "l"(g));
}
#define CP_COMMIT() asm volatile("cp.async.commit_group;" ::: "memory")
#define CP_WAIT(n)  asm volatile("cp.async.wait_group %0;" :: "n"(n) : "memory")

__device__ __forceinline__ void ldsm_x4(uint32_t& r0, uint32_t& r1, uint32_t& r2,
                                        uint32_t& r3, uint32_t addr) {
    asm volatile("ldmatrix.sync.aligned.m8n8.x4.shared.b16 {%0,%1,%2,%3}, [%4];"
                 : "=r"(r0), "=r"(r1), "=r"(r2), "=r"(r3) : "r"(addr));
}
__device__ __forceinline__ void mma_f16(float c[4], uint32_t a0, uint32_t a1,
                                        uint32_t a2, uint32_t a3,
                                        uint32_t b0, uint32_t b1) {
    asm volatile(
        "mma.sync.aligned.m16n8k16.row.col.f32.f16.f16.f32 "
        "{%0,%1,%2,%3}, {%4,%5,%6,%7}, {%8,%9}, {%0,%1,%2,%3};"
        : "+f"(c[0]), "+f"(c[1]), "+f"(c[2]), "+f"(c[3])
        : "r"(a0), "r"(a1), "r"(a2), "r"(a3), "r"(b0), "r"(b1));
}
__device__ __forceinline__ void sm_upd(float& m, float& s, float l) {
    if (l <= m) s += __expf(l - m);
    else { s = s * __expf(m - l) + 1.f; m = l; }
}
__device__ __forceinline__ void sm_comb(float& m, float& s, float om, float os) {
    float M = fmaxf(m, om);
    s = s * __expf(m - M) + os * __expf(om - M);
    m = M;
}

// ---------------- k_xd: coalesced downsample + per-pixel S2 ------------------
__global__ __launch_bounds__(256) void k_xd(const float* __restrict__ x) {
    int qy = blockIdx.x, b = blockIdx.y;
    __shared__ __half tile[64 * 130];   // [qx][c], row stride 130 halves (odd words)
    __shared__ float s2p[4][64];
    int tid = threadIdx.x;
    int qx = tid & 63;
    int cg = tid >> 6;                   // 0..3
    const float* xrow = x + (size_t)b * C_ * H_ * W_ + (size_t)(2 * qy) * W_;

    float s2 = 0.f;
#pragma unroll 8
    for (int it = 0; it < 32; it++) {
        int c = it * 4 + cg;
        float v = __ldg(&xrow[(size_t)c * (H_ * W_) + 2 * qx]);
        s2 += v * v;
        tile[qx * 130 + c] = __float2half_rn(v);
    }
    s2p[cg][qx] = s2;
    __syncthreads();
    if (tid < 64)
        g_S2[b * L_ + qy * 64 + tid] =
            s2p[0][tid] + s2p[1][tid] + s2p[2][tid] + s2p[3][tid];

    // write xd rows coalesced (uint32 granularity; 64 rows x 32 words)
    const uint32_t* t32 = (const uint32_t*)tile;
    uint32_t* dst = (uint32_t*)(g_xd + ((size_t)(b * L_ + qy * 64)) * 128);
#pragma unroll
    for (int i = tid; i < 2048; i += 256) {
        int row = i >> 5, w = i & 31;
        dst[row * 64 + w] = t32[row * 65 + w];
    }
}

// ---------------- k_rs: 3x3 stencil on S2 + mask -> rscale/mfilt -------------
__global__ __launch_bounds__(256) void k_rs(const float* __restrict__ mask) {
    int i = blockIdx.x * 256 + threadIdx.x;
    int b = i >> 12, q = i & (L_ - 1);
    int qy = q >> 6, qx = q & 63;
    const float* mb = mask + (size_t)b * (H_ * W_);
    float ss = 0.f, msum = 0.f;
#pragma unroll
    for (int dy = 0; dy < 3; dy++) {
        int sy = qy - 1 + dy;
        if ((unsigned)sy >= HR) continue;
#pragma unroll
        for (int dx = 0; dx < 3; dx++) {
            int sx = qx - 1 + dx;
            if ((unsigned)sx >= HR) continue;
            ss   += __ldg(&g_S2[b * L_ + (sy << 6) + sx]);
            msum += __ldg(&mb[(2 * sy) * W_ + 2 * sx]);
        }
    }
    float denom = sqrtf(ss + F_FULL * EPS_);
    float mf = (msum == 0.f) ? 1.f : 0.f;
    g_mfilt[b * L_ + q]  = mf;
    g_rscale[b * L_ + q] = SCALE_ * mf / denom;
}

// ---------------- k_R: R[p][q] = xd[p] . xd[q]  (K=128, half out) ------------
#define BM 128
#define BN 128
#define BKH 32
#define LDH 40
#define STAGES 3
#define STG_A (BM * LDH * 2)
#define SMEM_R (2 * STAGES * STG_A)   // 61440

__global__ __launch_bounds__(256) void k_R() {
    int b = blockIdx.z;
    int m0 = blockIdx.y * BM;
    int n0 = blockIdx.x * BN;
    const __half* A = g_xd + (size_t)b * L_ * 128;
    const int lda = 128;
    const int NI = 4;

    extern __shared__ char smem[];
    uint32_t sA = smem_u32(smem);
    uint32_t sB = sA + STAGES * STG_A;

    int tid  = threadIdx.x;
    int wid  = tid >> 5, lane = tid & 31;
    int wm   = wid >> 2, wn = wid & 3;
    int g    = lane >> 2, tig = lane & 3;

    int arow  = lane & 15;
    int acol8 = (lane >> 4) * 8;
    int bmi   = lane >> 3;
    int brow  = (bmi >> 1) * 8 + (lane & 7);
    int bk8   = (bmi & 1) * 8;

    int rowL = tid >> 2, seg = tid & 3;

    float acc[4][4][4];
#pragma unroll
    for (int mt = 0; mt < 4; mt++)
#pragma unroll
        for (int nt = 0; nt < 4; nt++)
#pragma unroll
            for (int k = 0; k < 4; k++) acc[mt][nt][k] = 0.f;

#define ISSUE(it2) do {                                                          \
    int st_ = (it2) % STAGES;                                                    \
    int k0_ = (it2) * BKH;                                                       \
    _Pragma("unroll")                                                            \
    for (int h_ = 0; h_ < 2; h_++) {                                             \
        int row_ = rowL + h_ * 64;                                               \
        cp_async16(sA + st_ * STG_A + (row_ * LDH + seg * 8) * 2,                \
                   &A[(size_t)(m0 + row_) * lda + k0_ + seg * 8]);               \
        cp_async16(sB + st_ * STG_A + (row_ * LDH + seg * 8) * 2,                \
                   &A[(size_t)(n0 + row_) * lda + k0_ + seg * 8]);               \
    }                                                                            \
} while (0)

    ISSUE(0); CP_COMMIT();
    ISSUE(1); CP_COMMIT();

    for (int it = 0; it < NI; it++) {
        CP_WAIT(1);
        __syncthreads();
        if (it + 2 < NI) ISSUE(it + 2);
        CP_COMMIT();

        uint32_t sAb = sA + (it % STAGES) * STG_A;
        uint32_t sBb = sB + (it % STAGES) * STG_A;
#pragma unroll
        for (int ks = 0; ks < 2; ks++) {
            int ko = ks * 16;
            uint32_t af[4][4];
#pragma unroll
            for (int mt = 0; mt < 4; mt++)
                ldsm_x4(af[mt][0], af[mt][1], af[mt][2], af[mt][3],
                        sAb + ((wm * 64 + mt * 16 + arow) * LDH + ko + acol8) * 2);
            uint32_t bf[2][4];
#pragma unroll
            for (int nt2 = 0; nt2 < 2; nt2++)
                ldsm_x4(bf[nt2][0], bf[nt2][1], bf[nt2][2], bf[nt2][3],
                        sBb + ((wn * 32 + nt2 * 16 + brow) * LDH + ko + bk8) * 2);
#pragma unroll
            for (int mt = 0; mt < 4; mt++)
#pragma unroll
                for (int nt = 0; nt < 4; nt++) {
                    int nt2 = nt >> 1, sel = (nt & 1) * 2;
                    mma_f16(acc[mt][nt], af[mt][0], af[mt][1], af[mt][2], af[mt][3],
                            bf[nt2][sel], bf[nt2][sel + 1]);
                }
        }
    }
#undef ISSUE

    __half* Rr = g_R + (size_t)b * L_ * L_;
#pragma unroll
    for (int mt = 0; mt < 4; mt++) {
        int row = m0 + wm * 64 + mt * 16 + g;
#pragma unroll
        for (int nt = 0; nt < 4; nt++) {
            int col = n0 + wn * 32 + nt * 8 + tig * 2;
            *(__half2*)&Rr[(size_t)row * L_ + col] =
                __floats2half2_rn(acc[mt][nt][0], acc[mt][nt][1]);
            *(__half2*)&Rr[(size_t)(row + 8) * L_ + col] =
                __floats2half2_rn(acc[mt][nt][2], acc[mt][nt][3]);
        }
    }
}

// ---------------- k_att: 9-point diagonal stencil of R + rs + stats ----------
#define AT_R 16
#define AT_C 512
#define AT_SROWS 54
#define AT_SCOLS 656
#define AT_SC32 (AT_SCOLS / 2)
#define AT_SMEM (AT_SROWS * AT_SCOLS * 2 + AT_C * 4)   // 72896

__global__ __launch_bounds__(256) void k_att() {
    int b  = blockIdx.z;
    int c0 = blockIdx.x * AT_C;
    int rb0 = blockIdx.y * AT_R;
    extern __shared__ char smc[];
    __half* sR = (__half*)smc;
    const uint32_t* sR32 = (const uint32_t*)smc;
    float* s_rs = (float*)(smc + AT_SROWS * AT_SCOLS * 2);
    const __half* Rg = g_R + (size_t)b * L_ * L_;
    int tid = threadIdx.x;

    for (int i = tid; i < AT_C; i += 256) s_rs[i] = g_rscale[b * L_ + c0 + i];

    for (int i = tid; i < AT_SROWS * (AT_SCOLS / 8); i += 256) {
        int srow = i / (AT_SCOLS / 8);
        int v8   = i % (AT_SCOLS / 8);
        int band = srow / 18, within = srow % 18;
        int rr = rb0 + 64 * (band - 1) - 1 + within;
        int gc0 = c0 - 72 + v8 * 8;
        if ((unsigned)rr < (unsigned)L_ && gc0 >= 0 && gc0 + 8 <= L_) {
            *(uint4*)&sR[srow * AT_SCOLS + v8 * 8] = *(const uint4*)&Rg[(size_t)rr * L_ + gc0];
        } else {
            for (int k2 = 0; k2 < 8; k2++) {
                int gc = gc0 + k2;
                __half hv = ((unsigned)rr < (unsigned)L_ && (unsigned)gc < (unsigned)L_)
                                ? Rg[(size_t)rr * L_ + gc] : __float2half(0.f);
                sR[srow * AT_SCOLS + v8 * 8 + k2] = hv;
            }
        }
    }
    __syncthreads();

    int w = tid >> 5, lane = tid & 31;
    float fl0  = (lane > 0)  ? 1.f : 0.f;
    float fl31 = (lane < 31) ? 1.f : 0.f;
    __half* att = g_att + (size_t)b * L_ * L_;

    for (int rr2 = 0; rr2 < 2; rr2++) {
        int k = w * 2 + rr2;
        int r = rb0 + k;
        int ry = r >> 6, rx = r & 63;
        float frxm1 = (rx > 0)  ? 1.f : 0.f;
        float frx1  = (rx < 63) ? 1.f : 0.f;
        bool vrym1 = (ry > 0), vry1 = (ry < 63);
        float m = -1e30f, s = 0.f;
        for (int cc = 0; cc < 8; cc++) {
            int cy = (c0 >> 6) + cc;
            int lc = cc * 64 + lane * 2;
            int c  = c0 + lc;
            float g0 = 0.f, g1 = 0.f;
#pragma unroll
            for (int dy = -1; dy <= 1; dy++) {
                bool vy = (dy < 0) ? (vrym1 && cy > 0)
                                   : ((dy > 0) ? (vry1 && cy < 63) : true);
                if (!vy) continue;
                int sb = (dy + 1) * 18 + k + 1;
                int cb = lc + 64 * dy + 72;
                const uint32_t* rm1 = sR32 + (sb - 1) * AT_SC32;
                const uint32_t* rw0 = sR32 + sb * AT_SC32;
                const uint32_t* rp1 = sR32 + (sb + 1) * AT_SC32;
                uint32_t uA1 = rm1[(cb - 2) >> 1];
                uint32_t uA2 = rm1[cb >> 1];
                uint32_t uB  = rw0[cb >> 1];
                uint32_t uC1 = rp1[cb >> 1];
                uint32_t uC2 = rp1[(cb + 2) >> 1];
                __half2 hA1 = *(__half2*)&uA1, hA2 = *(__half2*)&uA2;
                __half2 hB  = *(__half2*)&uB;
                __half2 hC1 = *(__half2*)&uC1, hC2 = *(__half2*)&uC2;
                g0 += frxm1 * fl0 * __high2float(hA1) + __low2float(hB)
                      + frx1 * __high2float(hC1);
                g1 += frxm1 * __low2float(hA2) + __high2float(hB)
                      + frx1 * fl31 * __low2float(hC2);
            }
            __half2 h = __floats2half2_rn(g0 * s_rs[lc], g1 * s_rs[lc + 1]);
            *(__half2*)&att[(size_t)r * L_ + c] = h;
            sm_upd(m, s, __low2float(h));
            sm_upd(m, s, __high2float(h));
            if (cc & 1) {
                float mm = m, ss = s;
#pragma unroll
                for (int off = 16; off > 0; off >>= 1) {
                    float om = __shfl_xor_sync(0xffffffffu, mm, off);
                    float os = __shfl_xor_sync(0xffffffffu, ss, off);
                    sm_comb(mm, ss, om, os);
                }
                if (lane == 0) {
                    int pc = (c0 >> 7) + (cc >> 1);
                    size_t o = ((size_t)b * NPC + pc) * L_ + r;
                    g_statm[o] = mm;
                    g_stats[o] = ss;
                }
                m = -1e30f; s = 0.f;
            }
        }
    }
}

// ---------------- stage C: combine stats + chunk-gated list build ------------
__global__ __launch_bounds__(256) void k_smC() {
    int b = blockIdx.y;
    int wid = threadIdx.x >> 5, lane = threadIdx.x & 31;
    int r = blockIdx.x * 8 + wid;
    const __half* Ar = g_att + (size_t)b * L_ * L_ + (size_t)r * L_;
    const float* mfp = g_mfilt + b * L_;

    float sm = g_statm[((size_t)b * NPC + lane) * L_ + r];
    float ms = sm, ss = g_stats[((size_t)b * NPC + lane) * L_ + r];
#pragma unroll
    for (int off = 16; off > 0; off >>= 1) {
        float om = __shfl_xor_sync(0xffffffffu, ms, off);
        float os = __shfl_xor_sync(0xffffffffu, ss, off);
        sm_comb(ms, ss, om, os);
    }
    float M = ms, Iv = 1.f / ss;
    if (lane == 0) { g_cm[b * L_ + r] = M; g_ci[b * L_ + r] = Iv; }

    bool qual = (__expf(sm - M) * Iv >= THRESH);
    unsigned qmask = __ballot_sync(0xffffffffu, qual);

    int cnt = 0;
    size_t base = (size_t)(b * L_ + r) * CAP;
    while (qmask) {
        int pc = __ffs(qmask) - 1;
        qmask &= qmask - 1;
        int c = pc * 128 + lane * 4;
        uint2 v = *(const uint2*)&Ar[c];
        __half2 h0 = *(__half2*)&v.x, h1 = *(__half2*)&v.y;
        float4 mfv = *(const float4*)&mfp[c];
        float wv[4];
        wv[0] = __expf(__low2float(h0) - M) * Iv * mfv.x;
        wv[1] = __expf(__high2float(h0) - M) * Iv * mfv.y;
        wv[2] = __expf(__low2float(h1) - M) * Iv * mfv.z;
        wv[3] = __expf(__high2float(h1) - M) * Iv * mfv.w;
        int lc = (wv[0] >= THRESH) + (wv[1] >= THRESH) + (wv[2] >= THRESH) + (wv[3] >= THRESH);
        int incl = lc;
#pragma unroll
        for (int d = 1; d < 32; d <<= 1) {
            int o2 = __shfl_up_sync(0xffffffffu, incl, d);
            if (lane >= d) incl += o2;
        }
        int idx = cnt + incl - lc;
#pragma unroll
        for (int k = 0; k < 4; k++)
            if (wv[k] >= THRESH) {
                if (idx < CAP) { g_listp[base + idx] = c + k; g_listw[base + idx] = wv[k]; }
                idx++;
            }
        cnt += __shfl_sync(0xffffffffu, incl, 31);
    }
    if (lane == 0) g_cnt[b * L_ + r] = cnt;
}

// ---------------- fused sparse apply + overlap-add (channel-amortized) -------
__global__ __launch_bounds__(128) void k_out(const float* __restrict__ x,
                                             float* __restrict__ out) {
    int y = blockIdx.x, cg = blockIdx.y, b = blockIdx.z;
    int xx = threadIdx.x;
    int c0 = cg * 16;
    const float* xb = x + (size_t)(b * C_ + c0) * (H_ * W_);
    float acc[16];
#pragma unroll
    for (int k = 0; k < 16; k++) acc[k] = 0.f;

    int ki0 = (y + 1) & 1, kj0 = (xx + 1) & 1;
#pragma unroll
    for (int a = 0; a < 2; a++) {
        int ki = ki0 + a * 2;
        int sy2 = y + 1 - ki;
        if (sy2 < 0) continue;
        int sy = sy2 >> 1;
        if (sy >= HR) continue;
#pragma unroll
        for (int bb = 0; bb < 2; bb++) {
            int kj = kj0 + bb * 2;
            int sx2 = xx + 1 - kj;
            if (sx2 < 0) continue;
            int sx = sx2 >> 1;
            if (sx >= HR) continue;
            int q = (sy << 6) + sx;
            int cnt = g_cnt[b * L_ + q];
            if (cnt <= CAP) {
                size_t base = (size_t)(b * L_ + q) * CAP;
                for (int t = 0; t < cnt; t++) {
                    int p = g_listp[base + t];
                    float wv = g_listw[base + t];
                    int py = p >> 6, px = p & 63;
                    int ry = 2 * py - 1 + ki, rx = 2 * px - 1 + kj;
                    if ((unsigned)ry < H_ && (unsigned)rx < W_) {
                        int off = ry * W_ + rx;
#pragma unroll
                        for (int cn = 0; cn < 16; cn++)
                            acc[cn] += wv * __ldg(&xb[(size_t)cn * (H_ * W_) + off]);
                    }
                }
            } else {
                const __half* Ar = g_att + (size_t)b * L_ * L_ + (size_t)q * L_;
                float M = g_cm[b * L_ + q], Iv = g_ci[b * L_ + q];
                const float* mfp = g_mfilt + b * L_;
                for (int p = 0; p < L_; p++) {
                    float wv = __expf(__half2float(Ar[p]) - M) * Iv * mfp[p];
                    if (wv < THRESH) continue;
                    int py = p >> 6, px = p & 63;
                    int ry = 2 * py - 1 + ki, rx = 2 * px - 1 + kj;
                    if ((unsigned)ry < H_ && (unsigned)rx < W_) {
                        int off = ry * W_ + rx;
                        for (int cn = 0; cn < 16; cn++)
                            acc[cn] += wv * __ldg(&xb[(size_t)cn * (H_ * W_) + off]);
                    }
                }
            }
        }
    }
#pragma unroll
    for (int cn = 0; cn < 16; cn++)
        out[(((size_t)(b * C_ + c0 + cn)) * H_ + y) * W_ + xx] = 0.25f * acc[cn];
}

// ---------------- launch ------------------------------------------------------
extern "C" void kernel_launch(void* const* d_in, const int* in_sizes, int n_in,
                              void* d_out, int out_size) {
    const float* x    = (const float*)d_in[0];
    const float* mask = (const float*)d_in[1];
    float* out = (float*)d_out;

    cudaFuncSetAttribute(k_R, cudaFuncAttributeMaxDynamicSharedMemorySize, SMEM_R);
    cudaFuncSetAttribute(k_att, cudaFuncAttributeMaxDynamicSharedMemorySize, AT_SMEM);

    k_xd<<<dim3(HR, B_), 256>>>(x);
    k_rs<<<(B_ * L_) / 256, 256>>>(mask);
    k_R<<<dim3(L_ / BN, L_ / BM, B_), 256, SMEM_R>>>();
    k_att<<<dim3(L_ / AT_C, L_ / AT_R, B_), 256, AT_SMEM>>>();
    k_smC<<<dim3(L_ / 8, B_), 256>>>();
    k_out<<<dim3(H_, 8, B_), 128>>>(x, out);
}

// round 12
// speedup vs baseline: 32.5405x; 1.3977x over previous
#include <cuda_runtime.h>
#include <cuda_fp16.h>
#include <cstdint>
#include <math.h>

#define B_   2
#define C_   128
#define H_   128
#define W_   128
#define HR   64
#define L_   4096
#define EPS_ 0.0001f
#define SCALE_ 10.0f
#define NPC  32
#define CAP  32
#define THRESH 5.9604645e-8f
#define F_FULL 1152.0f

// ---------------- scratch ----------------------------------------------------
__device__ __half g_xd [(size_t)B_ * L_ * 128];  // [b][q][c]
__device__ float  g_S2 [B_ * L_];
__device__ __half g_R  [(size_t)B_ * L_ * L_];   // [b][p][q] correlation
__device__ __half g_att[(size_t)B_ * L_ * L_];   // [b][r][c] logits
__device__ float  g_rscale[B_ * L_];
__device__ float  g_mfilt[B_ * L_];
__device__ float  g_statm[(size_t)B_ * NPC * L_]; // per-chunk MAX of logits
__device__ float  g_cm[B_ * L_];
__device__ float  g_ci[B_ * L_];
__device__ int    g_cnt[B_ * L_];
__device__ int    g_listp[(size_t)B_ * L_ * CAP];
__device__ float  g_listw[(size_t)B_ * L_ * CAP];

// ---------------- helpers ----------------------------------------------------
__device__ __forceinline__ uint32_t smem_u32(const void* p) {
    uint32_t a;
    asm("{ .reg .u64 t; cvta.to.shared.u64 t, %1; cvt.u32.u64 %0, t; }" : "=r"(a) : "l"(p));
    return a;
}
__device__ __forceinline__ void cp_async16(uint32_t saddr, const void* g) {
    asm volatile("cp.async.cg.shared.global [%0], [%1], 16;" :: "r"(saddr), "l"(g));
}
#define CP_COMMIT() asm volatile("cp.async.commit_group;" ::: "memory")
#define CP_WAIT(n)  asm volatile("cp.async.wait_group %0;" :: "n"(n) : "memory")

__device__ __forceinline__ void ldsm_x4(uint32_t& r0, uint32_t& r1, uint32_t& r2,
                                        uint32_t& r3, uint32_t addr) {
    asm volatile("ldmatrix.sync.aligned.m8n8.x4.shared.b16 {%0,%1,%2,%3}, [%4];"
                 : "=r"(r0), "=r"(r1), "=r"(r2), "=r"(r3) : "r"(addr));
}
__device__ __forceinline__ void mma_f16(float c[4], uint32_t a0, uint32_t a1,
                                        uint32_t a2, uint32_t a3,
                                        uint32_t b0, uint32_t b1) {
    asm volatile(
        "mma.sync.aligned.m16n8k16.row.col.f32.f16.f16.f32 "
        "{%0,%1,%2,%3}, {%4,%5,%6,%7}, {%8,%9}, {%0,%1,%2,%3};"
        : "+f"(c[0]), "+f"(c[1]), "+f"(c[2]), "+f"(c[3])
        : "r"(a0), "r"(a1), "r"(a2), "r"(a3), "r"(b0), "r"(b1));
}

// ---------------- k_xd: coalesced downsample + per-pixel S2 ------------------
__global__ __launch_bounds__(256) void k_xd(const float* __restrict__ x) {
    int qy = blockIdx.x, b = blockIdx.y;
    __shared__ __half tile[64 * 130];
    __shared__ float s2p[4][64];
    int tid = threadIdx.x;
    int qx = tid & 63;
    int cg = tid >> 6;
    const float* xrow = x + (size_t)b * C_ * H_ * W_ + (size_t)(2 * qy) * W_;

    float s2 = 0.f;
#pragma unroll 8
    for (int it = 0; it < 32; it++) {
        int c = it * 4 + cg;
        float v = __ldg(&xrow[(size_t)c * (H_ * W_) + 2 * qx]);
        s2 += v * v;
        tile[qx * 130 + c] = __float2half_rn(v);
    }
    s2p[cg][qx] = s2;
    __syncthreads();
    if (tid < 64)
        g_S2[b * L_ + qy * 64 + tid] =
            s2p[0][tid] + s2p[1][tid] + s2p[2][tid] + s2p[3][tid];

    const uint32_t* t32 = (const uint32_t*)tile;
    uint32_t* dst = (uint32_t*)(g_xd + ((size_t)(b * L_ + qy * 64)) * 128);
#pragma unroll
    for (int i = tid; i < 2048; i += 256) {
        int row = i >> 5, w = i & 31;
        dst[row * 64 + w] = t32[row * 65 + w];
    }
}

// ---------------- k_rs: 3x3 stencil on S2 + mask -> rscale/mfilt -------------
__global__ __launch_bounds__(256) void k_rs(const float* __restrict__ mask) {
    int i = blockIdx.x * 256 + threadIdx.x;
    int b = i >> 12, q = i & (L_ - 1);
    int qy = q >> 6, qx = q & 63;
    const float* mb = mask + (size_t)b * (H_ * W_);
    float ss = 0.f, msum = 0.f;
#pragma unroll
    for (int dy = 0; dy < 3; dy++) {
        int sy = qy - 1 + dy;
        if ((unsigned)sy >= HR) continue;
#pragma unroll
        for (int dx = 0; dx < 3; dx++) {
            int sx = qx - 1 + dx;
            if ((unsigned)sx >= HR) continue;
            ss   += __ldg(&g_S2[b * L_ + (sy << 6) + sx]);
            msum += __ldg(&mb[(2 * sy) * W_ + 2 * sx]);
        }
    }
    float denom = sqrtf(ss + F_FULL * EPS_);
    float mf = (msum == 0.f) ? 1.f : 0.f;
    g_mfilt[b * L_ + q]  = mf;
    g_rscale[b * L_ + q] = SCALE_ * mf / denom;
}

// ---------------- k_R: R[p][q] = xd[p] . xd[q]  (K=128, half out) ------------
#define BM 128
#define BN 128
#define BKH 32
#define LDH 40
#define STAGES 3
#define STG_A (BM * LDH * 2)
#define SMEM_R (2 * STAGES * STG_A)

__global__ __launch_bounds__(256) void k_R() {
    int b = blockIdx.z;
    int m0 = blockIdx.y * BM;
    int n0 = blockIdx.x * BN;
    const __half* A = g_xd + (size_t)b * L_ * 128;
    const int lda = 128;
    const int NI = 4;

    extern __shared__ char smem[];
    uint32_t sA = smem_u32(smem);
    uint32_t sB = sA + STAGES * STG_A;

    int tid  = threadIdx.x;
    int wid  = tid >> 5, lane = tid & 31;
    int wm   = wid >> 2, wn = wid & 3;
    int g    = lane >> 2, tig = lane & 3;

    int arow  = lane & 15;
    int acol8 = (lane >> 4) * 8;
    int bmi   = lane >> 3;
    int brow  = (bmi >> 1) * 8 + (lane & 7);
    int bk8   = (bmi & 1) * 8;

    int rowL = tid >> 2, seg = tid & 3;

    float acc[4][4][4];
#pragma unroll
    for (int mt = 0; mt < 4; mt++)
#pragma unroll
        for (int nt = 0; nt < 4; nt++)
#pragma unroll
            for (int k = 0; k < 4; k++) acc[mt][nt][k] = 0.f;

#define ISSUE(it2) do {                                                          \
    int st_ = (it2) % STAGES;                                                    \
    int k0_ = (it2) * BKH;                                                       \
    _Pragma("unroll")                                                            \
    for (int h_ = 0; h_ < 2; h_++) {                                             \
        int row_ = rowL + h_ * 64;                                               \
        cp_async16(sA + st_ * STG_A + (row_ * LDH + seg * 8) * 2,                \
                   &A[(size_t)(m0 + row_) * lda + k0_ + seg * 8]);               \
        cp_async16(sB + st_ * STG_A + (row_ * LDH + seg * 8) * 2,                \
                   &A[(size_t)(n0 + row_) * lda + k0_ + seg * 8]);               \
    }                                                                            \
} while (0)

    ISSUE(0); CP_COMMIT();
    ISSUE(1); CP_COMMIT();

    for (int it = 0; it < NI; it++) {
        CP_WAIT(1);
        __syncthreads();
        if (it + 2 < NI) ISSUE(it + 2);
        CP_COMMIT();

        uint32_t sAb = sA + (it % STAGES) * STG_A;
        uint32_t sBb = sB + (it % STAGES) * STG_A;
#pragma unroll
        for (int ks = 0; ks < 2; ks++) {
            int ko = ks * 16;
            uint32_t af[4][4];
#pragma unroll
            for (int mt = 0; mt < 4; mt++)
                ldsm_x4(af[mt][0], af[mt][1], af[mt][2], af[mt][3],
                        sAb + ((wm * 64 + mt * 16 + arow) * LDH + ko + acol8) * 2);
            uint32_t bf[2][4];
#pragma unroll
            for (int nt2 = 0; nt2 < 2; nt2++)
                ldsm_x4(bf[nt2][0], bf[nt2][1], bf[nt2][2], bf[nt2][3],
                        sBb + ((wn * 32 + nt2 * 16 + brow) * LDH + ko + bk8) * 2);
#pragma unroll
            for (int mt = 0; mt < 4; mt++)
#pragma unroll
                for (int nt = 0; nt < 4; nt++) {
                    int nt2 = nt >> 1, sel = (nt & 1) * 2;
                    mma_f16(acc[mt][nt], af[mt][0], af[mt][1], af[mt][2], af[mt][3],
                            bf[nt2][sel], bf[nt2][sel + 1]);
                }
        }
    }
#undef ISSUE

    __half* Rr = g_R + (size_t)b * L_ * L_;
#pragma unroll
    for (int mt = 0; mt < 4; mt++) {
        int row = m0 + wm * 64 + mt * 16 + g;
#pragma unroll
        for (int nt = 0; nt < 4; nt++) {
            int col = n0 + wn * 32 + nt * 8 + tig * 2;
            *(__half2*)&Rr[(size_t)row * L_ + col] =
                __floats2half2_rn(acc[mt][nt][0], acc[mt][nt][1]);
            *(__half2*)&Rr[(size_t)(row + 8) * L_ + col] =
                __floats2half2_rn(acc[mt][nt][2], acc[mt][nt][3]);
        }
    }
}

// ---------------- k_att: vectorized 9-point diag stencil + rs + chunk max ----
#define AT_R 16
#define AT_C 512
#define AT_SROWS 54
#define AT_SCOLS 656
#define AT_SC32 (AT_SCOLS / 2)
#define AT_SMEM (AT_SROWS * AT_SCOLS * 2 + AT_C * 4)

__global__ __launch_bounds__(256) void k_att() {
    int b  = blockIdx.z;
    int c0 = blockIdx.x * AT_C;
    int rb0 = blockIdx.y * AT_R;
    extern __shared__ char smc[];
    __half* sR = (__half*)smc;
    const uint32_t* sR32 = (const uint32_t*)smc;
    float* s_rs = (float*)(smc + AT_SROWS * AT_SCOLS * 2);
    const __half* Rg = g_R + (size_t)b * L_ * L_;
    int tid = threadIdx.x;

    for (int i = tid; i < AT_C; i += 256) s_rs[i] = g_rscale[b * L_ + c0 + i];

    for (int i = tid; i < AT_SROWS * (AT_SCOLS / 8); i += 256) {
        int srow = i / (AT_SCOLS / 8);
        int v8   = i % (AT_SCOLS / 8);
        int band = srow / 18, within = srow % 18;
        int rr = rb0 + 64 * (band - 1) - 1 + within;
        int gc0 = c0 - 72 + v8 * 8;
        if ((unsigned)rr < (unsigned)L_ && gc0 >= 0 && gc0 + 8 <= L_) {
            *(uint4*)&sR[srow * AT_SCOLS + v8 * 8] = *(const uint4*)&Rg[(size_t)rr * L_ + gc0];
        } else {
            for (int k2 = 0; k2 < 8; k2++) {
                int gc = gc0 + k2;
                __half hv = ((unsigned)rr < (unsigned)L_ && (unsigned)gc < (unsigned)L_)
                                ? Rg[(size_t)rr * L_ + gc] : __float2half(0.f);
                sR[srow * AT_SCOLS + v8 * 8 + k2] = hv;
            }
        }
    }
    __syncthreads();

    int w = tid >> 5, lane = tid & 31;
    int lane8 = lane & 7;
    uint32_t edgeA = (lane8 == 0) ? 0xFFFF0000u : 0xFFFFFFFFu;
    uint32_t edgeC = (lane8 == 7) ? 0x0000FFFFu : 0xFFFFFFFFu;
    __half* att = g_att + (size_t)b * L_ * L_;

    for (int rr2 = 0; rr2 < 2; rr2++) {
        int k = w * 2 + rr2;
        int r = rb0 + k;
        int ry = r >> 6, rx = r & 63;
        uint32_t aAll = (rx > 0)  ? 0xFFFFFFFFu : 0u;
        uint32_t cAll = (rx < 63) ? 0xFFFFFFFFu : 0u;
        uint32_t mA0 = edgeA & aAll, mC3 = edgeC & cAll;

#pragma unroll
        for (int pass = 0; pass < 2; pass++) {
            int lc = pass * 256 + lane * 8;
            int cy = (c0 + lc) >> 6;
            uint32_t acc[4] = {0u, 0u, 0u, 0u};
#pragma unroll
            for (int dy = -1; dy <= 1; dy++) {
                bool vy = ((unsigned)(ry + dy) < 64u) && ((unsigned)(cy + dy) < 64u);
                int sb = (dy + 1) * 18 + k + 1;
                int wb = (lc + 64 * dy + 72) >> 1;
                const uint32_t* rm1 = sR32 + (sb - 1) * AT_SC32;
                const uint32_t* rw0 = sR32 + sb * AT_SC32;
                const uint32_t* rp1 = sR32 + (sb + 1) * AT_SC32;
                uint32_t aw = ((const uint4*)(rm1 + wb - 4))->w;   // halves cb-2,cb-1
                uint4 av = *(const uint4*)(rm1 + wb);
                uint4 bv = *(const uint4*)(rw0 + wb);
                uint4 cv = *(const uint4*)(rp1 + wb);
                uint32_t cw = ((const uint4*)(rp1 + wb + 4))->x;   // halves cb+8,cb+9

                uint32_t A2[4], C2[4];
                A2[0] = __byte_perm(aw,   av.x, 0x5432) & mA0;
                A2[1] = __byte_perm(av.x, av.y, 0x5432) & aAll;
                A2[2] = __byte_perm(av.y, av.z, 0x5432) & aAll;
                A2[3] = __byte_perm(av.z, av.w, 0x5432) & aAll;
                C2[0] = __byte_perm(cv.x, cv.y, 0x5432) & cAll;
                C2[1] = __byte_perm(cv.y, cv.z, 0x5432) & cAll;
                C2[2] = __byte_perm(cv.z, cv.w, 0x5432) & cAll;
                C2[3] = __byte_perm(cv.w, cw,   0x5432) & mC3;
                const uint32_t* bw = (const uint32_t*)&bv;
                if (vy) {
#pragma unroll
                    for (int kk = 0; kk < 4; kk++) {
                        __half2 t = __hadd2(*(__half2*)&A2[kk], *(__half2*)&bw[kk]);
                        t = __hadd2(t, *(__half2*)&C2[kk]);
                        *(__half2*)&acc[kk] = __hadd2(*(__half2*)&acc[kk], t);
                    }
                }
            }
            // epilogue: scale by rs, store, per-chunk max
            float4 rs0 = *(float4*)&s_rs[lc];
            float4 rs1 = *(float4*)&s_rs[lc + 4];
            float rsv[8] = {rs0.x, rs0.y, rs0.z, rs0.w, rs1.x, rs1.y, rs1.z, rs1.w};
            uint32_t outw[4];
            __half2 mx2 = __float2half2_rn(-60000.f);
#pragma unroll
            for (int kk = 0; kk < 4; kk++) {
                float2 f = __half22float2(*(__half2*)&acc[kk]);
                __half2 h = __floats2half2_rn(f.x * rsv[2 * kk], f.y * rsv[2 * kk + 1]);
                outw[kk] = *(uint32_t*)&h;
                mx2 = __hmax2(mx2, h);
            }
            *(uint4*)&att[(size_t)r * L_ + c0 + lc] = *(uint4*)outw;
            float m = fmaxf(__low2float(mx2), __high2float(mx2));
#pragma unroll
            for (int off = 8; off > 0; off >>= 1)
                m = fmaxf(m, __shfl_xor_sync(0xffffffffu, m, off));
            if ((lane & 15) == 0) {
                int pc = (c0 + lc) >> 7;
                g_statm[((size_t)b * NPC + pc) * L_ + r] = m;
            }
        }
    }
}

// ---------------- k_smC: M from chunk maxima, gated S, gated list ------------
__global__ __launch_bounds__(256) void k_smC() {
    int b = blockIdx.y;
    int wid = threadIdx.x >> 5, lane = threadIdx.x & 31;
    int r = blockIdx.x * 8 + wid;
    const __half* Ar = g_att + (size_t)b * L_ * L_ + (size_t)r * L_;
    const float* mfp = g_mfilt + b * L_;

    float cm = g_statm[((size_t)b * NPC + lane) * L_ + r];
    float M = cm;
#pragma unroll
    for (int off = 16; off > 0; off >>= 1)
        M = fmaxf(M, __shfl_xor_sync(0xffffffffu, M, off));

    unsigned qmask = __ballot_sync(0xffffffffu, cm >= M - 20.f);

    // pass 1: S over gated chunks (deterministic: pc ascending, butterfly sum)
    float S = 0.f;
    unsigned qm = qmask;
    while (qm) {
        int pc = __ffs(qm) - 1;
        qm &= qm - 1;
        int c = pc * 128 + lane * 4;
        uint2 v = *(const uint2*)&Ar[c];
        __half2 h0 = *(__half2*)&v.x, h1 = *(__half2*)&v.y;
        float s4 = __expf(__low2float(h0) - M) + __expf(__high2float(h0) - M)
                 + __expf(__low2float(h1) - M) + __expf(__high2float(h1) - M);
#pragma unroll
        for (int off = 16; off > 0; off >>= 1)
            s4 += __shfl_xor_sync(0xffffffffu, s4, off);
        S += s4;
    }
    float Iv = 1.f / S;
    if (lane == 0) { g_cm[b * L_ + r] = M; g_ci[b * L_ + r] = Iv; }

    // pass 2: list build over the same chunk set
    int cnt = 0;
    size_t base = (size_t)(b * L_ + r) * CAP;
    while (qmask) {
        int pc = __ffs(qmask) - 1;
        qmask &= qmask - 1;
        int c = pc * 128 + lane * 4;
        uint2 v = *(const uint2*)&Ar[c];
        __half2 h0 = *(__half2*)&v.x, h1 = *(__half2*)&v.y;
        float4 mfv = *(const float4*)&mfp[c];
        float wv[4];
        wv[0] = __expf(__low2float(h0) - M) * Iv * mfv.x;
        wv[1] = __expf(__high2float(h0) - M) * Iv * mfv.y;
        wv[2] = __expf(__low2float(h1) - M) * Iv * mfv.z;
        wv[3] = __expf(__high2float(h1) - M) * Iv * mfv.w;
        int lcount = (wv[0] >= THRESH) + (wv[1] >= THRESH) + (wv[2] >= THRESH) + (wv[3] >= THRESH);
        int incl = lcount;
#pragma unroll
        for (int d = 1; d < 32; d <<= 1) {
            int o2 = __shfl_up_sync(0xffffffffu, incl, d);
            if (lane >= d) incl += o2;
        }
        int idx = cnt + incl - lcount;
#pragma unroll
        for (int k = 0; k < 4; k++)
            if (wv[k] >= THRESH) {
                if (idx < CAP) { g_listp[base + idx] = c + k; g_listw[base + idx] = wv[k]; }
                idx++;
            }
        cnt += __shfl_sync(0xffffffffu, incl, 31);
    }
    if (lane == 0) g_cnt[b * L_ + r] = cnt;
}

// ---------------- fused sparse apply + overlap-add (channel-amortized) -------
__global__ __launch_bounds__(128) void k_out(const float* __restrict__ x,
                                             float* __restrict__ out) {
    int y = blockIdx.x, cg = blockIdx.y, b = blockIdx.z;
    int xx = threadIdx.x;
    int c0 = cg * 16;
    const float* xb = x + (size_t)(b * C_ + c0) * (H_ * W_);
    float acc[16];
#pragma unroll
    for (int k = 0; k < 16; k++) acc[k] = 0.f;

    int ki0 = (y + 1) & 1, kj0 = (xx + 1) & 1;
#pragma unroll
    for (int a = 0; a < 2; a++) {
        int ki = ki0 + a * 2;
        int sy2 = y + 1 - ki;
        if (sy2 < 0) continue;
        int sy = sy2 >> 1;
        if (sy >= HR) continue;
#pragma unroll
        for (int bb = 0; bb < 2; bb++) {
            int kj = kj0 + bb * 2;
            int sx2 = xx + 1 - kj;
            if (sx2 < 0) continue;
            int sx = sx2 >> 1;
            if (sx >= HR) continue;
            int q = (sy << 6) + sx;
            int cnt = g_cnt[b * L_ + q];
            if (cnt <= CAP) {
                size_t base = (size_t)(b * L_ + q) * CAP;
                for (int t = 0; t < cnt; t++) {
                    int p = g_listp[base + t];
                    float wv = g_listw[base + t];
                    int py = p >> 6, px = p & 63;
                    int ry = 2 * py - 1 + ki, rx = 2 * px - 1 + kj;
                    if ((unsigned)ry < H_ && (unsigned)rx < W_) {
                        int off = ry * W_ + rx;
#pragma unroll
                        for (int cn = 0; cn < 16; cn++)
                            acc[cn] += wv * __ldg(&xb[(size_t)cn * (H_ * W_) + off]);
                    }
                }
            } else {
                const __half* Ar = g_att + (size_t)b * L_ * L_ + (size_t)q * L_;
                float M = g_cm[b * L_ + q], Iv = g_ci[b * L_ + q];
                const float* mfp = g_mfilt + b * L_;
                for (int p = 0; p < L_; p++) {
                    float wv = __expf(__half2float(Ar[p]) - M) * Iv * mfp[p];
                    if (wv < THRESH) continue;
                    int py = p >> 6, px = p & 63;
                    int ry = 2 * py - 1 + ki, rx = 2 * px - 1 + kj;
                    if ((unsigned)ry < H_ && (unsigned)rx < W_) {
                        int off = ry * W_ + rx;
                        for (int cn = 0; cn < 16; cn++)
                            acc[cn] += wv * __ldg(&xb[(size_t)cn * (H_ * W_) + off]);
                    }
                }
            }
        }
    }
#pragma unroll
    for (int cn = 0; cn < 16; cn++)
        out[(((size_t)(b * C_ + c0 + cn)) * H_ + y) * W_ + xx] = 0.25f * acc[cn];
}

// ---------------- launch ------------------------------------------------------
extern "C" void kernel_launch(void* const* d_in, const int* in_sizes, int n_in,
                              void* d_out, int out_size) {
    const float* x    = (const float*)d_in[0];
    const float* mask = (const float*)d_in[1];
    float* out = (float*)d_out;

    cudaFuncSetAttribute(k_R, cudaFuncAttributeMaxDynamicSharedMemorySize, SMEM_R);
    cudaFuncSetAttribute(k_att, cudaFuncAttributeMaxDynamicSharedMemorySize, AT_SMEM);

    k_xd<<<dim3(HR, B_), 256>>>(x);
    k_rs<<<(B_ * L_) / 256, 256>>>(mask);
    k_R<<<dim3(L_ / BN, L_ / BM, B_), 256, SMEM_R>>>();
    k_att<<<dim3(L_ / AT_C, L_ / AT_R, B_), 256, AT_SMEM>>>();
    k_smC<<<dim3(L_ / 8, B_), 256>>>();
    k_out<<<dim3(H_, 8, B_), 128>>>(x, out);
}

// round 13
// speedup vs baseline: 43.4181x; 1.3343x over previous
#include <cuda_runtime.h>
#include <cuda_fp16.h>
#include <cstdint>
#include <math.h>

#define B_   2
#define C_   128
#define H_   128
#define W_   128
#define HR   64
#define L_   4096
#define EPS_ 0.0001f
#define SCALE_ 10.0f
#define NPC  32
#define CAP  32
#define THRESH 5.9604645e-8f
#define F_FULL 1152.0f

// ---------------- scratch ----------------------------------------------------
__device__ __half g_xd [(size_t)B_ * L_ * 128];  // [b][q][c]
__device__ float  g_S2 [B_ * L_];
__device__ __half g_R  [(size_t)B_ * L_ * L_];   // [b][p][q] correlation
__device__ __half g_att[(size_t)B_ * L_ * L_];   // [b][r][c] logits
__device__ float  g_rscale[B_ * L_];
__device__ float  g_mfilt[B_ * L_];
__device__ float  g_statm[(size_t)B_ * NPC * L_]; // per-chunk MAX of logits
__device__ float  g_cm[B_ * L_];
__device__ float  g_ci[B_ * L_];
__device__ int    g_cnt[B_ * L_];
__device__ int    g_listp[(size_t)B_ * L_ * CAP];
__device__ float  g_listw[(size_t)B_ * L_ * CAP];

// ---------------- helpers ----------------------------------------------------
__device__ __forceinline__ uint32_t smem_u32(const void* p) {
    uint32_t a;
    asm("{ .reg .u64 t; cvta.to.shared.u64 t, %1; cvt.u32.u64 %0, t; }" : "=r"(a) : "l"(p));
    return a;
}
__device__ __forceinline__ void cp_async16(uint32_t saddr, const void* g) {
    asm volatile("cp.async.cg.shared.global [%0], [%1], 16;" :: "r"(saddr), "l"(g));
}
__device__ __forceinline__ void cp_async16z(uint32_t saddr, const void* g, int sz) {
    asm volatile("cp.async.cg.shared.global [%0], [%1], 16, %2;"
                 :: "r"(saddr), "l"(g), "r"(sz));
}
#define CP_COMMIT() asm volatile("cp.async.commit_group;" ::: "memory")
#define CP_WAIT(n)  asm volatile("cp.async.wait_group %0;" :: "n"(n) : "memory")

__device__ __forceinline__ void ldsm_x4(uint32_t& r0, uint32_t& r1, uint32_t& r2,
                                        uint32_t& r3, uint32_t addr) {
    asm volatile("ldmatrix.sync.aligned.m8n8.x4.shared.b16 {%0,%1,%2,%3}, [%4];"
                 : "=r"(r0), "=r"(r1), "=r"(r2), "=r"(r3) : "r"(addr));
}
__device__ __forceinline__ void mma_f16(float c[4], uint32_t a0, uint32_t a1,
                                        uint32_t a2, uint32_t a3,
                                        uint32_t b0, uint32_t b1) {
    asm volatile(
        "mma.sync.aligned.m16n8k16.row.col.f32.f16.f16.f32 "
        "{%0,%1,%2,%3}, {%4,%5,%6,%7}, {%8,%9}, {%0,%1,%2,%3};"
        : "+f"(c[0]), "+f"(c[1]), "+f"(c[2]), "+f"(c[3])
        : "r"(a0), "r"(a1), "r"(a2), "r"(a3), "r"(b0), "r"(b1));
}

// ---------------- k_xd: coalesced downsample + per-pixel S2 ------------------
__global__ __launch_bounds__(256) void k_xd(const float* __restrict__ x) {
    int qy = blockIdx.x, b = blockIdx.y;
    __shared__ __half tile[64 * 130];
    __shared__ float s2p[4][64];
    int tid = threadIdx.x;
    int qx = tid & 63;
    int cg = tid >> 6;
    const float* xrow = x + (size_t)b * C_ * H_ * W_ + (size_t)(2 * qy) * W_;

    float s2 = 0.f;
#pragma unroll 8
    for (int it = 0; it < 32; it++) {
        int c = it * 4 + cg;
        float v = __ldg(&xrow[(size_t)c * (H_ * W_) + 2 * qx]);
        s2 += v * v;
        tile[qx * 130 + c] = __float2half_rn(v);
    }
    s2p[cg][qx] = s2;
    __syncthreads();
    if (tid < 64)
        g_S2[b * L_ + qy * 64 + tid] =
            s2p[0][tid] + s2p[1][tid] + s2p[2][tid] + s2p[3][tid];

    const uint32_t* t32 = (const uint32_t*)tile;
    uint32_t* dst = (uint32_t*)(g_xd + ((size_t)(b * L_ + qy * 64)) * 128);
#pragma unroll
    for (int i = tid; i < 2048; i += 256) {
        int row = i >> 5, w = i & 31;
        dst[row * 64 + w] = t32[row * 65 + w];
    }
}

// ---------------- k_rs: 3x3 stencil on S2 + mask -> rscale/mfilt -------------
__global__ __launch_bounds__(256) void k_rs(const float* __restrict__ mask) {
    int i = blockIdx.x * 256 + threadIdx.x;
    int b = i >> 12, q = i & (L_ - 1);
    int qy = q >> 6, qx = q & 63;
    const float* mb = mask + (size_t)b * (H_ * W_);
    float ss = 0.f, msum = 0.f;
#pragma unroll
    for (int dy = 0; dy < 3; dy++) {
        int sy = qy - 1 + dy;
        if ((unsigned)sy >= HR) continue;
#pragma unroll
        for (int dx = 0; dx < 3; dx++) {
            int sx = qx - 1 + dx;
            if ((unsigned)sx >= HR) continue;
            ss   += __ldg(&g_S2[b * L_ + (sy << 6) + sx]);
            msum += __ldg(&mb[(2 * sy) * W_ + 2 * sx]);
        }
    }
    float denom = sqrtf(ss + F_FULL * EPS_);
    float mf = (msum == 0.f) ? 1.f : 0.f;
    g_mfilt[b * L_ + q]  = mf;
    g_rscale[b * L_ + q] = SCALE_ * mf / denom;
}

// ---------------- k_R: R[p][q] = xd[p] . xd[q]  (K=128, half out) ------------
#define BM 128
#define BN 128
#define BKH 32
#define LDH 40
#define STAGES 3
#define STG_A (BM * LDH * 2)
#define SMEM_R (2 * STAGES * STG_A)

__global__ __launch_bounds__(256) void k_R() {
    int b = blockIdx.z;
    int m0 = blockIdx.y * BM;
    int n0 = blockIdx.x * BN;
    const __half* A = g_xd + (size_t)b * L_ * 128;
    const int lda = 128;
    const int NI = 4;

    extern __shared__ char smem[];
    uint32_t sA = smem_u32(smem);
    uint32_t sB = sA + STAGES * STG_A;

    int tid  = threadIdx.x;
    int wid  = tid >> 5, lane = tid & 31;
    int wm   = wid >> 2, wn = wid & 3;
    int g    = lane >> 2, tig = lane & 3;

    int arow  = lane & 15;
    int acol8 = (lane >> 4) * 8;
    int bmi   = lane >> 3;
    int brow  = (bmi >> 1) * 8 + (lane & 7);
    int bk8   = (bmi & 1) * 8;

    int rowL = tid >> 2, seg = tid & 3;

    float acc[4][4][4];
#pragma unroll
    for (int mt = 0; mt < 4; mt++)
#pragma unroll
        for (int nt = 0; nt < 4; nt++)
#pragma unroll
            for (int k = 0; k < 4; k++) acc[mt][nt][k] = 0.f;

#define ISSUE(it2) do {                                                          \
    int st_ = (it2) % STAGES;                                                    \
    int k0_ = (it2) * BKH;                                                       \
    _Pragma("unroll")                                                            \
    for (int h_ = 0; h_ < 2; h_++) {                                             \
        int row_ = rowL + h_ * 64;                                               \
        cp_async16(sA + st_ * STG_A + (row_ * LDH + seg * 8) * 2,                \
                   &A[(size_t)(m0 + row_) * lda + k0_ + seg * 8]);               \
        cp_async16(sB + st_ * STG_A + (row_ * LDH + seg * 8) * 2,                \
                   &A[(size_t)(n0 + row_) * lda + k0_ + seg * 8]);               \
    }                                                                            \
} while (0)

    ISSUE(0); CP_COMMIT();
    ISSUE(1); CP_COMMIT();

    for (int it = 0; it < NI; it++) {
        CP_WAIT(1);
        __syncthreads();
        if (it + 2 < NI) ISSUE(it + 2);
        CP_COMMIT();

        uint32_t sAb = sA + (it % STAGES) * STG_A;
        uint32_t sBb = sB + (it % STAGES) * STG_A;
#pragma unroll
        for (int ks = 0; ks < 2; ks++) {
            int ko = ks * 16;
            uint32_t af[4][4];
#pragma unroll
            for (int mt = 0; mt < 4; mt++)
                ldsm_x4(af[mt][0], af[mt][1], af[mt][2], af[mt][3],
                        sAb + ((wm * 64 + mt * 16 + arow) * LDH + ko + acol8) * 2);
            uint32_t bf[2][4];
#pragma unroll
            for (int nt2 = 0; nt2 < 2; nt2++)
                ldsm_x4(bf[nt2][0], bf[nt2][1], bf[nt2][2], bf[nt2][3],
                        sBb + ((wn * 32 + nt2 * 16 + brow) * LDH + ko + bk8) * 2);
#pragma unroll
            for (int mt = 0; mt < 4; mt++)
#pragma unroll
                for (int nt = 0; nt < 4; nt++) {
                    int nt2 = nt >> 1, sel = (nt & 1) * 2;
                    mma_f16(acc[mt][nt], af[mt][0], af[mt][1], af[mt][2], af[mt][3],
                            bf[nt2][sel], bf[nt2][sel + 1]);
                }
        }
    }
#undef ISSUE

    __half* Rr = g_R + (size_t)b * L_ * L_;
#pragma unroll
    for (int mt = 0; mt < 4; mt++) {
        int row = m0 + wm * 64 + mt * 16 + g;
#pragma unroll
        for (int nt = 0; nt < 4; nt++) {
            int col = n0 + wn * 32 + nt * 8 + tig * 2;
            *(__half2*)&Rr[(size_t)row * L_ + col] =
                __floats2half2_rn(acc[mt][nt][0], acc[mt][nt][1]);
            *(__half2*)&Rr[(size_t)(row + 8) * L_ + col] =
                __floats2half2_rn(acc[mt][nt][2], acc[mt][nt][3]);
        }
    }
}

// ---------------- k_att: band-at-a-time 9-point diag stencil -----------------
#define AT_R 16
#define AT_C 512
#define AT_BROWS 18
#define AT_SCOLS 656
#define AT_SC32 (AT_SCOLS / 2)
#define AT_SMEM (AT_BROWS * AT_SCOLS * 2 + AT_C * 4)   // 25664

__global__ __launch_bounds__(256) void k_att() {
    int b  = blockIdx.z;
    int c0 = blockIdx.x * AT_C;
    int rb0 = blockIdx.y * AT_R;
    extern __shared__ char smc[];
    const uint32_t* sB32 = (const uint32_t*)smc;
    float* s_rs = (float*)(smc + AT_BROWS * AT_SCOLS * 2);
    const __half* Rg = g_R + (size_t)b * L_ * L_;
    int tid = threadIdx.x;
    int w = tid >> 5, lane = tid & 31;
    int lane8 = lane & 7;
    uint32_t sbase = smem_u32(smc);

    for (int i = tid; i < AT_C; i += 256) s_rs[i] = g_rscale[b * L_ + c0 + i];

    uint32_t acc[2][2][4];
#pragma unroll
    for (int a = 0; a < 2; a++)
#pragma unroll
        for (int p = 0; p < 2; p++)
#pragma unroll
            for (int k = 0; k < 4; k++) acc[a][p][k] = 0u;

#pragma unroll
    for (int dy = -1; dy <= 1; dy++) {
        __syncthreads();   // prior band's reads done before overwrite
        for (int i = tid; i < AT_BROWS * (AT_SCOLS / 8); i += 256) {
            int row = i / (AT_SCOLS / 8);
            int v8  = i % (AT_SCOLS / 8);
            int rr  = rb0 + 64 * dy - 1 + row;
            int gc0 = c0 - 72 + v8 * 8;
            // gc0 is 8-aligned and bounds are 8-aligned -> vector fully in or out
            bool ok = ((unsigned)rr < (unsigned)L_) && ((unsigned)gc0 < (unsigned)L_);
            const void* src = ok ? (const void*)&Rg[(size_t)rr * L_ + gc0] : (const void*)Rg;
            cp_async16z(sbase + (row * AT_SCOLS + v8 * 8) * 2, src, ok ? 16 : 0);
        }
        CP_COMMIT();
        CP_WAIT(0);
        __syncthreads();

#pragma unroll
        for (int rr2 = 0; rr2 < 2; rr2++) {
            int k = w * 2 + rr2;
            int r = rb0 + k;
            int ry = r >> 6, rx = r & 63;
            if ((unsigned)(ry + dy) >= 64u) continue;
            uint32_t aAll = (rx > 0)  ? 0xFFFFFFFFu : 0u;
            uint32_t cAll = (rx < 63) ? 0xFFFFFFFFu : 0u;
            uint32_t mA0 = ((lane8 == 0) ? 0xFFFF0000u : 0xFFFFFFFFu) & aAll;
            uint32_t mC3 = ((lane8 == 7) ? 0x0000FFFFu : 0xFFFFFFFFu) & cAll;
#pragma unroll
            for (int pass = 0; pass < 2; pass++) {
                int lc = pass * 256 + lane * 8;
                int cy = (c0 + lc) >> 6;
                if ((unsigned)(cy + dy) >= 64u) continue;
                int wb = (lc + 64 * dy + 72) >> 1;
                const uint32_t* r0p = sB32 + k * AT_SC32;
                const uint32_t* r1p = sB32 + (k + 1) * AT_SC32;
                const uint32_t* r2p = sB32 + (k + 2) * AT_SC32;
                uint32_t aw = r0p[wb - 1];
                uint4 av = *(const uint4*)(r0p + wb);
                uint4 bv = *(const uint4*)(r1p + wb);
                uint4 cv = *(const uint4*)(r2p + wb);
                uint32_t cw = r2p[wb + 4];

                uint32_t A2[4], C2[4];
                A2[0] = __byte_perm(aw,   av.x, 0x5432) & mA0;
                A2[1] = __byte_perm(av.x, av.y, 0x5432) & aAll;
                A2[2] = __byte_perm(av.y, av.z, 0x5432) & aAll;
                A2[3] = __byte_perm(av.z, av.w, 0x5432) & aAll;
                C2[0] = __byte_perm(cv.x, cv.y, 0x5432) & cAll;
                C2[1] = __byte_perm(cv.y, cv.z, 0x5432) & cAll;
                C2[2] = __byte_perm(cv.z, cv.w, 0x5432) & cAll;
                C2[3] = __byte_perm(cv.w, cw,   0x5432) & mC3;
                const uint32_t* bw = (const uint32_t*)&bv;
#pragma unroll
                for (int kk = 0; kk < 4; kk++) {
                    __half2 t = __hadd2(*(__half2*)&A2[kk], *(__half2*)&bw[kk]);
                    t = __hadd2(t, *(__half2*)&C2[kk]);
                    *(__half2*)&acc[rr2][pass][kk] =
                        __hadd2(*(__half2*)&acc[rr2][pass][kk], t);
                }
            }
        }
    }

    // epilogue: scale by rs, store, per-chunk max
    __half* att = g_att + (size_t)b * L_ * L_;
#pragma unroll
    for (int rr2 = 0; rr2 < 2; rr2++) {
        int k = w * 2 + rr2;
        int r = rb0 + k;
#pragma unroll
        for (int pass = 0; pass < 2; pass++) {
            int lc = pass * 256 + lane * 8;
            float4 rs0 = *(float4*)&s_rs[lc];
            float4 rs1 = *(float4*)&s_rs[lc + 4];
            float rsv[8] = {rs0.x, rs0.y, rs0.z, rs0.w, rs1.x, rs1.y, rs1.z, rs1.w};
            uint32_t outw[4];
            __half2 mx2 = __float2half2_rn(-60000.f);
#pragma unroll
            for (int kk = 0; kk < 4; kk++) {
                float2 f = __half22float2(*(__half2*)&acc[rr2][pass][kk]);
                __half2 h = __floats2half2_rn(f.x * rsv[2 * kk], f.y * rsv[2 * kk + 1]);
                outw[kk] = *(uint32_t*)&h;
                mx2 = __hmax2(mx2, h);
            }
            *(uint4*)&att[(size_t)r * L_ + c0 + lc] = *(uint4*)outw;
            float m = fmaxf(__low2float(mx2), __high2float(mx2));
#pragma unroll
            for (int off = 8; off > 0; off >>= 1)
                m = fmaxf(m, __shfl_xor_sync(0xffffffffu, m, off));
            if ((lane & 15) == 0) {
                int pc = (c0 + lc) >> 7;
                g_statm[((size_t)b * NPC + pc) * L_ + r] = m;
            }
        }
    }
}

// ---------------- k_smC: M from chunk maxima, gated S, gated list ------------
__global__ __launch_bounds__(256) void k_smC() {
    int b = blockIdx.y;
    int wid = threadIdx.x >> 5, lane = threadIdx.x & 31;
    int r = blockIdx.x * 8 + wid;
    const __half* Ar = g_att + (size_t)b * L_ * L_ + (size_t)r * L_;
    const float* mfp = g_mfilt + b * L_;

    float cm = g_statm[((size_t)b * NPC + lane) * L_ + r];
    float M = cm;
#pragma unroll
    for (int off = 16; off > 0; off >>= 1)
        M = fmaxf(M, __shfl_xor_sync(0xffffffffu, M, off));

    unsigned qmask = __ballot_sync(0xffffffffu, cm >= M - 20.f);

    float S = 0.f;
    unsigned qm = qmask;
    while (qm) {
        int pc = __ffs(qm) - 1;
        qm &= qm - 1;
        int c = pc * 128 + lane * 4;
        uint2 v = *(const uint2*)&Ar[c];
        __half2 h0 = *(__half2*)&v.x, h1 = *(__half2*)&v.y;
        float s4 = __expf(__low2float(h0) - M) + __expf(__high2float(h0) - M)
                 + __expf(__low2float(h1) - M) + __expf(__high2float(h1) - M);
#pragma unroll
        for (int off = 16; off > 0; off >>= 1)
            s4 += __shfl_xor_sync(0xffffffffu, s4, off);
        S += s4;
    }
    float Iv = 1.f / S;
    if (lane == 0) { g_cm[b * L_ + r] = M; g_ci[b * L_ + r] = Iv; }

    int cnt = 0;
    size_t base = (size_t)(b * L_ + r) * CAP;
    while (qmask) {
        int pc = __ffs(qmask) - 1;
        qmask &= qmask - 1;
        int c = pc * 128 + lane * 4;
        uint2 v = *(const uint2*)&Ar[c];
        __half2 h0 = *(__half2*)&v.x, h1 = *(__half2*)&v.y;
        float4 mfv = *(const float4*)&mfp[c];
        float wv[4];
        wv[0] = __expf(__low2float(h0) - M) * Iv * mfv.x;
        wv[1] = __expf(__high2float(h0) - M) * Iv * mfv.y;
        wv[2] = __expf(__low2float(h1) - M) * Iv * mfv.z;
        wv[3] = __expf(__high2float(h1) - M) * Iv * mfv.w;
        int lcount = (wv[0] >= THRESH) + (wv[1] >= THRESH) + (wv[2] >= THRESH) + (wv[3] >= THRESH);
        int incl = lcount;
#pragma unroll
        for (int d = 1; d < 32; d <<= 1) {
            int o2 = __shfl_up_sync(0xffffffffu, incl, d);
            if (lane >= d) incl += o2;
        }
        int idx = cnt + incl - lcount;
#pragma unroll
        for (int k = 0; k < 4; k++)
            if (wv[k] >= THRESH) {
                if (idx < CAP) { g_listp[base + idx] = c + k; g_listw[base + idx] = wv[k]; }
                idx++;
            }
        cnt += __shfl_sync(0xffffffffu, incl, 31);
    }
    if (lane == 0) g_cnt[b * L_ + r] = cnt;
}

// ---------------- fused sparse apply + overlap-add (channel-amortized) -------
__global__ __launch_bounds__(128) void k_out(const float* __restrict__ x,
                                             float* __restrict__ out) {
    int y = blockIdx.x, cg = blockIdx.y, b = blockIdx.z;
    int xx = threadIdx.x;
    int c0 = cg * 16;
    const float* xb = x + (size_t)(b * C_ + c0) * (H_ * W_);
    float acc[16];
#pragma unroll
    for (int k = 0; k < 16; k++) acc[k] = 0.f;

    int ki0 = (y + 1) & 1, kj0 = (xx + 1) & 1;
#pragma unroll
    for (int a = 0; a < 2; a++) {
        int ki = ki0 + a * 2;
        int sy2 = y + 1 - ki;
        if (sy2 < 0) continue;
        int sy = sy2 >> 1;
        if (sy >= HR) continue;
#pragma unroll
        for (int bb = 0; bb < 2; bb++) {
            int kj = kj0 + bb * 2;
            int sx2 = xx + 1 - kj;
            if (sx2 < 0) continue;
            int sx = sx2 >> 1;
            if (sx >= HR) continue;
            int q = (sy << 6) + sx;
            int cnt = g_cnt[b * L_ + q];
            if (cnt <= CAP) {
                size_t base = (size_t)(b * L_ + q) * CAP;
                for (int t = 0; t < cnt; t++) {
                    int p = g_listp[base + t];
                    float wv = g_listw[base + t];
                    int py = p >> 6, px = p & 63;
                    int ry = 2 * py - 1 + ki, rx = 2 * px - 1 + kj;
                    if ((unsigned)ry < H_ && (unsigned)rx < W_) {
                        int off = ry * W_ + rx;
#pragma unroll
                        for (int cn = 0; cn < 16; cn++)
                            acc[cn] += wv * __ldg(&xb[(size_t)cn * (H_ * W_) + off]);
                    }
                }
            } else {
                const __half* Ar = g_att + (size_t)b * L_ * L_ + (size_t)q * L_;
                float M = g_cm[b * L_ + q], Iv = g_ci[b * L_ + q];
                const float* mfp = g_mfilt + b * L_;
                for (int p = 0; p < L_; p++) {
                    float wv = __expf(__half2float(Ar[p]) - M) * Iv * mfp[p];
                    if (wv < THRESH) continue;
                    int py = p >> 6, px = p & 63;
                    int ry = 2 * py - 1 + ki, rx = 2 * px - 1 + kj;
                    if ((unsigned)ry < H_ && (unsigned)rx < W_) {
                        int off = ry * W_ + rx;
                        for (int cn = 0; cn < 16; cn++)
                            acc[cn] += wv * __ldg(&xb[(size_t)cn * (H_ * W_) + off]);
                    }
                }
            }
        }
    }
#pragma unroll
    for (int cn = 0; cn < 16; cn++)
        out[(((size_t)(b * C_ + c0 + cn)) * H_ + y) * W_ + xx] = 0.25f * acc[cn];
}

// ---------------- launch ------------------------------------------------------
extern "C" void kernel_launch(void* const* d_in, const int* in_sizes, int n_in,
                              void* d_out, int out_size) {
    const float* x    = (const float*)d_in[0];
    const float* mask = (const float*)d_in[1];
    float* out = (float*)d_out;

    cudaFuncSetAttribute(k_R, cudaFuncAttributeMaxDynamicSharedMemorySize, SMEM_R);
    cudaFuncSetAttribute(k_att, cudaFuncAttributeMaxDynamicSharedMemorySize, AT_SMEM);

    k_xd<<<dim3(HR, B_), 256>>>(x);
    k_rs<<<(B_ * L_) / 256, 256>>>(mask);
    k_R<<<dim3(L_ / BN, L_ / BM, B_), 256, SMEM_R>>>();
    k_att<<<dim3(L_ / AT_C, L_ / AT_R, B_), 256, AT_SMEM>>>();
    k_smC<<<dim3(L_ / 8, B_), 256>>>();
    k_out<<<dim3(H_, 8, B_), 128>>>(x, out);
}

// round 14
// speedup vs baseline: 44.6777x; 1.0290x over previous
#include <cuda_runtime.h>
#include <cuda_fp16.h>
#include <cstdint>
#include <math.h>

#define B_   2
#define C_   128
#define H_   128
#define W_   128
#define HR   64
#define L_   4096
#define EPS_ 0.0001f
#define SCALE_ 10.0f
#define NPC  32
#define CAP  32
#define THRESH 5.9604645e-8f
#define F_FULL 1152.0f

// ---------------- scratch ----------------------------------------------------
__device__ __half g_xd [(size_t)B_ * L_ * 128];  // [b][q][c]
__device__ float  g_S2 [B_ * L_];
__device__ __half g_R  [(size_t)B_ * L_ * L_];   // [b][p][q] correlation
__device__ __half g_att[(size_t)B_ * L_ * L_];   // [b][r][c] logits (sparsely stored)
__device__ float  g_rscale[B_ * L_];
__device__ float  g_mfilt[B_ * L_];
__device__ float  g_diag[B_ * L_];                // diagonal logit lower bound for M
__device__ float  g_statm[(size_t)B_ * NPC * L_]; // per-chunk MAX of logits
__device__ float  g_cm[B_ * L_];
__device__ float  g_ci[B_ * L_];
__device__ int    g_cnt[B_ * L_];
__device__ int    g_listp[(size_t)B_ * L_ * CAP];
__device__ float  g_listw[(size_t)B_ * L_ * CAP];

// ---------------- helpers ----------------------------------------------------
__device__ __forceinline__ uint32_t smem_u32(const void* p) {
    uint32_t a;
    asm("{ .reg .u64 t; cvta.to.shared.u64 t, %1; cvt.u32.u64 %0, t; }" : "=r"(a) : "l"(p));
    return a;
}
__device__ __forceinline__ void cp_async16(uint32_t saddr, const void* g) {
    asm volatile("cp.async.cg.shared.global [%0], [%1], 16;" :: "r"(saddr), "l"(g));
}
__device__ __forceinline__ void cp_async16z(uint32_t saddr, const void* g, int sz) {
    asm volatile("cp.async.cg.shared.global [%0], [%1], 16, %2;"
                 :: "r"(saddr), "l"(g), "r"(sz));
}
#define CP_COMMIT() asm volatile("cp.async.commit_group;" ::: "memory")
#define CP_WAIT(n)  asm volatile("cp.async.wait_group %0;" :: "n"(n) : "memory")

__device__ __forceinline__ void ldsm_x4(uint32_t& r0, uint32_t& r1, uint32_t& r2,
                                        uint32_t& r3, uint32_t addr) {
    asm volatile("ldmatrix.sync.aligned.m8n8.x4.shared.b16 {%0,%1,%2,%3}, [%4];"
                 : "=r"(r0), "=r"(r1), "=r"(r2), "=r"(r3) : "r"(addr));
}
__device__ __forceinline__ void mma_f16(float c[4], uint32_t a0, uint32_t a1,
                                        uint32_t a2, uint32_t a3,
                                        uint32_t b0, uint32_t b1) {
    asm volatile(
        "mma.sync.aligned.m16n8k16.row.col.f32.f16.f16.f32 "
        "{%0,%1,%2,%3}, {%4,%5,%6,%7}, {%8,%9}, {%0,%1,%2,%3};"
        : "+f"(c[0]), "+f"(c[1]), "+f"(c[2]), "+f"(c[3])
        : "r"(a0), "r"(a1), "r"(a2), "r"(a3), "r"(b0), "r"(b1));
}

// ---------------- k_xd: coalesced downsample + per-pixel S2 ------------------
__global__ __launch_bounds__(256) void k_xd(const float* __restrict__ x) {
    int qy = blockIdx.x, b = blockIdx.y;
    __shared__ __half tile[64 * 130];
    __shared__ float s2p[4][64];
    int tid = threadIdx.x;
    int qx = tid & 63;
    int cg = tid >> 6;
    const float* xrow = x + (size_t)b * C_ * H_ * W_ + (size_t)(2 * qy) * W_;

    float s2 = 0.f;
#pragma unroll 8
    for (int it = 0; it < 32; it++) {
        int c = it * 4 + cg;
        float v = __ldg(&xrow[(size_t)c * (H_ * W_) + 2 * qx]);
        s2 += v * v;
        tile[qx * 130 + c] = __float2half_rn(v);
    }
    s2p[cg][qx] = s2;
    __syncthreads();
    if (tid < 64)
        g_S2[b * L_ + qy * 64 + tid] =
            s2p[0][tid] + s2p[1][tid] + s2p[2][tid] + s2p[3][tid];

    const uint32_t* t32 = (const uint32_t*)tile;
    uint32_t* dst = (uint32_t*)(g_xd + ((size_t)(b * L_ + qy * 64)) * 128);
#pragma unroll
    for (int i = tid; i < 2048; i += 256) {
        int row = i >> 5, w = i & 31;
        dst[row * 64 + w] = t32[row * 65 + w];
    }
}

// ---------------- k_rs: 3x3 stencil on S2 + mask -> rscale/mfilt -------------
__global__ __launch_bounds__(256) void k_rs(const float* __restrict__ mask) {
    int i = blockIdx.x * 256 + threadIdx.x;
    int b = i >> 12, q = i & (L_ - 1);
    int qy = q >> 6, qx = q & 63;
    const float* mb = mask + (size_t)b * (H_ * W_);
    float ss = 0.f, msum = 0.f;
#pragma unroll
    for (int dy = 0; dy < 3; dy++) {
        int sy = qy - 1 + dy;
        if ((unsigned)sy >= HR) continue;
#pragma unroll
        for (int dx = 0; dx < 3; dx++) {
            int sx = qx - 1 + dx;
            if ((unsigned)sx >= HR) continue;
            ss   += __ldg(&g_S2[b * L_ + (sy << 6) + sx]);
            msum += __ldg(&mb[(2 * sy) * W_ + 2 * sx]);
        }
    }
    float denom = sqrtf(ss + F_FULL * EPS_);
    float mf = (msum == 0.f) ? 1.f : 0.f;
    g_mfilt[b * L_ + q]  = mf;
    g_rscale[b * L_ + q] = SCALE_ * mf / denom;
}

// ---------------- k_R: R[p][q] = xd[p] . xd[q]  (K=128, half out) ------------
#define BM 128
#define BN 128
#define BKH 32
#define LDH 40
#define STAGES 3
#define STG_A (BM * LDH * 2)
#define SMEM_R (2 * STAGES * STG_A)

__global__ __launch_bounds__(256) void k_R() {
    int b = blockIdx.z;
    int m0 = blockIdx.y * BM;
    int n0 = blockIdx.x * BN;
    const __half* A = g_xd + (size_t)b * L_ * 128;
    const int lda = 128;
    const int NI = 4;

    extern __shared__ char smem[];
    uint32_t sA = smem_u32(smem);
    uint32_t sB = sA + STAGES * STG_A;

    int tid  = threadIdx.x;
    int wid  = tid >> 5, lane = tid & 31;
    int wm   = wid >> 2, wn = wid & 3;
    int g    = lane >> 2, tig = lane & 3;

    int arow  = lane & 15;
    int acol8 = (lane >> 4) * 8;
    int bmi   = lane >> 3;
    int brow  = (bmi >> 1) * 8 + (lane & 7);
    int bk8   = (bmi & 1) * 8;

    int rowL = tid >> 2, seg = tid & 3;

    float acc[4][4][4];
#pragma unroll
    for (int mt = 0; mt < 4; mt++)
#pragma unroll
        for (int nt = 0; nt < 4; nt++)
#pragma unroll
            for (int k = 0; k < 4; k++) acc[mt][nt][k] = 0.f;

#define ISSUE(it2) do {                                                          \
    int st_ = (it2) % STAGES;                                                    \
    int k0_ = (it2) * BKH;                                                       \
    _Pragma("unroll")                                                            \
    for (int h_ = 0; h_ < 2; h_++) {                                             \
        int row_ = rowL + h_ * 64;                                               \
        cp_async16(sA + st_ * STG_A + (row_ * LDH + seg * 8) * 2,                \
                   &A[(size_t)(m0 + row_) * lda + k0_ + seg * 8]);               \
        cp_async16(sB + st_ * STG_A + (row_ * LDH + seg * 8) * 2,                \
                   &A[(size_t)(n0 + row_) * lda + k0_ + seg * 8]);               \
    }                                                                            \
} while (0)

    ISSUE(0); CP_COMMIT();
    ISSUE(1); CP_COMMIT();

    for (int it = 0; it < NI; it++) {
        CP_WAIT(1);
        __syncthreads();
        if (it + 2 < NI) ISSUE(it + 2);
        CP_COMMIT();

        uint32_t sAb = sA + (it % STAGES) * STG_A;
        uint32_t sBb = sB + (it % STAGES) * STG_A;
#pragma unroll
        for (int ks = 0; ks < 2; ks++) {
            int ko = ks * 16;
            uint32_t af[4][4];
#pragma unroll
            for (int mt = 0; mt < 4; mt++)
                ldsm_x4(af[mt][0], af[mt][1], af[mt][2], af[mt][3],
                        sAb + ((wm * 64 + mt * 16 + arow) * LDH + ko + acol8) * 2);
            uint32_t bf[2][4];
#pragma unroll
            for (int nt2 = 0; nt2 < 2; nt2++)
                ldsm_x4(bf[nt2][0], bf[nt2][1], bf[nt2][2], bf[nt2][3],
                        sBb + ((wn * 32 + nt2 * 16 + brow) * LDH + ko + bk8) * 2);
#pragma unroll
            for (int mt = 0; mt < 4; mt++)
#pragma unroll
                for (int nt = 0; nt < 4; nt++) {
                    int nt2 = nt >> 1, sel = (nt & 1) * 2;
                    mma_f16(acc[mt][nt], af[mt][0], af[mt][1], af[mt][2], af[mt][3],
                            bf[nt2][sel], bf[nt2][sel + 1]);
                }
        }
    }
#undef ISSUE

    __half* Rr = g_R + (size_t)b * L_ * L_;
#pragma unroll
    for (int mt = 0; mt < 4; mt++) {
        int row = m0 + wm * 64 + mt * 16 + g;
#pragma unroll
        for (int nt = 0; nt < 4; nt++) {
            int col = n0 + wn * 32 + nt * 8 + tig * 2;
            *(__half2*)&Rr[(size_t)row * L_ + col] =
                __floats2half2_rn(acc[mt][nt][0], acc[mt][nt][1]);
            *(__half2*)&Rr[(size_t)(row + 8) * L_ + col] =
                __floats2half2_rn(acc[mt][nt][2], acc[mt][nt][3]);
        }
    }
}

// ---------------- k_diag: diagonal logit (lower bound on row max) ------------
__global__ __launch_bounds__(256) void k_diag() {
    int i = blockIdx.x * 256 + threadIdx.x;
    int b = i >> 12, r = i & (L_ - 1);
    int ry = r >> 6, rx = r & 63;
    const __half* Rg = g_R + (size_t)b * L_ * L_;
    float s = 0.f;
#pragma unroll
    for (int dy = -1; dy <= 1; dy++) {
        if ((unsigned)(ry + dy) >= 64u) continue;
#pragma unroll
        for (int dx = -1; dx <= 1; dx++) {
            if ((unsigned)(rx + dx) >= 64u) continue;
            int a = r + 64 * dy + dx;
            s += __half2float(Rg[(size_t)a * L_ + a]);
        }
    }
    g_diag[b * L_ + r] = g_rscale[b * L_ + r] * s;
}

// ---------------- k_att: double-buffered bands + gated stores ----------------
#define AT_R 16
#define AT_C 512
#define AT_BROWS 18
#define AT_SCOLS 656
#define AT_SC32 (AT_SCOLS / 2)
#define AT_BANDSZ (AT_BROWS * AT_SCOLS * 2)            // 23616
#define AT_SMEM (2 * AT_BANDSZ + AT_C * 4)             // 49280

__global__ __launch_bounds__(256) void k_att() {
    int b  = blockIdx.z;
    int c0 = blockIdx.x * AT_C;
    int rb0 = blockIdx.y * AT_R;
    extern __shared__ char smc[];
    float* s_rs = (float*)(smc + 2 * AT_BANDSZ);
    const __half* Rg = g_R + (size_t)b * L_ * L_;
    int tid = threadIdx.x;
    int w = tid >> 5, lane = tid & 31;
    int lane8 = lane & 7;
    uint32_t sbase = smem_u32(smc);

    float dg0 = g_diag[b * L_ + rb0 + w * 2]     - 20.f;
    float dg1 = g_diag[b * L_ + rb0 + w * 2 + 1] - 20.f;

    for (int i = tid; i < AT_C; i += 256) s_rs[i] = g_rscale[b * L_ + c0 + i];

#define ISSUE_BAND(dyv, bufv) do {                                               \
    uint32_t bb_ = sbase + (bufv) * AT_BANDSZ;                                   \
    for (int i_ = tid; i_ < AT_BROWS * (AT_SCOLS / 8); i_ += 256) {              \
        int row_ = i_ / (AT_SCOLS / 8);                                          \
        int v8_  = i_ % (AT_SCOLS / 8);                                          \
        int rr_  = rb0 + 64 * (dyv) - 1 + row_;                                  \
        int gc0_ = c0 - 72 + v8_ * 8;                                            \
        bool ok_ = ((unsigned)rr_ < (unsigned)L_) && ((unsigned)gc0_ < (unsigned)L_); \
        const void* src_ = ok_ ? (const void*)&Rg[(size_t)rr_ * L_ + gc0_]       \
                               : (const void*)Rg;                                \
        cp_async16z(bb_ + (row_ * AT_SCOLS + v8_ * 8) * 2, src_, ok_ ? 16 : 0);  \
    }                                                                            \
} while (0)

    uint32_t acc[2][2][4];
#pragma unroll
    for (int a = 0; a < 2; a++)
#pragma unroll
        for (int p = 0; p < 2; p++)
#pragma unroll
            for (int k = 0; k < 4; k++) acc[a][p][k] = 0u;

    ISSUE_BAND(-1, 0);
    CP_COMMIT();

#pragma unroll
    for (int it = 0; it < 3; it++) {
        int dy = it - 1;
        if (it > 0) __syncthreads();          // protect buffer (it&1) before refill
        if (it < 2) ISSUE_BAND(dy + 1, (it + 1) & 1);
        CP_COMMIT();
        if (it < 2) { CP_WAIT(1); } else { CP_WAIT(0); }
        __syncthreads();

        const uint32_t* sB32 = (const uint32_t*)(smc + (it & 1) * AT_BANDSZ);
#pragma unroll
        for (int rr2 = 0; rr2 < 2; rr2++) {
            int k = w * 2 + rr2;
            int r = rb0 + k;
            int ry = r >> 6, rx = r & 63;
            if ((unsigned)(ry + dy) >= 64u) continue;
            uint32_t aAll = (rx > 0)  ? 0xFFFFFFFFu : 0u;
            uint32_t cAll = (rx < 63) ? 0xFFFFFFFFu : 0u;
            uint32_t mA0 = ((lane8 == 0) ? 0xFFFF0000u : 0xFFFFFFFFu) & aAll;
            uint32_t mC3 = ((lane8 == 7) ? 0x0000FFFFu : 0xFFFFFFFFu) & cAll;
#pragma unroll
            for (int pass = 0; pass < 2; pass++) {
                int lc = pass * 256 + lane * 8;
                int cy = (c0 + lc) >> 6;
                if ((unsigned)(cy + dy) >= 64u) continue;
                int wb = (lc + 64 * dy + 72) >> 1;
                const uint32_t* r0p = sB32 + k * AT_SC32;
                const uint32_t* r1p = sB32 + (k + 1) * AT_SC32;
                const uint32_t* r2p = sB32 + (k + 2) * AT_SC32;
                uint32_t aw = r0p[wb - 1];
                uint4 av = *(const uint4*)(r0p + wb);
                uint4 bv = *(const uint4*)(r1p + wb);
                uint4 cv = *(const uint4*)(r2p + wb);
                uint32_t cw = r2p[wb + 4];

                uint32_t A2[4], C2[4];
                A2[0] = __byte_perm(aw,   av.x, 0x5432) & mA0;
                A2[1] = __byte_perm(av.x, av.y, 0x5432) & aAll;
                A2[2] = __byte_perm(av.y, av.z, 0x5432) & aAll;
                A2[3] = __byte_perm(av.z, av.w, 0x5432) & aAll;
                C2[0] = __byte_perm(cv.x, cv.y, 0x5432) & cAll;
                C2[1] = __byte_perm(cv.y, cv.z, 0x5432) & cAll;
                C2[2] = __byte_perm(cv.z, cv.w, 0x5432) & cAll;
                C2[3] = __byte_perm(cv.w, cw,   0x5432) & mC3;
                const uint32_t* bw = (const uint32_t*)&bv;
#pragma unroll
                for (int kk = 0; kk < 4; kk++) {
                    __half2 t = __hadd2(*(__half2*)&A2[kk], *(__half2*)&bw[kk]);
                    t = __hadd2(t, *(__half2*)&C2[kk]);
                    *(__half2*)&acc[rr2][pass][kk] =
                        __hadd2(*(__half2*)&acc[rr2][pass][kk], t);
                }
            }
        }
    }
#undef ISSUE_BAND

    // epilogue: scale by rs, chunk max, GATED store
    __half* att = g_att + (size_t)b * L_ * L_;
#pragma unroll
    for (int rr2 = 0; rr2 < 2; rr2++) {
        int k = w * 2 + rr2;
        int r = rb0 + k;
        float dgate = rr2 ? dg1 : dg0;
#pragma unroll
        for (int pass = 0; pass < 2; pass++) {
            int lc = pass * 256 + lane * 8;
            float4 rs0 = *(float4*)&s_rs[lc];
            float4 rs1 = *(float4*)&s_rs[lc + 4];
            float rsv[8] = {rs0.x, rs0.y, rs0.z, rs0.w, rs1.x, rs1.y, rs1.z, rs1.w};
            uint32_t outw[4];
            __half2 mx2 = __float2half2_rn(-60000.f);
#pragma unroll
            for (int kk = 0; kk < 4; kk++) {
                float2 f = __half22float2(*(__half2*)&acc[rr2][pass][kk]);
                __half2 h = __floats2half2_rn(f.x * rsv[2 * kk], f.y * rsv[2 * kk + 1]);
                outw[kk] = *(uint32_t*)&h;
                mx2 = __hmax2(mx2, h);
            }
            float m = fmaxf(__low2float(mx2), __high2float(mx2));
#pragma unroll
            for (int off = 8; off > 0; off >>= 1)
                m = fmaxf(m, __shfl_xor_sync(0xffffffffu, m, off));
            if (m >= dgate)   // only chunks that can ever be gated downstream
                *(uint4*)&att[(size_t)r * L_ + c0 + lc] = *(uint4*)outw;
            if ((lane & 15) == 0) {
                int pc = (c0 + lc) >> 7;
                g_statm[((size_t)b * NPC + pc) * L_ + r] = m;
            }
        }
    }
}

// ---------------- k_smC: M from chunk maxima, gated S, gated list ------------
__global__ __launch_bounds__(256) void k_smC() {
    int b = blockIdx.y;
    int wid = threadIdx.x >> 5, lane = threadIdx.x & 31;
    int r = blockIdx.x * 8 + wid;
    const __half* Ar = g_att + (size_t)b * L_ * L_ + (size_t)r * L_;
    const float* mfp = g_mfilt + b * L_;

    float cm = g_statm[((size_t)b * NPC + lane) * L_ + r];
    float M = cm;
#pragma unroll
    for (int off = 16; off > 0; off >>= 1)
        M = fmaxf(M, __shfl_xor_sync(0xffffffffu, M, off));

    unsigned qmask = __ballot_sync(0xffffffffu, cm >= M - 20.f);

    float S = 0.f;
    unsigned qm = qmask;
    while (qm) {
        int pc = __ffs(qm) - 1;
        qm &= qm - 1;
        int c = pc * 128 + lane * 4;
        uint2 v = *(const uint2*)&Ar[c];
        __half2 h0 = *(__half2*)&v.x, h1 = *(__half2*)&v.y;
        float s4 = __expf(__low2float(h0) - M) + __expf(__high2float(h0) - M)
                 + __expf(__low2float(h1) - M) + __expf(__high2float(h1) - M);
#pragma unroll
        for (int off = 16; off > 0; off >>= 1)
            s4 += __shfl_xor_sync(0xffffffffu, s4, off);
        S += s4;
    }
    float Iv = 1.f / S;
    if (lane == 0) { g_cm[b * L_ + r] = M; g_ci[b * L_ + r] = Iv; }

    int cnt = 0;
    size_t base = (size_t)(b * L_ + r) * CAP;
    while (qmask) {
        int pc = __ffs(qmask) - 1;
        qmask &= qmask - 1;
        int c = pc * 128 + lane * 4;
        uint2 v = *(const uint2*)&Ar[c];
        __half2 h0 = *(__half2*)&v.x, h1 = *(__half2*)&v.y;
        float4 mfv = *(const float4*)&mfp[c];
        float wv[4];
        wv[0] = __expf(__low2float(h0) - M) * Iv * mfv.x;
        wv[1] = __expf(__high2float(h0) - M) * Iv * mfv.y;
        wv[2] = __expf(__low2float(h1) - M) * Iv * mfv.z;
        wv[3] = __expf(__high2float(h1) - M) * Iv * mfv.w;
        int lcount = (wv[0] >= THRESH) + (wv[1] >= THRESH) + (wv[2] >= THRESH) + (wv[3] >= THRESH);
        int incl = lcount;
#pragma unroll
        for (int d = 1; d < 32; d <<= 1) {
            int o2 = __shfl_up_sync(0xffffffffu, incl, d);
            if (lane >= d) incl += o2;
        }
        int idx = cnt + incl - lcount;
#pragma unroll
        for (int k = 0; k < 4; k++)
            if (wv[k] >= THRESH) {
                if (idx < CAP) { g_listp[base + idx] = c + k; g_listw[base + idx] = wv[k]; }
                idx++;
            }
        cnt += __shfl_sync(0xffffffffu, incl, 31);
    }
    if (lane == 0) g_cnt[b * L_ + r] = cnt;
}

// ---------------- fused sparse apply + overlap-add (channel-amortized) -------
__global__ __launch_bounds__(128) void k_out(const float* __restrict__ x,
                                             float* __restrict__ out) {
    int y = blockIdx.x, cg = blockIdx.y, b = blockIdx.z;
    int xx = threadIdx.x;
    int c0 = cg * 16;
    const float* xb = x + (size_t)(b * C_ + c0) * (H_ * W_);
    float acc[16];
#pragma unroll
    for (int k = 0; k < 16; k++) acc[k] = 0.f;

    int ki0 = (y + 1) & 1, kj0 = (xx + 1) & 1;
#pragma unroll
    for (int a = 0; a < 2; a++) {
        int ki = ki0 + a * 2;
        int sy2 = y + 1 - ki;
        if (sy2 < 0) continue;
        int sy = sy2 >> 1;
        if (sy >= HR) continue;
#pragma unroll
        for (int bb = 0; bb < 2; bb++) {
            int kj = kj0 + bb * 2;
            int sx2 = xx + 1 - kj;
            if (sx2 < 0) continue;
            int sx = sx2 >> 1;
            if (sx >= HR) continue;
            int q = (sy << 6) + sx;
            int cnt = g_cnt[b * L_ + q];
            if (cnt <= CAP) {
                size_t base = (size_t)(b * L_ + q) * CAP;
                for (int t = 0; t < cnt; t++) {
                    int p = g_listp[base + t];
                    float wv = g_listw[base + t];
                    int py = p >> 6, px = p & 63;
                    int ry = 2 * py - 1 + ki, rx = 2 * px - 1 + kj;
                    if ((unsigned)ry < H_ && (unsigned)rx < W_) {
                        int off = ry * W_ + rx;
#pragma unroll
                        for (int cn = 0; cn < 16; cn++)
                            acc[cn] += wv * __ldg(&xb[(size_t)cn * (H_ * W_) + off]);
                    }
                }
            } else {
                // dense fallback over GATED (stored) chunks only
                const __half* Ar = g_att + (size_t)b * L_ * L_ + (size_t)q * L_;
                float M = g_cm[b * L_ + q], Iv = g_ci[b * L_ + q];
                const float* mfp = g_mfilt + b * L_;
                for (int pc = 0; pc < NPC; pc++) {
                    if (g_statm[((size_t)b * NPC + pc) * L_ + q] < M - 20.f) continue;
                    for (int pl = 0; pl < 128; pl++) {
                        int p = pc * 128 + pl;
                        float wv = __expf(__half2float(Ar[p]) - M) * Iv * mfp[p];
                        if (wv < THRESH) continue;
                        int py = p >> 6, px = p & 63;
                        int ry = 2 * py - 1 + ki, rx = 2 * px - 1 + kj;
                        if ((unsigned)ry < H_ && (unsigned)rx < W_) {
                            int off = ry * W_ + rx;
                            for (int cn = 0; cn < 16; cn++)
                                acc[cn] += wv * __ldg(&xb[(size_t)cn * (H_ * W_) + off]);
                        }
                    }
                }
            }
        }
    }
#pragma unroll
    for (int cn = 0; cn < 16; cn++)
        out[(((size_t)(b * C_ + c0 + cn)) * H_ + y) * W_ + xx] = 0.25f * acc[cn];
}

// ---------------- launch ------------------------------------------------------
extern "C" void kernel_launch(void* const* d_in, const int* in_sizes, int n_in,
                              void* d_out, int out_size) {
    const float* x    = (const float*)d_in[0];
    const float* mask = (const float*)d_in[1];
    float* out = (float*)d_out;

    cudaFuncSetAttribute(k_R, cudaFuncAttributeMaxDynamicSharedMemorySize, SMEM_R);
    cudaFuncSetAttribute(k_att, cudaFuncAttributeMaxDynamicSharedMemorySize, AT_SMEM);

    k_xd<<<dim3(HR, B_), 256>>>(x);
    k_rs<<<(B_ * L_) / 256, 256>>>(mask);
    k_R<<<dim3(L_ / BN, L_ / BM, B_), 256, SMEM_R>>>();
    k_diag<<<(B_ * L_) / 256, 256>>>();
    k_att<<<dim3(L_ / AT_C, L_ / AT_R, B_), 256, AT_SMEM>>>();
    k_smC<<<dim3(L_ / 8, B_), 256>>>();
    k_out<<<dim3(H_, 8, B_), 128>>>(x, out);
}